// round 3
// baseline (speedup 1.0000x reference)
#include <cuda_runtime.h>
#include <cstdint>

// ---------------------------------------------------------------------------
// GCN_609885356937: 4-layer GCN + global mean pool + linear head.
//   per layer: h = A_in @ W ; out = D^-1/2 (A+I) D^-1/2 h + b ; relu (layers 1-3)
// Indices (edge_index, batch) are int32: JAX x64 is disabled by default, so the
// reference's jnp.int64 arrays materialize as int32. All indexed accesses are
// bounds-guarded so a dtype mismatch degrades to wrong output, not a trap.
// ---------------------------------------------------------------------------

#define MAXN 100000
#define HID  256
#define MAXG 4096

__device__ float g_h[(size_t)MAXN * HID];     // GEMM output
__device__ float g_a[(size_t)MAXN * HID];     // aggregated output / next layer input
__device__ float g_dinv[MAXN];                // deg -> rsqrt(deg+1)
__device__ float g_pool[(size_t)MAXG * HID];  // per-graph sums
__device__ float g_cnt[MAXG];                 // per-graph node counts

// ---------------- degree / dinv ----------------
__global__ void k_zero_dinv(int N) {
    int i = blockIdx.x * blockDim.x + threadIdx.x;
    if (i < N) g_dinv[i] = 0.f;
}

__global__ void k_count_deg(const int* __restrict__ dst, int E, int N) {
    int e = blockIdx.x * blockDim.x + threadIdx.x;
    if (e < E) {
        unsigned d = (unsigned)dst[e];
        if (d < (unsigned)N) atomicAdd(&g_dinv[d], 1.f);
    }
}

__global__ void k_dinv(int N) {
    int i = blockIdx.x * blockDim.x + threadIdx.x;
    if (i < N) g_dinv[i] = rsqrtf(g_dinv[i] + 1.f);   // +1 self loop
}

// ---------------- SGEMM: g_h[M,256] = act(A)[M,K] @ W[K,256] ----------------
// 64x64 tile, BK=16, 256 threads, 4x4 microtile.
template <bool RELU_IN, bool A_FROM_GA>
__global__ void k_sgemm(const float* __restrict__ Aext, const float* __restrict__ W,
                        int M, int K) {
    const float* A = A_FROM_GA ? (const float*)g_a : Aext;

    __shared__ float As[16][64];   // [k][m]
    __shared__ float Ws[16][68];   // [k][n] (+pad vs bank conflicts)

    const int tid = threadIdx.x;
    const int tx = tid & 15, ty = tid >> 4;
    const int m0 = blockIdx.x * 64;
    const int n0 = blockIdx.y * 64;

    float acc[4][4] = {};

    for (int k0 = 0; k0 < K; k0 += 16) {
#pragma unroll
        for (int i = 0; i < 4; i++) {
            int idx = tid + i * 256;           // 64 rows x 16 k
            int r = idx >> 4, kk = idx & 15;
            int gm = m0 + r, gk = k0 + kk;
            float v = 0.f;
            if (gm < M && gk < K) {
                v = A[(long long)gm * K + gk];
                if (RELU_IN) v = fmaxf(v, 0.f);
            }
            As[kk][r] = v;
        }
#pragma unroll
        for (int i = 0; i < 4; i++) {
            int idx = tid + i * 256;           // 16 k x 64 n
            int kk = idx >> 6, c = idx & 63;
            int gk = k0 + kk;
            Ws[kk][c] = (gk < K) ? W[(long long)gk * HID + n0 + c] : 0.f;
        }
        __syncthreads();
#pragma unroll
        for (int kk = 0; kk < 16; kk++) {
            float a[4], b[4];
#pragma unroll
            for (int i = 0; i < 4; i++) a[i] = As[kk][ty * 4 + i];
#pragma unroll
            for (int j = 0; j < 4; j++) b[j] = Ws[kk][tx * 4 + j];
#pragma unroll
            for (int i = 0; i < 4; i++)
#pragma unroll
                for (int j = 0; j < 4; j++)
                    acc[i][j] = fmaf(a[i], b[j], acc[i][j]);
        }
        __syncthreads();
    }

#pragma unroll
    for (int i = 0; i < 4; i++) {
        int gm = m0 + ty * 4 + i;
        if (gm < M) {
            float4 r = make_float4(acc[i][0], acc[i][1], acc[i][2], acc[i][3]);
            *(float4*)(g_h + (long long)gm * HID + n0 + tx * 4) = r;
        }
    }
}

// ---------------- aggregation ----------------
// g_a[i] = g_h[i]*dinv[i]^2 + b   (self loop + bias; full overwrite, no memset)
__global__ void k_self_bias(const float* __restrict__ b, int N) {
    long long t = (long long)blockIdx.x * blockDim.x + threadIdx.x;
    int i = (int)(t >> 6);
    int c = (int)(t & 63) * 4;
    if (i >= N) return;
    float di = g_dinv[i];
    float n2 = di * di;
    float4 v = *(const float4*)(g_h + (long long)i * HID + c);
    float4 bb = *(const float4*)(b + c);
    float4 r = make_float4(fmaf(v.x, n2, bb.x), fmaf(v.y, n2, bb.y),
                           fmaf(v.z, n2, bb.z), fmaf(v.w, n2, bb.w));
    *(float4*)(g_a + (long long)i * HID + c) = r;
}

// g_a[dst] += g_h[src] * dinv[src]*dinv[dst], one float4 chunk per thread
__global__ void k_edge_scatter(const int* __restrict__ src,
                               const int* __restrict__ dst, int E, int N) {
    long long t = (long long)blockIdx.x * blockDim.x + threadIdx.x;
    int e = (int)(t >> 6);
    int c = (int)(t & 63) * 4;
    if (e >= E) return;
    unsigned s = (unsigned)src[e], d = (unsigned)dst[e];
    if (s >= (unsigned)N || d >= (unsigned)N) return;   // dtype-mismatch guard
    float norm = g_dinv[s] * g_dinv[d];
    float4 v = *(const float4*)(g_h + (long long)s * HID + c);
    float* o = g_a + (long long)d * HID + c;
    atomicAdd(o + 0, v.x * norm);
    atomicAdd(o + 1, v.y * norm);
    atomicAdd(o + 2, v.z * norm);
    atomicAdd(o + 3, v.w * norm);
}

// ---------------- pooling + head ----------------
__global__ void k_zero_pool(int G) {
    long long t = (long long)blockIdx.x * blockDim.x + threadIdx.x;
    long long n = (long long)G * HID;
    if (t < n) g_pool[t] = 0.f;
    if (t < G) g_cnt[t] = 0.f;
}

__global__ void k_pool(const int* __restrict__ batch, int N, int G) {
    long long t = (long long)blockIdx.x * blockDim.x + threadIdx.x;
    int i = (int)(t >> 6);
    int c = (int)(t & 63) * 4;
    if (i >= N) return;
    unsigned g = (unsigned)batch[i];
    if (g >= (unsigned)G) return;                       // dtype-mismatch guard
    float4 v = *(const float4*)(g_a + (long long)i * HID + c);
    float* p = g_pool + (long long)g * HID + c;
    atomicAdd(p + 0, v.x);
    atomicAdd(p + 1, v.y);
    atomicAdd(p + 2, v.z);
    atomicAdd(p + 3, v.w);
    if (c == 0) atomicAdd(&g_cnt[g], 1.f);
}

__global__ void k_head(const float* __restrict__ Wl, const float* __restrict__ bl,
                       float* __restrict__ out) {
    int g = blockIdx.x;
    int t = threadIdx.x;                 // 256 threads
    float cn = fmaxf(g_cnt[g], 1.f);
    float v = g_pool[(long long)g * HID + t] / cn;
    float p0 = v * Wl[t * 2 + 0];
    float p1 = v * Wl[t * 2 + 1];
    __shared__ float s0[256], s1[256];
    s0[t] = p0; s1[t] = p1;
    __syncthreads();
    for (int st = 128; st > 0; st >>= 1) {
        if (t < st) { s0[t] += s0[t + st]; s1[t] += s1[t + st]; }
        __syncthreads();
    }
    if (t == 0) {
        out[g * 2 + 0] = s0[0] + bl[0];
        out[g * 2 + 1] = s1[0] + bl[1];
    }
}

// ---------------------------------------------------------------------------
extern "C" void kernel_launch(void* const* d_in, const int* in_sizes, int n_in,
                              void* d_out, int out_size) {
    const float* x   = (const float*)d_in[0];
    const int*   ei  = (const int*)d_in[1];     // int32 (JAX x64 disabled)
    const int*   bat = (const int*)d_in[2];     // int32
    const float* W1 = (const float*)d_in[3];
    const float* b1 = (const float*)d_in[4];
    const float* W2 = (const float*)d_in[5];
    const float* b2 = (const float*)d_in[6];
    const float* W3 = (const float*)d_in[7];
    const float* b3 = (const float*)d_in[8];
    const float* W4 = (const float*)d_in[9];
    const float* b4 = (const float*)d_in[10];
    const float* Wl = (const float*)d_in[11];
    const float* bl = (const float*)d_in[12];
    float* out = (float*)d_out;

    const int N  = in_sizes[2];
    const int E  = in_sizes[1] / 2;
    const int K1 = in_sizes[0] / N;              // IN_DIM (69)
    const int G  = out_size / 2;

    const int* src = ei;
    const int* dst = ei + E;

    const int TB = 256;
    const long long nodeChunks = (long long)N * 64;   // float4 chunks
    const long long edgeChunks = (long long)E * 64;
    const unsigned nodeGrid = (unsigned)((nodeChunks + TB - 1) / TB);
    const unsigned edgeGrid = (unsigned)((edgeChunks + TB - 1) / TB);

    // degrees -> dinv
    k_zero_dinv<<<(N + TB - 1) / TB, TB>>>(N);
    k_count_deg<<<(E + TB - 1) / TB, TB>>>(dst, E, N);
    k_dinv<<<(N + TB - 1) / TB, TB>>>(N);

    dim3 gemmGrid((N + 63) / 64, HID / 64);

    // ---- layer 1 (input x, K=K1, no input relu) ----
    k_sgemm<false, false><<<gemmGrid, 256>>>(x, W1, N, K1);
    k_self_bias<<<nodeGrid, TB>>>(b1, N);
    k_edge_scatter<<<edgeGrid, TB>>>(src, dst, E, N);

    // ---- layer 2 (relu fused into GEMM A-load) ----
    k_sgemm<true, true><<<gemmGrid, 256>>>(nullptr, W2, N, HID);
    k_self_bias<<<nodeGrid, TB>>>(b2, N);
    k_edge_scatter<<<edgeGrid, TB>>>(src, dst, E, N);

    // ---- layer 3 ----
    k_sgemm<true, true><<<gemmGrid, 256>>>(nullptr, W3, N, HID);
    k_self_bias<<<nodeGrid, TB>>>(b3, N);
    k_edge_scatter<<<edgeGrid, TB>>>(src, dst, E, N);

    // ---- layer 4 (no relu after) ----
    k_sgemm<true, true><<<gemmGrid, 256>>>(nullptr, W4, N, HID);
    k_self_bias<<<nodeGrid, TB>>>(b4, N);
    k_edge_scatter<<<edgeGrid, TB>>>(src, dst, E, N);

    // ---- global mean pool + linear head ----
    k_zero_pool<<<(unsigned)(((long long)G * HID + TB - 1) / TB), TB>>>(G);
    k_pool<<<nodeGrid, TB>>>(bat, N, G);
    k_head<<<G, 256>>>(Wl, bl, out);
}

// round 4
// speedup vs baseline: 1.6998x; 1.6998x over previous
#include <cuda_runtime.h>
#include <cstdint>

// ---------------------------------------------------------------------------
// GCN: 4x (GEMM -> D^-1/2(A+I)D^-1/2 + b -> relu) -> mean pool -> linear head
// Buffers ping-pong g_a/g_b between layers so the fused GEMM epilogue never
// overwrites its own input (grid-wide RAW hazard).
//   L1: x --gemm69--> g_h ; self_bias -> g_a ; scatter(g_h)+= g_a
//   L2: g_a --gemm256--> g_h (+agg-init g_b) ; scatter += g_b
//   L3: g_b --gemm256--> g_h (+agg-init g_a) ; scatter += g_a
//   L4: g_a --gemm256--> g_h (+agg-init g_b) ; scatter += g_b ; pool(g_b)
// ---------------------------------------------------------------------------

#define MAXN 100000
#define HID  256
#define MAXG 4096

__device__ float g_h[(size_t)MAXN * HID];
__device__ float g_a[(size_t)MAXN * HID];
__device__ float g_b[(size_t)MAXN * HID];
__device__ float g_dinv[MAXN];
__device__ float g_pool[(size_t)MAXG * HID];
__device__ float g_cnt[MAXG];

// ---------------- degree / dinv ----------------
__global__ void k_zero_dinv(int N) {
    int i = blockIdx.x * blockDim.x + threadIdx.x;
    if (i < N) g_dinv[i] = 0.f;
}
__global__ void k_count_deg(const int* __restrict__ dst, int E, int N) {
    int e = blockIdx.x * blockDim.x + threadIdx.x;
    if (e < E) {
        unsigned d = (unsigned)dst[e];
        if (d < (unsigned)N) atomicAdd(&g_dinv[d], 1.f);
    }
}
__global__ void k_dinv(int N) {
    int i = blockIdx.x * blockDim.x + threadIdx.x;
    if (i < N) g_dinv[i] = rsqrtf(g_dinv[i] + 1.f);
}

// ---------------- layer-1 SGEMM (K=69, small): 64x64 tile ----------------
__global__ void k_sgemm_l1(const float* __restrict__ A, const float* __restrict__ W,
                           int M, int K) {
    __shared__ float As[16][64];
    __shared__ float Ws[16][68];
    const int tid = threadIdx.x;
    const int tx = tid & 15, ty = tid >> 4;
    const int m0 = blockIdx.x * 64;
    const int n0 = blockIdx.y * 64;
    float acc[4][4] = {};
    for (int k0 = 0; k0 < K; k0 += 16) {
#pragma unroll
        for (int i = 0; i < 4; i++) {
            int idx = tid + i * 256;
            int r = idx >> 4, kk = idx & 15;
            int gm = m0 + r, gk = k0 + kk;
            As[kk][r] = (gm < M && gk < K) ? A[(size_t)gm * K + gk] : 0.f;
        }
#pragma unroll
        for (int i = 0; i < 4; i++) {
            int idx = tid + i * 256;
            int kk = idx >> 6, c = idx & 63;
            int gk = k0 + kk;
            Ws[kk][c] = (gk < K) ? W[(size_t)gk * HID + n0 + c] : 0.f;
        }
        __syncthreads();
#pragma unroll
        for (int kk = 0; kk < 16; kk++) {
            float a[4], b[4];
#pragma unroll
            for (int i = 0; i < 4; i++) a[i] = As[kk][ty * 4 + i];
#pragma unroll
            for (int j = 0; j < 4; j++) b[j] = Ws[kk][tx * 4 + j];
#pragma unroll
            for (int i = 0; i < 4; i++)
#pragma unroll
                for (int j = 0; j < 4; j++)
                    acc[i][j] = fmaf(a[i], b[j], acc[i][j]);
        }
        __syncthreads();
    }
#pragma unroll
    for (int i = 0; i < 4; i++) {
        int gm = m0 + ty * 4 + i;
        if (gm < M)
            *(float4*)(g_h + (size_t)gm * HID + n0 + tx * 4) =
                make_float4(acc[i][0], acc[i][1], acc[i][2], acc[i][3]);
    }
}

// g_a[i] = g_h[i]*dinv[i]^2 + b  (layer-1 agg init)
__global__ void k_self_bias(const float* __restrict__ b, int N) {
    long long t = (long long)blockIdx.x * blockDim.x + threadIdx.x;
    int i = (int)(t >> 6);
    int c = (int)(t & 63) * 4;
    if (i >= N) return;
    float di = g_dinv[i];
    float n2 = di * di;
    float4 v = *(const float4*)(g_h + (size_t)i * HID + c);
    float4 bb = *(const float4*)(b + c);
    *(float4*)(g_a + (size_t)i * HID + c) =
        make_float4(fmaf(v.x, n2, bb.x), fmaf(v.y, n2, bb.y),
                    fmaf(v.z, n2, bb.z), fmaf(v.w, n2, bb.w));
}

// ---------------- K=256 SGEMM: 128x128 tile, 8x8 microtile, double buffer ----
// Reads relu(src) where src = (srcsel? g_b : g_a); writes g_h and
// dstagg = C*dinv^2 + bias into the OTHER buffer.
__global__ __launch_bounds__(256, 2)
void k_sgemm256(const float* __restrict__ W, const float* __restrict__ bias,
                int M, int srcsel) {
    const float* Asrc = srcsel ? (const float*)g_b : (const float*)g_a;
    float* Dagg = srcsel ? (float*)g_a : (float*)g_b;

    __shared__ float As[2][8][128];
    __shared__ float Ws[2][8][128];

    const int tid = threadIdx.x;
    const int m0 = blockIdx.x * 128;
    const int n0 = blockIdx.y * 128;

    const int arow = tid & 127;          // A tile row
    const int akg  = (tid >> 7) * 4;     // A k-group (0 or 4)
    const int wrow = tid >> 5;           // W tile k-row (0..7)
    const int wcol = (tid & 31) * 4;     // W tile col
    const int tx = tid & 15;             // microtile n
    const int ty = tid >> 4;             // microtile m

    float4 pa, pw;

#define LDG_STAGE(k0)                                                          \
    do {                                                                       \
        int gm = m0 + arow;                                                    \
        if (gm < M) {                                                          \
            pa = *(const float4*)(Asrc + (size_t)gm * HID + (k0) + akg);       \
            pa.x = fmaxf(pa.x, 0.f); pa.y = fmaxf(pa.y, 0.f);                  \
            pa.z = fmaxf(pa.z, 0.f); pa.w = fmaxf(pa.w, 0.f);                  \
        } else pa = make_float4(0.f, 0.f, 0.f, 0.f);                           \
        pw = *(const float4*)(W + (size_t)((k0) + wrow) * HID + n0 + wcol);    \
    } while (0)

#define STS_STAGE(buf)                                                         \
    do {                                                                       \
        As[buf][akg + 0][arow] = pa.x;                                         \
        As[buf][akg + 1][arow] = pa.y;                                         \
        As[buf][akg + 2][arow] = pa.z;                                         \
        As[buf][akg + 3][arow] = pa.w;                                         \
        *(float4*)&Ws[buf][wrow][wcol] = pw;                                   \
    } while (0)

    float acc[8][8] = {};

    LDG_STAGE(0);
    STS_STAGE(0);
    __syncthreads();

    const int NS = HID / 8;  // 32 stages
    for (int s = 0; s < NS; s++) {
        if (s + 1 < NS) LDG_STAGE((s + 1) * 8);
        const int buf = s & 1;
#pragma unroll
        for (int kk = 0; kk < 8; kk++) {
            float4 a0 = *(const float4*)&As[buf][kk][ty * 4];
            float4 a1 = *(const float4*)&As[buf][kk][64 + ty * 4];
            float4 b0 = *(const float4*)&Ws[buf][kk][tx * 4];
            float4 b1 = *(const float4*)&Ws[buf][kk][64 + tx * 4];
            float a[8] = {a0.x, a0.y, a0.z, a0.w, a1.x, a1.y, a1.z, a1.w};
            float b[8] = {b0.x, b0.y, b0.z, b0.w, b1.x, b1.y, b1.z, b1.w};
#pragma unroll
            for (int i = 0; i < 8; i++)
#pragma unroll
                for (int j = 0; j < 8; j++)
                    acc[i][j] = fmaf(a[i], b[j], acc[i][j]);
        }
        if (s + 1 < NS) {
            STS_STAGE((s + 1) & 1);
            __syncthreads();
        }
    }
#undef LDG_STAGE
#undef STS_STAGE

    // fused epilogue: g_h = C ; Dagg = C*dinv^2 + bias
    float4 bb0 = *(const float4*)(bias + n0 + tx * 4);
    float4 bb1 = *(const float4*)(bias + n0 + 64 + tx * 4);
#pragma unroll
    for (int i = 0; i < 8; i++) {
        int gm = m0 + ((i < 4) ? (ty * 4 + i) : (64 + ty * 4 + i - 4));
        if (gm >= M) continue;
        float di = g_dinv[gm];
        float n2 = di * di;
        float4 c0 = make_float4(acc[i][0], acc[i][1], acc[i][2], acc[i][3]);
        float4 c1 = make_float4(acc[i][4], acc[i][5], acc[i][6], acc[i][7]);
        size_t off0 = (size_t)gm * HID + n0 + tx * 4;
        size_t off1 = off0 + 64;
        *(float4*)(g_h + off0) = c0;
        *(float4*)(g_h + off1) = c1;
        *(float4*)(Dagg + off0) = make_float4(fmaf(c0.x, n2, bb0.x), fmaf(c0.y, n2, bb0.y),
                                              fmaf(c0.z, n2, bb0.z), fmaf(c0.w, n2, bb0.w));
        *(float4*)(Dagg + off1) = make_float4(fmaf(c1.x, n2, bb1.x), fmaf(c1.y, n2, bb1.y),
                                              fmaf(c1.z, n2, bb1.z), fmaf(c1.w, n2, bb1.w));
    }
}

// ---------------- edge scatter: out[dst] += g_h[src]*norm (vector red) -----
__global__ void k_edge_scatter(const int* __restrict__ src,
                               const int* __restrict__ dst, int E, int N, int sel) {
    float* outb = sel ? (float*)g_b : (float*)g_a;
    long long t = (long long)blockIdx.x * blockDim.x + threadIdx.x;
    int e = (int)(t >> 6);
    int c = (int)(t & 63) * 4;
    if (e >= E) return;
    unsigned s = (unsigned)src[e], d = (unsigned)dst[e];
    if (s >= (unsigned)N || d >= (unsigned)N) return;
    float norm = g_dinv[s] * g_dinv[d];
    float4 v = *(const float4*)(g_h + (size_t)s * HID + c);
    float* o = outb + (size_t)d * HID + c;
    asm volatile("red.global.add.v4.f32 [%0], {%1, %2, %3, %4};"
                 :: "l"(o), "f"(v.x * norm), "f"(v.y * norm),
                    "f"(v.z * norm), "f"(v.w * norm)
                 : "memory");
}

// ---------------- pooling + head ----------------
__global__ void k_zero_pool(int G) {
    long long t = (long long)blockIdx.x * blockDim.x + threadIdx.x;
    long long n = (long long)G * HID;
    if (t < n) g_pool[t] = 0.f;
    if (t < G) g_cnt[t] = 0.f;
}

__global__ void k_pool(const int* __restrict__ batch, int N, int G) {
    long long t = (long long)blockIdx.x * blockDim.x + threadIdx.x;
    int i = (int)(t >> 6);
    int c = (int)(t & 63) * 4;
    if (i >= N) return;
    unsigned g = (unsigned)batch[i];
    if (g >= (unsigned)G) return;
    float4 v = *(const float4*)(g_b + (size_t)i * HID + c);
    float* p = g_pool + (size_t)g * HID + c;
    asm volatile("red.global.add.v4.f32 [%0], {%1, %2, %3, %4};"
                 :: "l"(p), "f"(v.x), "f"(v.y), "f"(v.z), "f"(v.w)
                 : "memory");
    if (c == 0) atomicAdd(&g_cnt[g], 1.f);
}

__global__ void k_head(const float* __restrict__ Wl, const float* __restrict__ bl,
                       float* __restrict__ out) {
    int g = blockIdx.x;
    int t = threadIdx.x;  // 256
    float cn = fmaxf(g_cnt[g], 1.f);
    float v = g_pool[(size_t)g * HID + t] / cn;
    float p0 = v * Wl[t * 2 + 0];
    float p1 = v * Wl[t * 2 + 1];
    __shared__ float s0[256], s1[256];
    s0[t] = p0; s1[t] = p1;
    __syncthreads();
    for (int st = 128; st > 0; st >>= 1) {
        if (t < st) { s0[t] += s0[t + st]; s1[t] += s1[t + st]; }
        __syncthreads();
    }
    if (t == 0) {
        out[g * 2 + 0] = s0[0] + bl[0];
        out[g * 2 + 1] = s1[0] + bl[1];
    }
}

// ---------------------------------------------------------------------------
extern "C" void kernel_launch(void* const* d_in, const int* in_sizes, int n_in,
                              void* d_out, int out_size) {
    const float* x   = (const float*)d_in[0];
    const int*   ei  = (const int*)d_in[1];
    const int*   bat = (const int*)d_in[2];
    const float* W1 = (const float*)d_in[3];
    const float* b1 = (const float*)d_in[4];
    const float* W2 = (const float*)d_in[5];
    const float* b2 = (const float*)d_in[6];
    const float* W3 = (const float*)d_in[7];
    const float* b3 = (const float*)d_in[8];
    const float* W4 = (const float*)d_in[9];
    const float* b4 = (const float*)d_in[10];
    const float* Wl = (const float*)d_in[11];
    const float* bl = (const float*)d_in[12];
    float* out = (float*)d_out;

    const int N  = in_sizes[2];
    const int E  = in_sizes[1] / 2;
    const int K1 = in_sizes[0] / N;   // IN_DIM (69)
    const int G  = out_size / 2;

    const int* src = ei;
    const int* dst = ei + E;

    const int TB = 256;
    const long long nodeChunks = (long long)N * 64;
    const long long edgeChunks = (long long)E * 64;
    const unsigned nodeGrid = (unsigned)((nodeChunks + TB - 1) / TB);
    const unsigned edgeGrid = (unsigned)((edgeChunks + TB - 1) / TB);

    k_zero_dinv<<<(N + TB - 1) / TB, TB>>>(N);
    k_count_deg<<<(E + TB - 1) / TB, TB>>>(dst, E, N);
    k_dinv<<<(N + TB - 1) / TB, TB>>>(N);

    dim3 grid1((N + 63) / 64, HID / 64);
    dim3 grid256((N + 127) / 128, HID / 128);

    // ---- layer 1 ----
    k_sgemm_l1<<<grid1, 256>>>(x, W1, N, K1);
    k_self_bias<<<nodeGrid, TB>>>(b1, N);
    k_edge_scatter<<<edgeGrid, TB>>>(src, dst, E, N, /*sel g_a*/0);

    // ---- layer 2: read g_a -> agg g_b ----
    k_sgemm256<<<grid256, 256>>>(W2, b2, N, /*srcsel g_a*/0);
    k_edge_scatter<<<edgeGrid, TB>>>(src, dst, E, N, /*sel g_b*/1);

    // ---- layer 3: read g_b -> agg g_a ----
    k_sgemm256<<<grid256, 256>>>(W3, b3, N, /*srcsel g_b*/1);
    k_edge_scatter<<<edgeGrid, TB>>>(src, dst, E, N, /*sel g_a*/0);

    // ---- layer 4: read g_a -> agg g_b ----
    k_sgemm256<<<grid256, 256>>>(W4, b4, N, /*srcsel g_a*/0);
    k_edge_scatter<<<edgeGrid, TB>>>(src, dst, E, N, /*sel g_b*/1);

    // ---- pool + head (reads g_b) ----
    k_zero_pool<<<(unsigned)(((long long)G * HID + TB - 1) / TB), TB>>>(G);
    k_pool<<<nodeGrid, TB>>>(bat, N, G);
    k_head<<<G, 256>>>(Wl, bl, out);
}

// round 5
// speedup vs baseline: 1.9685x; 1.1581x over previous
#include <cuda_runtime.h>
#include <cstdint>

// ---------------------------------------------------------------------------
// GCN: 4x (GEMM -> norm-agg(+bias) -> relu) -> mean pool -> linear head.
// GEMM writes hs[i] = (A@W)[i] * dinv[i].
// CSR agg (one warp per dst node, built once per launch):
//   out[d] = dinv[d] * (hs[d] + sum_{s in in(d)} hs[s]) + b
// which equals D^-1/2 (A+I) D^-1/2 (A@W) + b. No float atomics, row written once.
// ---------------------------------------------------------------------------

#define MAXN 100000
#define MAXE 400000
#define HID  256
#define MAXG 4096

__device__ float g_h[(size_t)MAXN * HID];     // hs = h * dinv
__device__ float g_a[(size_t)MAXN * HID];     // aggregated / next layer input
__device__ float g_dinv[MAXN];
__device__ int   g_deg[MAXN];
__device__ int   g_ptr[MAXN + 1];
__device__ int   g_cur[MAXN];
__device__ int   g_csrc[MAXE];
__device__ float g_pool[(size_t)MAXG * HID];
__device__ float g_cnt[MAXG];

// ---------------- CSR build ----------------
__global__ void k_zero_deg(int N) {
    int i = blockIdx.x * blockDim.x + threadIdx.x;
    if (i < N) g_deg[i] = 0;
}
__global__ void k_count_deg(const int* __restrict__ dst, int E, int N) {
    int e = blockIdx.x * blockDim.x + threadIdx.x;
    if (e < E) {
        unsigned d = (unsigned)dst[e];
        if (d < (unsigned)N) atomicAdd(&g_deg[d], 1);
    }
}
__global__ void k_dinv(int N) {
    int i = blockIdx.x * blockDim.x + threadIdx.x;
    if (i < N) g_dinv[i] = rsqrtf((float)g_deg[i] + 1.f);
}
// single-block exclusive scan of g_deg -> g_ptr / g_cur (N up to ~1M)
__global__ void k_scan(int N) {
    __shared__ int sums[1024];
    const int tid = threadIdx.x;
    const int per = (N + 1023) / 1024;
    int beg = tid * per;
    int end = min(beg + per, N);
    int s = 0;
    for (int i = beg; i < end; i++) s += g_deg[i];
    sums[tid] = s;
    __syncthreads();
    for (int off = 1; off < 1024; off <<= 1) {
        int v = (tid >= off) ? sums[tid - off] : 0;
        __syncthreads();
        sums[tid] += v;
        __syncthreads();
    }
    int run = (tid == 0) ? 0 : sums[tid - 1];
    for (int i = beg; i < end; i++) {
        g_ptr[i] = run;
        g_cur[i] = run;
        run += g_deg[i];
    }
    if (beg < N && end == N) g_ptr[N] = run;
}
__global__ void k_fill_csr(const int* __restrict__ src, const int* __restrict__ dst,
                           int E, int N) {
    int e = blockIdx.x * blockDim.x + threadIdx.x;
    if (e >= E) return;
    unsigned s = (unsigned)src[e], d = (unsigned)dst[e];
    if (s >= (unsigned)N || d >= (unsigned)N) return;
    int pos = atomicAdd(&g_cur[d], 1);
    if (pos < MAXE) g_csrc[pos] = (int)s;
}

// ---------------- layer-1 SGEMM (K=69): 128x128 tile, 8x8 microtile --------
// g_h[m] = (A@W)[m] * dinv[m]
__global__ __launch_bounds__(256, 2)
void k_sgemm_l1(const float* __restrict__ A, const float* __restrict__ W,
                int M, int K) {
    __shared__ float As[8][128];
    __shared__ float Ws[8][128];
    const int tid = threadIdx.x;
    const int m0 = blockIdx.x * 128;
    const int n0 = blockIdx.y * 128;
    const int wrow = tid >> 5;            // 0..7
    const int wcol = (tid & 31) * 4;
    const int tx = tid & 15;
    const int ty = tid >> 4;

    float acc[8][8] = {};

    for (int k0 = 0; k0 < K; k0 += 8) {
        __syncthreads();
#pragma unroll
        for (int i = 0; i < 4; i++) {
            int idx = tid + i * 256;       // 128 rows x 8 k
            int r = idx >> 3, kk = idx & 7;
            int gm = m0 + r, gk = k0 + kk;
            As[kk][r] = (gm < M && gk < K) ? A[(size_t)gm * K + gk] : 0.f;
        }
        {
            int gk = k0 + wrow;
            float4 w = (gk < K) ? *(const float4*)(W + (size_t)gk * HID + n0 + wcol)
                                : make_float4(0.f, 0.f, 0.f, 0.f);
            *(float4*)&Ws[wrow][wcol] = w;
        }
        __syncthreads();
#pragma unroll
        for (int kk = 0; kk < 8; kk++) {
            float4 a0 = *(const float4*)&As[kk][ty * 4];
            float4 a1 = *(const float4*)&As[kk][64 + ty * 4];
            float4 b0 = *(const float4*)&Ws[kk][tx * 4];
            float4 b1 = *(const float4*)&Ws[kk][64 + tx * 4];
            float a[8] = {a0.x, a0.y, a0.z, a0.w, a1.x, a1.y, a1.z, a1.w};
            float b[8] = {b0.x, b0.y, b0.z, b0.w, b1.x, b1.y, b1.z, b1.w};
#pragma unroll
            for (int i = 0; i < 8; i++)
#pragma unroll
                for (int j = 0; j < 8; j++)
                    acc[i][j] = fmaf(a[i], b[j], acc[i][j]);
        }
    }

#pragma unroll
    for (int i = 0; i < 8; i++) {
        int gm = m0 + ((i < 4) ? (ty * 4 + i) : (64 + ty * 4 + i - 4));
        if (gm >= M) continue;
        float dn = g_dinv[gm];
        size_t off = (size_t)gm * HID + n0 + tx * 4;
        *(float4*)(g_h + off) = make_float4(acc[i][0] * dn, acc[i][1] * dn,
                                            acc[i][2] * dn, acc[i][3] * dn);
        *(float4*)(g_h + off + 64) = make_float4(acc[i][4] * dn, acc[i][5] * dn,
                                                 acc[i][6] * dn, acc[i][7] * dn);
    }
}

// ---------------- K=256 SGEMM: 128x128 tile, 8x8 microtile, double buffer ---
// g_h[m] = (relu(g_a)@W)[m] * dinv[m]
__global__ __launch_bounds__(256, 2)
void k_sgemm256(const float* __restrict__ W, int M) {
    const float* Asrc = (const float*)g_a;

    __shared__ float As[2][8][128];
    __shared__ float Ws[2][8][128];

    const int tid = threadIdx.x;
    const int m0 = blockIdx.x * 128;
    const int n0 = blockIdx.y * 128;

    const int arow = tid & 127;
    const int akg  = (tid >> 7) * 4;
    const int wrow = tid >> 5;
    const int wcol = (tid & 31) * 4;
    const int tx = tid & 15;
    const int ty = tid >> 4;

    float4 pa, pw;

#define LDG_STAGE(k0)                                                          \
    do {                                                                       \
        int gm = m0 + arow;                                                    \
        if (gm < M) {                                                          \
            pa = *(const float4*)(Asrc + (size_t)gm * HID + (k0) + akg);       \
            pa.x = fmaxf(pa.x, 0.f); pa.y = fmaxf(pa.y, 0.f);                  \
            pa.z = fmaxf(pa.z, 0.f); pa.w = fmaxf(pa.w, 0.f);                  \
        } else pa = make_float4(0.f, 0.f, 0.f, 0.f);                           \
        pw = *(const float4*)(W + (size_t)((k0) + wrow) * HID + n0 + wcol);    \
    } while (0)

#define STS_STAGE(buf)                                                         \
    do {                                                                       \
        As[buf][akg + 0][arow] = pa.x;                                         \
        As[buf][akg + 1][arow] = pa.y;                                         \
        As[buf][akg + 2][arow] = pa.z;                                         \
        As[buf][akg + 3][arow] = pa.w;                                         \
        *(float4*)&Ws[buf][wrow][wcol] = pw;                                   \
    } while (0)

    float acc[8][8] = {};

    LDG_STAGE(0);
    STS_STAGE(0);
    __syncthreads();

    const int NS = HID / 8;
    for (int s = 0; s < NS; s++) {
        if (s + 1 < NS) LDG_STAGE((s + 1) * 8);
        const int buf = s & 1;
#pragma unroll
        for (int kk = 0; kk < 8; kk++) {
            float4 a0 = *(const float4*)&As[buf][kk][ty * 4];
            float4 a1 = *(const float4*)&As[buf][kk][64 + ty * 4];
            float4 b0 = *(const float4*)&Ws[buf][kk][tx * 4];
            float4 b1 = *(const float4*)&Ws[buf][kk][64 + tx * 4];
            float a[8] = {a0.x, a0.y, a0.z, a0.w, a1.x, a1.y, a1.z, a1.w};
            float b[8] = {b0.x, b0.y, b0.z, b0.w, b1.x, b1.y, b1.z, b1.w};
#pragma unroll
            for (int i = 0; i < 8; i++)
#pragma unroll
                for (int j = 0; j < 8; j++)
                    acc[i][j] = fmaf(a[i], b[j], acc[i][j]);
        }
        if (s + 1 < NS) {
            STS_STAGE((s + 1) & 1);
            __syncthreads();
        }
    }
#undef LDG_STAGE
#undef STS_STAGE

#pragma unroll
    for (int i = 0; i < 8; i++) {
        int gm = m0 + ((i < 4) ? (ty * 4 + i) : (64 + ty * 4 + i - 4));
        if (gm >= M) continue;
        float dn = g_dinv[gm];
        size_t off = (size_t)gm * HID + n0 + tx * 4;
        *(float4*)(g_h + off) = make_float4(acc[i][0] * dn, acc[i][1] * dn,
                                            acc[i][2] * dn, acc[i][3] * dn);
        *(float4*)(g_h + off + 64) = make_float4(acc[i][4] * dn, acc[i][5] * dn,
                                                 acc[i][6] * dn, acc[i][7] * dn);
    }
}

// ---------------- CSR aggregation: one warp per dst node -------------------
// g_a[d] = dinv[d] * (g_h[d] + sum_{s in in(d)} g_h[s]) + b
__global__ void k_agg(const float* __restrict__ bias, int N) {
    int node = blockIdx.x * (blockDim.x >> 5) + (threadIdx.x >> 5);
    int lane = threadIdx.x & 31;
    if (node >= N) return;
    const int c0 = lane * 4, c1 = 128 + lane * 4;

    const float* selfr = g_h + (size_t)node * HID;
    float4 a0 = *(const float4*)(selfr + c0);
    float4 a1 = *(const float4*)(selfr + c1);

    int beg = g_ptr[node], end = g_ptr[node + 1];
    for (int j = beg; j < end; j++) {
        int s = g_csrc[j];
        const float* r = g_h + (size_t)s * HID;
        float4 v0 = *(const float4*)(r + c0);
        float4 v1 = *(const float4*)(r + c1);
        a0.x += v0.x; a0.y += v0.y; a0.z += v0.z; a0.w += v0.w;
        a1.x += v1.x; a1.y += v1.y; a1.z += v1.z; a1.w += v1.w;
    }
    float dn = g_dinv[node];
    float4 b0 = *(const float4*)(bias + c0);
    float4 b1 = *(const float4*)(bias + c1);
    float* o = g_a + (size_t)node * HID;
    *(float4*)(o + c0) = make_float4(fmaf(a0.x, dn, b0.x), fmaf(a0.y, dn, b0.y),
                                     fmaf(a0.z, dn, b0.z), fmaf(a0.w, dn, b0.w));
    *(float4*)(o + c1) = make_float4(fmaf(a1.x, dn, b1.x), fmaf(a1.y, dn, b1.y),
                                     fmaf(a1.z, dn, b1.z), fmaf(a1.w, dn, b1.w));
}

// ---------------- pooling + head ----------------
__global__ void k_zero_pool(int G) {
    long long t = (long long)blockIdx.x * blockDim.x + threadIdx.x;
    long long n = (long long)G * HID;
    if (t < n) g_pool[t] = 0.f;
    if (t < G) g_cnt[t] = 0.f;
}

__global__ void k_pool(const int* __restrict__ batch, int N, int G) {
    long long t = (long long)blockIdx.x * blockDim.x + threadIdx.x;
    int i = (int)(t >> 6);
    int c = (int)(t & 63) * 4;
    if (i >= N) return;
    unsigned g = (unsigned)batch[i];
    if (g >= (unsigned)G) return;
    float4 v = *(const float4*)(g_a + (size_t)i * HID + c);
    float* p = g_pool + (size_t)g * HID + c;
    asm volatile("red.global.add.v4.f32 [%0], {%1, %2, %3, %4};"
                 :: "l"(p), "f"(v.x), "f"(v.y), "f"(v.z), "f"(v.w)
                 : "memory");
    if (c == 0) atomicAdd(&g_cnt[g], 1.f);
}

__global__ void k_head(const float* __restrict__ Wl, const float* __restrict__ bl,
                       float* __restrict__ out) {
    int g = blockIdx.x;
    int t = threadIdx.x;  // 256
    float cn = fmaxf(g_cnt[g], 1.f);
    float v = g_pool[(size_t)g * HID + t] / cn;
    float p0 = v * Wl[t * 2 + 0];
    float p1 = v * Wl[t * 2 + 1];
    __shared__ float s0[256], s1[256];
    s0[t] = p0; s1[t] = p1;
    __syncthreads();
    for (int st = 128; st > 0; st >>= 1) {
        if (t < st) { s0[t] += s0[t + st]; s1[t] += s1[t + st]; }
        __syncthreads();
    }
    if (t == 0) {
        out[g * 2 + 0] = s0[0] + bl[0];
        out[g * 2 + 1] = s1[0] + bl[1];
    }
}

// ---------------------------------------------------------------------------
extern "C" void kernel_launch(void* const* d_in, const int* in_sizes, int n_in,
                              void* d_out, int out_size) {
    const float* x   = (const float*)d_in[0];
    const int*   ei  = (const int*)d_in[1];
    const int*   bat = (const int*)d_in[2];
    const float* W1 = (const float*)d_in[3];
    const float* b1 = (const float*)d_in[4];
    const float* W2 = (const float*)d_in[5];
    const float* b2 = (const float*)d_in[6];
    const float* W3 = (const float*)d_in[7];
    const float* b3 = (const float*)d_in[8];
    const float* W4 = (const float*)d_in[9];
    const float* b4 = (const float*)d_in[10];
    const float* Wl = (const float*)d_in[11];
    const float* bl = (const float*)d_in[12];
    float* out = (float*)d_out;

    const int N  = in_sizes[2];
    const int E  = in_sizes[1] / 2;
    const int K1 = in_sizes[0] / N;   // IN_DIM (69)
    const int G  = out_size / 2;

    const int* src = ei;
    const int* dst = ei + E;

    const int TB = 256;

    // ---- CSR build + dinv (once, reused by all 4 layers) ----
    k_zero_deg<<<(N + TB - 1) / TB, TB>>>(N);
    k_count_deg<<<(E + TB - 1) / TB, TB>>>(dst, E, N);
    k_dinv<<<(N + TB - 1) / TB, TB>>>(N);
    k_scan<<<1, 1024>>>(N);
    k_fill_csr<<<(E + TB - 1) / TB, TB>>>(src, dst, E, N);

    dim3 gemmGrid((N + 127) / 128, HID / 128);
    const unsigned aggGrid = (unsigned)((N + 7) / 8);

    // ---- layer 1 ----
    k_sgemm_l1<<<gemmGrid, 256>>>(x, W1, N, K1);
    k_agg<<<aggGrid, 256>>>(b1, N);
    // ---- layer 2 ----
    k_sgemm256<<<gemmGrid, 256>>>(W2, N);
    k_agg<<<aggGrid, 256>>>(b2, N);
    // ---- layer 3 ----
    k_sgemm256<<<gemmGrid, 256>>>(W3, N);
    k_agg<<<aggGrid, 256>>>(b3, N);
    // ---- layer 4 ----
    k_sgemm256<<<gemmGrid, 256>>>(W4, N);
    k_agg<<<aggGrid, 256>>>(b4, N);

    // ---- pool + head ----
    k_zero_pool<<<(unsigned)(((long long)G * HID + TB - 1) / TB), TB>>>(G);
    k_pool<<<(unsigned)(((long long)N * 64 + TB - 1) / TB), TB>>>(bat, N, G);
    k_head<<<G, 256>>>(Wl, bl, out);
}

// round 6
// speedup vs baseline: 3.0210x; 1.5347x over previous
#include <cuda_runtime.h>
#include <cstdint>

// ---------------------------------------------------------------------------
// GCN: 4x (GEMM -> norm-agg(+bias) -> relu) -> mean pool -> linear head.
// GEMM writes hs[i] = (A@W)[i] * dinv[i].
// CSR agg: out[d] = dinv[d]*(hs[d] + sum_in hs[s]) + b. No float atomics.
// K=256 GEMMs run on tensor cores (tf32 mma, fp32 accum).
// ---------------------------------------------------------------------------

#define MAXN 100000
#define MAXE 400000
#define HID  256
#define MAXG 4096
#define SCHUNK 2048   // elements per scan block

__device__ float g_h[(size_t)MAXN * HID];     // hs = h * dinv
__device__ float g_a[(size_t)MAXN * HID];     // aggregated / next layer input
__device__ float g_dinv[MAXN];
__device__ int   g_deg[MAXN];
__device__ int   g_ptr[MAXN + 1];
__device__ int   g_cur[MAXN];
__device__ int   g_csrc[MAXE];
__device__ int   g_bsum[256];
__device__ float g_pool[(size_t)MAXG * HID];
__device__ float g_cnt[MAXG];

__device__ __forceinline__ float to_tf32(float x) {
    float r;
    asm("cvt.rna.tf32.f32 %0, %1;" : "=f"(r) : "f"(x));
    return r;
}

// ---------------- CSR build ----------------
__global__ void k_zero_deg(int N) {
    int i = blockIdx.x * blockDim.x + threadIdx.x;
    if (i < N) g_deg[i] = 0;
}
__global__ void k_count_deg(const int* __restrict__ dst, int E, int N) {
    int e = blockIdx.x * blockDim.x + threadIdx.x;
    if (e < E) {
        unsigned d = (unsigned)dst[e];
        if (d < (unsigned)N) atomicAdd(&g_deg[d], 1);
    }
}
__global__ void k_dinv(int N) {
    int i = blockIdx.x * blockDim.x + threadIdx.x;
    if (i < N) g_dinv[i] = rsqrtf((float)g_deg[i] + 1.f);
}

// ---- multi-block exclusive scan: deg -> ptr/cur ----
// scan1: per-block totals
__global__ void k_scan1(int N) {
    __shared__ int sh[256];
    const int tid = threadIdx.x;
    const int base = blockIdx.x * SCHUNK + tid * 8;
    int s = 0;
#pragma unroll
    for (int i = 0; i < 8; i++) {
        int idx = base + i;
        if (idx < N) s += g_deg[idx];
    }
    sh[tid] = s;
    __syncthreads();
    for (int off = 1; off < 256; off <<= 1) {
        int v = (tid >= off) ? sh[tid - off] : 0;
        __syncthreads();
        sh[tid] += v;
        __syncthreads();
    }
    if (tid == 255) g_bsum[blockIdx.x] = sh[255];
}
// scan2: exclusive scan of block totals (<=256 blocks)
__global__ void k_scan2(int nb) {
    __shared__ int sh[256];
    const int tid = threadIdx.x;
    int v = (tid < nb) ? g_bsum[tid] : 0;
    sh[tid] = v;
    __syncthreads();
    for (int off = 1; off < 256; off <<= 1) {
        int t = (tid >= off) ? sh[tid - off] : 0;
        __syncthreads();
        sh[tid] += t;
        __syncthreads();
    }
    if (tid < nb) g_bsum[tid] = sh[tid] - v;   // exclusive
}
// scan3: write ptr/cur with offsets
__global__ void k_scan3(int N) {
    __shared__ int sh[256];
    const int tid = threadIdx.x;
    const int base = blockIdx.x * SCHUNK + tid * 8;
    int d[8];
    int s = 0;
#pragma unroll
    for (int i = 0; i < 8; i++) {
        int idx = base + i;
        d[i] = (idx < N) ? g_deg[idx] : 0;
        s += d[i];
    }
    sh[tid] = s;
    __syncthreads();
    for (int off = 1; off < 256; off <<= 1) {
        int v = (tid >= off) ? sh[tid - off] : 0;
        __syncthreads();
        sh[tid] += v;
        __syncthreads();
    }
    int run = g_bsum[blockIdx.x] + sh[tid] - s;   // exclusive prefix
#pragma unroll
    for (int i = 0; i < 8; i++) {
        int idx = base + i;
        if (idx < N) {
            g_ptr[idx] = run;
            g_cur[idx] = run;
            run += d[i];
            if (idx == N - 1) g_ptr[N] = run;
        }
    }
}
__global__ void k_fill_csr(const int* __restrict__ src, const int* __restrict__ dst,
                           int E, int N) {
    int e = blockIdx.x * blockDim.x + threadIdx.x;
    if (e >= E) return;
    unsigned s = (unsigned)src[e], d = (unsigned)dst[e];
    if (s >= (unsigned)N || d >= (unsigned)N) return;
    int pos = atomicAdd(&g_cur[d], 1);
    if (pos < MAXE) g_csrc[pos] = (int)s;
}

// ---------------- layer-1 SGEMM (K=69, fp32): 128x128 tile, 8x8 microtile --
__global__ __launch_bounds__(256, 2)
void k_sgemm_l1(const float* __restrict__ A, const float* __restrict__ W,
                int M, int K) {
    __shared__ float As[8][128];
    __shared__ float Ws[8][128];
    const int tid = threadIdx.x;
    const int m0 = blockIdx.x * 128;
    const int n0 = blockIdx.y * 128;
    const int wrow = tid >> 5;
    const int wcol = (tid & 31) * 4;
    const int tx = tid & 15;
    const int ty = tid >> 4;

    float acc[8][8] = {};

    for (int k0 = 0; k0 < K; k0 += 8) {
        __syncthreads();
#pragma unroll
        for (int i = 0; i < 4; i++) {
            int idx = tid + i * 256;
            int r = idx >> 3, kk = idx & 7;
            int gm = m0 + r, gk = k0 + kk;
            As[kk][r] = (gm < M && gk < K) ? A[(size_t)gm * K + gk] : 0.f;
        }
        {
            int gk = k0 + wrow;
            float4 w = (gk < K) ? *(const float4*)(W + (size_t)gk * HID + n0 + wcol)
                                : make_float4(0.f, 0.f, 0.f, 0.f);
            *(float4*)&Ws[wrow][wcol] = w;
        }
        __syncthreads();
#pragma unroll
        for (int kk = 0; kk < 8; kk++) {
            float4 a0 = *(const float4*)&As[kk][ty * 4];
            float4 a1 = *(const float4*)&As[kk][64 + ty * 4];
            float4 b0 = *(const float4*)&Ws[kk][tx * 4];
            float4 b1 = *(const float4*)&Ws[kk][64 + tx * 4];
            float a[8] = {a0.x, a0.y, a0.z, a0.w, a1.x, a1.y, a1.z, a1.w};
            float b[8] = {b0.x, b0.y, b0.z, b0.w, b1.x, b1.y, b1.z, b1.w};
#pragma unroll
            for (int i = 0; i < 8; i++)
#pragma unroll
                for (int j = 0; j < 8; j++)
                    acc[i][j] = fmaf(a[i], b[j], acc[i][j]);
        }
    }

#pragma unroll
    for (int i = 0; i < 8; i++) {
        int gm = m0 + ((i < 4) ? (ty * 4 + i) : (64 + ty * 4 + i - 4));
        if (gm >= M) continue;
        float dn = g_dinv[gm];
        size_t off = (size_t)gm * HID + n0 + tx * 4;
        *(float4*)(g_h + off) = make_float4(acc[i][0] * dn, acc[i][1] * dn,
                                            acc[i][2] * dn, acc[i][3] * dn);
        *(float4*)(g_h + off + 64) = make_float4(acc[i][4] * dn, acc[i][5] * dn,
                                                 acc[i][6] * dn, acc[i][7] * dn);
    }
}

// ---------------- K=256 GEMM on tensor cores (tf32 mma, fp32 accum) --------
// g_h[m] = (relu(g_a)@W)[m] * dinv[m]
// 128x128 block tile, 8 warps each 64x32, m16n8k8 mma, double-buffered SMEM.
__global__ __launch_bounds__(256, 2)
void k_mma256(const float* __restrict__ W, int M) {
    const float* Asrc = (const float*)g_a;

    __shared__ float As[2][8][136];   // [buf][k][m] (+pad: 136%32==8 -> conflict-free frags)
    __shared__ float Ws[2][8][136];   // [buf][k][n]

    const int tid = threadIdx.x;
    const int lane = tid & 31;
    const int warp = tid >> 5;
    const int m0 = blockIdx.x * 128;
    const int n0 = blockIdx.y * 128;
    const int wm = (warp >> 2) * 64;   // warp m-offset: 0 / 64
    const int wn = (warp & 3) * 32;    // warp n-offset: 0/32/64/96

    const int arow = tid & 127;
    const int akg  = (tid >> 7) * 4;
    const int wrow = tid >> 5;
    const int wcol = (tid & 31) * 4;

    float4 pa, pw;

#define LDG_STAGE(k0)                                                          \
    do {                                                                       \
        int gm = m0 + arow;                                                    \
        if (gm < M) {                                                          \
            pa = *(const float4*)(Asrc + (size_t)gm * HID + (k0) + akg);       \
            pa.x = fmaxf(pa.x, 0.f); pa.y = fmaxf(pa.y, 0.f);                  \
            pa.z = fmaxf(pa.z, 0.f); pa.w = fmaxf(pa.w, 0.f);                  \
        } else pa = make_float4(0.f, 0.f, 0.f, 0.f);                           \
        pw = *(const float4*)(W + (size_t)((k0) + wrow) * HID + n0 + wcol);    \
    } while (0)

#define STS_STAGE(buf)                                                         \
    do {                                                                       \
        As[buf][akg + 0][arow] = to_tf32(pa.x);                                \
        As[buf][akg + 1][arow] = to_tf32(pa.y);                                \
        As[buf][akg + 2][arow] = to_tf32(pa.z);                                \
        As[buf][akg + 3][arow] = to_tf32(pa.w);                                \
        float4 cw = make_float4(to_tf32(pw.x), to_tf32(pw.y),                  \
                                to_tf32(pw.z), to_tf32(pw.w));                 \
        *(float4*)&Ws[buf][wrow][wcol] = cw;                                   \
    } while (0)

    float c[4][4][4] = {};   // [mt][nt][reg]

    LDG_STAGE(0);
    STS_STAGE(0);
    __syncthreads();

    const int NS = HID / 8;   // 32 k-stages
    for (int s = 0; s < NS; s++) {
        if (s + 1 < NS) LDG_STAGE((s + 1) * 8);
        const int buf = s & 1;

        // load fragments (canonical m16n8k8 thread mapping)
        unsigned af[4][4], bf[4][2];
        const int kq = lane & 3;
        const int g8 = lane >> 2;
#pragma unroll
        for (int mt = 0; mt < 4; mt++) {
            int mr = wm + mt * 16 + g8;
            af[mt][0] = __float_as_uint(As[buf][kq][mr]);
            af[mt][1] = __float_as_uint(As[buf][kq][mr + 8]);
            af[mt][2] = __float_as_uint(As[buf][kq + 4][mr]);
            af[mt][3] = __float_as_uint(As[buf][kq + 4][mr + 8]);
        }
#pragma unroll
        for (int nt = 0; nt < 4; nt++) {
            int nc = wn + nt * 8 + g8;
            bf[nt][0] = __float_as_uint(Ws[buf][kq][nc]);
            bf[nt][1] = __float_as_uint(Ws[buf][kq + 4][nc]);
        }
#pragma unroll
        for (int mt = 0; mt < 4; mt++)
#pragma unroll
            for (int nt = 0; nt < 4; nt++) {
                asm volatile(
                    "mma.sync.aligned.m16n8k8.row.col.f32.tf32.tf32.f32 "
                    "{%0,%1,%2,%3}, {%4,%5,%6,%7}, {%8,%9}, {%0,%1,%2,%3};"
                    : "+f"(c[mt][nt][0]), "+f"(c[mt][nt][1]),
                      "+f"(c[mt][nt][2]), "+f"(c[mt][nt][3])
                    : "r"(af[mt][0]), "r"(af[mt][1]), "r"(af[mt][2]), "r"(af[mt][3]),
                      "r"(bf[nt][0]), "r"(bf[nt][1]));
            }

        if (s + 1 < NS) {
            STS_STAGE((s + 1) & 1);
            __syncthreads();
        }
    }
#undef LDG_STAGE
#undef STS_STAGE

    // epilogue: g_h = C * dinv[row]
    const int g8 = lane >> 2;
    const int cq = (lane & 3) * 2;
#pragma unroll
    for (int mt = 0; mt < 4; mt++) {
        int r0 = m0 + wm + mt * 16 + g8;
        int r1 = r0 + 8;
        float dn0 = (r0 < M) ? g_dinv[r0] : 0.f;
        float dn1 = (r1 < M) ? g_dinv[r1] : 0.f;
#pragma unroll
        for (int nt = 0; nt < 4; nt++) {
            int col = n0 + wn + nt * 8 + cq;
            if (r0 < M)
                *(float2*)(g_h + (size_t)r0 * HID + col) =
                    make_float2(c[mt][nt][0] * dn0, c[mt][nt][1] * dn0);
            if (r1 < M)
                *(float2*)(g_h + (size_t)r1 * HID + col) =
                    make_float2(c[mt][nt][2] * dn1, c[mt][nt][3] * dn1);
        }
    }
}

// ---------------- CSR aggregation: one warp per dst node -------------------
__global__ void k_agg(const float* __restrict__ bias, int N) {
    int node = blockIdx.x * (blockDim.x >> 5) + (threadIdx.x >> 5);
    int lane = threadIdx.x & 31;
    if (node >= N) return;
    const int c0 = lane * 4, c1 = 128 + lane * 4;

    const float* selfr = g_h + (size_t)node * HID;
    float4 a0 = *(const float4*)(selfr + c0);
    float4 a1 = *(const float4*)(selfr + c1);

    int beg = g_ptr[node], end = g_ptr[node + 1];
    for (int j = beg; j < end; j++) {
        int s = g_csrc[j];
        const float* r = g_h + (size_t)s * HID;
        float4 v0 = *(const float4*)(r + c0);
        float4 v1 = *(const float4*)(r + c1);
        a0.x += v0.x; a0.y += v0.y; a0.z += v0.z; a0.w += v0.w;
        a1.x += v1.x; a1.y += v1.y; a1.z += v1.z; a1.w += v1.w;
    }
    float dn = g_dinv[node];
    float4 b0 = *(const float4*)(bias + c0);
    float4 b1 = *(const float4*)(bias + c1);
    float* o = g_a + (size_t)node * HID;
    *(float4*)(o + c0) = make_float4(fmaf(a0.x, dn, b0.x), fmaf(a0.y, dn, b0.y),
                                     fmaf(a0.z, dn, b0.z), fmaf(a0.w, dn, b0.w));
    *(float4*)(o + c1) = make_float4(fmaf(a1.x, dn, b1.x), fmaf(a1.y, dn, b1.y),
                                     fmaf(a1.z, dn, b1.z), fmaf(a1.w, dn, b1.w));
}

// ---------------- pooling + head ----------------
__global__ void k_zero_pool(int G) {
    long long t = (long long)blockIdx.x * blockDim.x + threadIdx.x;
    long long n = (long long)G * HID;
    if (t < n) g_pool[t] = 0.f;
    if (t < G) g_cnt[t] = 0.f;
}

__global__ void k_pool(const int* __restrict__ batch, int N, int G) {
    long long t = (long long)blockIdx.x * blockDim.x + threadIdx.x;
    int i = (int)(t >> 6);
    int c = (int)(t & 63) * 4;
    if (i >= N) return;
    unsigned g = (unsigned)batch[i];
    if (g >= (unsigned)G) return;
    float4 v = *(const float4*)(g_a + (size_t)i * HID + c);
    float* p = g_pool + (size_t)g * HID + c;
    asm volatile("red.global.add.v4.f32 [%0], {%1, %2, %3, %4};"
                 :: "l"(p), "f"(v.x), "f"(v.y), "f"(v.z), "f"(v.w)
                 : "memory");
    if (c == 0) atomicAdd(&g_cnt[g], 1.f);
}

__global__ void k_head(const float* __restrict__ Wl, const float* __restrict__ bl,
                       float* __restrict__ out) {
    int g = blockIdx.x;
    int t = threadIdx.x;  // 256
    float cn = fmaxf(g_cnt[g], 1.f);
    float v = g_pool[(size_t)g * HID + t] / cn;
    float p0 = v * Wl[t * 2 + 0];
    float p1 = v * Wl[t * 2 + 1];
    __shared__ float s0[256], s1[256];
    s0[t] = p0; s1[t] = p1;
    __syncthreads();
    for (int st = 128; st > 0; st >>= 1) {
        if (t < st) { s0[t] += s0[t + st]; s1[t] += s1[t + st]; }
        __syncthreads();
    }
    if (t == 0) {
        out[g * 2 + 0] = s0[0] + bl[0];
        out[g * 2 + 1] = s1[0] + bl[1];
    }
}

// ---------------------------------------------------------------------------
extern "C" void kernel_launch(void* const* d_in, const int* in_sizes, int n_in,
                              void* d_out, int out_size) {
    const float* x   = (const float*)d_in[0];
    const int*   ei  = (const int*)d_in[1];
    const int*   bat = (const int*)d_in[2];
    const float* W1 = (const float*)d_in[3];
    const float* b1 = (const float*)d_in[4];
    const float* W2 = (const float*)d_in[5];
    const float* b2 = (const float*)d_in[6];
    const float* W3 = (const float*)d_in[7];
    const float* b3 = (const float*)d_in[8];
    const float* W4 = (const float*)d_in[9];
    const float* b4 = (const float*)d_in[10];
    const float* Wl = (const float*)d_in[11];
    const float* bl = (const float*)d_in[12];
    float* out = (float*)d_out;

    const int N  = in_sizes[2];
    const int E  = in_sizes[1] / 2;
    const int K1 = in_sizes[0] / N;   // IN_DIM (69)
    const int G  = out_size / 2;

    const int* src = ei;
    const int* dst = ei + E;

    const int TB = 256;
    const int nScanBlocks = (N + SCHUNK - 1) / SCHUNK;

    // ---- CSR build + dinv (once, reused by all 4 layers) ----
    k_zero_deg<<<(N + TB - 1) / TB, TB>>>(N);
    k_count_deg<<<(E + TB - 1) / TB, TB>>>(dst, E, N);
    k_dinv<<<(N + TB - 1) / TB, TB>>>(N);
    k_scan1<<<nScanBlocks, 256>>>(N);
    k_scan2<<<1, 256>>>(nScanBlocks);
    k_scan3<<<nScanBlocks, 256>>>(N);
    k_fill_csr<<<(E + TB - 1) / TB, TB>>>(src, dst, E, N);

    dim3 gemmGrid((N + 127) / 128, HID / 128);
    const unsigned aggGrid = (unsigned)((N + 7) / 8);

    // ---- layer 1 (fp32, K=69) ----
    k_sgemm_l1<<<gemmGrid, 256>>>(x, W1, N, K1);
    k_agg<<<aggGrid, 256>>>(b1, N);
    // ---- layers 2-4 (tf32 tensor cores) ----
    k_mma256<<<gemmGrid, 256>>>(W2, N);
    k_agg<<<aggGrid, 256>>>(b2, N);
    k_mma256<<<gemmGrid, 256>>>(W3, N);
    k_agg<<<aggGrid, 256>>>(b3, N);
    k_mma256<<<gemmGrid, 256>>>(W4, N);
    k_agg<<<aggGrid, 256>>>(b4, N);

    // ---- pool + head ----
    k_zero_pool<<<(unsigned)(((long long)G * HID + TB - 1) / TB), TB>>>(G);
    k_pool<<<(unsigned)(((long long)N * 64 + TB - 1) / TB), TB>>>(bat, N, G);
    k_head<<<G, 256>>>(Wl, bl, out);
}

// round 7
// speedup vs baseline: 3.8941x; 1.2890x over previous
#include <cuda_runtime.h>
#include <cstdint>

// ---------------------------------------------------------------------------
// GCN: L1-L3: (GEMM -> norm-agg(+bias) -> relu). Layer 4 + pool + head folded:
//   out_g = mean_{i in g}( S * (relu(h3) @ (W4@Wl)) )_i + (b4@Wl + bl)
// using linearity of layer 4, pooling, and the head. S = D^-1/2 (A+I) D^-1/2.
// GEMMs write hs = h*dinv; CSR agg: out[d] = dinv[d]*(hs[d]+sum hs[src]) + b.
// ---------------------------------------------------------------------------

#define MAXN 100000
#define MAXE 400000
#define HID  256
#define MAXG 4096
#define SCHUNK 2048

__device__ float g_h[(size_t)MAXN * HID];
__device__ float g_a[(size_t)MAXN * HID];
__device__ float g_hs2[(size_t)MAXN * 2];    // layer-4 folded features
__device__ float g_dinv[MAXN];
__device__ int   g_deg[MAXN];
__device__ int   g_ptr[MAXN + 1];
__device__ int   g_cur[MAXN];
__device__ int   g_csrc[MAXE];
__device__ int   g_bsum[256];
__device__ float g_w4l[HID * 2 + 2];         // W4@Wl (512) then b4@Wl+bl (2)
__device__ float g_pool[(size_t)MAXG * 2];
__device__ float g_cnt[MAXG];

__device__ __forceinline__ float to_tf32(float x) {
    float r;
    asm("cvt.rna.tf32.f32 %0, %1;" : "=f"(r) : "f"(x));
    return r;
}

// ---------------- CSR build ----------------
__global__ void k_zero_deg(int N) {
    int i = blockIdx.x * blockDim.x + threadIdx.x;
    if (i < N) g_deg[i] = 0;
}
__global__ void k_count_deg(const int* __restrict__ dst, int E, int N) {
    int e = blockIdx.x * blockDim.x + threadIdx.x;
    if (e < E) {
        unsigned d = (unsigned)dst[e];
        if (d < (unsigned)N) atomicAdd(&g_deg[d], 1);
    }
}
__global__ void k_dinv(int N) {
    int i = blockIdx.x * blockDim.x + threadIdx.x;
    if (i < N) g_dinv[i] = rsqrtf((float)g_deg[i] + 1.f);
}
__global__ void k_scan1(int N) {
    __shared__ int sh[256];
    const int tid = threadIdx.x;
    const int base = blockIdx.x * SCHUNK + tid * 8;
    int s = 0;
#pragma unroll
    for (int i = 0; i < 8; i++) {
        int idx = base + i;
        if (idx < N) s += g_deg[idx];
    }
    sh[tid] = s;
    __syncthreads();
    for (int off = 1; off < 256; off <<= 1) {
        int v = (tid >= off) ? sh[tid - off] : 0;
        __syncthreads();
        sh[tid] += v;
        __syncthreads();
    }
    if (tid == 255) g_bsum[blockIdx.x] = sh[255];
}
__global__ void k_scan2(int nb) {
    __shared__ int sh[256];
    const int tid = threadIdx.x;
    int v = (tid < nb) ? g_bsum[tid] : 0;
    sh[tid] = v;
    __syncthreads();
    for (int off = 1; off < 256; off <<= 1) {
        int t = (tid >= off) ? sh[tid - off] : 0;
        __syncthreads();
        sh[tid] += t;
        __syncthreads();
    }
    if (tid < nb) g_bsum[tid] = sh[tid] - v;
}
__global__ void k_scan3(int N) {
    __shared__ int sh[256];
    const int tid = threadIdx.x;
    const int base = blockIdx.x * SCHUNK + tid * 8;
    int d[8];
    int s = 0;
#pragma unroll
    for (int i = 0; i < 8; i++) {
        int idx = base + i;
        d[i] = (idx < N) ? g_deg[idx] : 0;
        s += d[i];
    }
    sh[tid] = s;
    __syncthreads();
    for (int off = 1; off < 256; off <<= 1) {
        int v = (tid >= off) ? sh[tid - off] : 0;
        __syncthreads();
        sh[tid] += v;
        __syncthreads();
    }
    int run = g_bsum[blockIdx.x] + sh[tid] - s;
#pragma unroll
    for (int i = 0; i < 8; i++) {
        int idx = base + i;
        if (idx < N) {
            g_ptr[idx] = run;
            g_cur[idx] = run;
            run += d[i];
            if (idx == N - 1) g_ptr[N] = run;
        }
    }
}
__global__ void k_fill_csr(const int* __restrict__ src, const int* __restrict__ dst,
                           int E, int N) {
    int e = blockIdx.x * blockDim.x + threadIdx.x;
    if (e >= E) return;
    unsigned s = (unsigned)src[e], d = (unsigned)dst[e];
    if (s >= (unsigned)N || d >= (unsigned)N) return;
    int pos = atomicAdd(&g_cur[d], 1);
    if (pos < MAXE) g_csrc[pos] = (int)s;
}

// ---------------- fold W4@Wl and b4@Wl+bl (tiny, one block) ----------------
__global__ void k_w4l(const float* __restrict__ W4, const float* __restrict__ Wl,
                      const float* __restrict__ b4, const float* __restrict__ bl) {
    __shared__ float wl[HID * 2];
    const int tid = threadIdx.x;   // 256
    wl[tid] = Wl[tid];
    wl[tid + 256] = Wl[tid + 256];
    __syncthreads();
    float s0 = 0.f, s1 = 0.f;
    for (int k = 0; k < HID; k++) {
        float w = W4[(size_t)tid * HID + k];   // W4 row tid? No: W4[k_in][k_out]
        (void)w;
        break;
    }
    // W4 is [256 in, 256 out] row-major; W4l[r][c] = sum_k W4[r][k]*Wl[k][c]
    s0 = 0.f; s1 = 0.f;
    for (int k = 0; k < HID; k++) {
        float w = W4[(size_t)tid * HID + k];
        s0 = fmaf(w, wl[k * 2 + 0], s0);
        s1 = fmaf(w, wl[k * 2 + 1], s1);
    }
    g_w4l[tid * 2 + 0] = s0;
    g_w4l[tid * 2 + 1] = s1;
    // bias fold: b4l[c] = sum_k b4[k]*Wl[k][c] + bl[c]
    __shared__ float r0[256], r1[256];
    float b = b4[tid];
    r0[tid] = b * wl[tid * 2 + 0];
    r1[tid] = b * wl[tid * 2 + 1];
    __syncthreads();
    for (int st = 128; st > 0; st >>= 1) {
        if (tid < st) { r0[tid] += r0[tid + st]; r1[tid] += r1[tid + st]; }
        __syncthreads();
    }
    if (tid == 0) {
        g_w4l[HID * 2 + 0] = r0[0] + bl[0];
        g_w4l[HID * 2 + 1] = r1[0] + bl[1];
    }
}

// ---------------- layer-1 SGEMM (K=69, fp32) ----------------
__global__ __launch_bounds__(256, 2)
void k_sgemm_l1(const float* __restrict__ A, const float* __restrict__ W,
                int M, int K) {
    __shared__ float As[8][128];
    __shared__ float Ws[8][128];
    const int tid = threadIdx.x;
    const int m0 = blockIdx.x * 128;
    const int n0 = blockIdx.y * 128;
    const int wrow = tid >> 5;
    const int wcol = (tid & 31) * 4;
    const int tx = tid & 15;
    const int ty = tid >> 4;

    float acc[8][8] = {};

    for (int k0 = 0; k0 < K; k0 += 8) {
        __syncthreads();
#pragma unroll
        for (int i = 0; i < 4; i++) {
            int idx = tid + i * 256;
            int r = idx >> 3, kk = idx & 7;
            int gm = m0 + r, gk = k0 + kk;
            As[kk][r] = (gm < M && gk < K) ? A[(size_t)gm * K + gk] : 0.f;
        }
        {
            int gk = k0 + wrow;
            float4 w = (gk < K) ? *(const float4*)(W + (size_t)gk * HID + n0 + wcol)
                                : make_float4(0.f, 0.f, 0.f, 0.f);
            *(float4*)&Ws[wrow][wcol] = w;
        }
        __syncthreads();
#pragma unroll
        for (int kk = 0; kk < 8; kk++) {
            float4 a0 = *(const float4*)&As[kk][ty * 4];
            float4 a1 = *(const float4*)&As[kk][64 + ty * 4];
            float4 b0 = *(const float4*)&Ws[kk][tx * 4];
            float4 b1 = *(const float4*)&Ws[kk][64 + tx * 4];
            float a[8] = {a0.x, a0.y, a0.z, a0.w, a1.x, a1.y, a1.z, a1.w};
            float b[8] = {b0.x, b0.y, b0.z, b0.w, b1.x, b1.y, b1.z, b1.w};
#pragma unroll
            for (int i = 0; i < 8; i++)
#pragma unroll
                for (int j = 0; j < 8; j++)
                    acc[i][j] = fmaf(a[i], b[j], acc[i][j]);
        }
    }

#pragma unroll
    for (int i = 0; i < 8; i++) {
        int gm = m0 + ((i < 4) ? (ty * 4 + i) : (64 + ty * 4 + i - 4));
        if (gm >= M) continue;
        float dn = g_dinv[gm];
        size_t off = (size_t)gm * HID + n0 + tx * 4;
        *(float4*)(g_h + off) = make_float4(acc[i][0] * dn, acc[i][1] * dn,
                                            acc[i][2] * dn, acc[i][3] * dn);
        *(float4*)(g_h + off + 64) = make_float4(acc[i][4] * dn, acc[i][5] * dn,
                                                 acc[i][6] * dn, acc[i][7] * dn);
    }
}

// ---------------- K=256 GEMM on tensor cores (tf32 mma) ----------------
__global__ __launch_bounds__(256, 2)
void k_mma256(const float* __restrict__ W, int M) {
    const float* Asrc = (const float*)g_a;

    __shared__ float As[2][8][136];
    __shared__ float Ws[2][8][136];

    const int tid = threadIdx.x;
    const int lane = tid & 31;
    const int warp = tid >> 5;
    const int m0 = blockIdx.x * 128;
    const int n0 = blockIdx.y * 128;
    const int wm = (warp >> 2) * 64;
    const int wn = (warp & 3) * 32;

    const int arow = tid & 127;
    const int akg  = (tid >> 7) * 4;
    const int wrow = tid >> 5;
    const int wcol = (tid & 31) * 4;

    float4 pa, pw;

#define LDG_STAGE(k0)                                                          \
    do {                                                                       \
        int gm = m0 + arow;                                                    \
        if (gm < M) {                                                          \
            pa = *(const float4*)(Asrc + (size_t)gm * HID + (k0) + akg);       \
            pa.x = fmaxf(pa.x, 0.f); pa.y = fmaxf(pa.y, 0.f);                  \
            pa.z = fmaxf(pa.z, 0.f); pa.w = fmaxf(pa.w, 0.f);                  \
        } else pa = make_float4(0.f, 0.f, 0.f, 0.f);                           \
        pw = *(const float4*)(W + (size_t)((k0) + wrow) * HID + n0 + wcol);    \
    } while (0)

#define STS_STAGE(buf)                                                         \
    do {                                                                       \
        As[buf][akg + 0][arow] = to_tf32(pa.x);                                \
        As[buf][akg + 1][arow] = to_tf32(pa.y);                                \
        As[buf][akg + 2][arow] = to_tf32(pa.z);                                \
        As[buf][akg + 3][arow] = to_tf32(pa.w);                                \
        float4 cw = make_float4(to_tf32(pw.x), to_tf32(pw.y),                  \
                                to_tf32(pw.z), to_tf32(pw.w));                 \
        *(float4*)&Ws[buf][wrow][wcol] = cw;                                   \
    } while (0)

    float c[4][4][4] = {};

    LDG_STAGE(0);
    STS_STAGE(0);
    __syncthreads();

    const int NS = HID / 8;
    for (int s = 0; s < NS; s++) {
        if (s + 1 < NS) LDG_STAGE((s + 1) * 8);
        const int buf = s & 1;

        unsigned af[4][4], bf[4][2];
        const int kq = lane & 3;
        const int g8 = lane >> 2;
#pragma unroll
        for (int mt = 0; mt < 4; mt++) {
            int mr = wm + mt * 16 + g8;
            af[mt][0] = __float_as_uint(As[buf][kq][mr]);
            af[mt][1] = __float_as_uint(As[buf][kq][mr + 8]);
            af[mt][2] = __float_as_uint(As[buf][kq + 4][mr]);
            af[mt][3] = __float_as_uint(As[buf][kq + 4][mr + 8]);
        }
#pragma unroll
        for (int nt = 0; nt < 4; nt++) {
            int nc = wn + nt * 8 + g8;
            bf[nt][0] = __float_as_uint(Ws[buf][kq][nc]);
            bf[nt][1] = __float_as_uint(Ws[buf][kq + 4][nc]);
        }
#pragma unroll
        for (int mt = 0; mt < 4; mt++)
#pragma unroll
            for (int nt = 0; nt < 4; nt++) {
                asm volatile(
                    "mma.sync.aligned.m16n8k8.row.col.f32.tf32.tf32.f32 "
                    "{%0,%1,%2,%3}, {%4,%5,%6,%7}, {%8,%9}, {%0,%1,%2,%3};"
                    : "+f"(c[mt][nt][0]), "+f"(c[mt][nt][1]),
                      "+f"(c[mt][nt][2]), "+f"(c[mt][nt][3])
                    : "r"(af[mt][0]), "r"(af[mt][1]), "r"(af[mt][2]), "r"(af[mt][3]),
                      "r"(bf[nt][0]), "r"(bf[nt][1]));
            }

        if (s + 1 < NS) {
            STS_STAGE((s + 1) & 1);
            __syncthreads();
        }
    }
#undef LDG_STAGE
#undef STS_STAGE

    const int g8 = lane >> 2;
    const int cq = (lane & 3) * 2;
#pragma unroll
    for (int mt = 0; mt < 4; mt++) {
        int r0 = m0 + wm + mt * 16 + g8;
        int r1 = r0 + 8;
        float dn0 = (r0 < M) ? g_dinv[r0] : 0.f;
        float dn1 = (r1 < M) ? g_dinv[r1] : 0.f;
#pragma unroll
        for (int nt = 0; nt < 4; nt++) {
            int col = n0 + wn + nt * 8 + cq;
            if (r0 < M)
                *(float2*)(g_h + (size_t)r0 * HID + col) =
                    make_float2(c[mt][nt][0] * dn0, c[mt][nt][1] * dn0);
            if (r1 < M)
                *(float2*)(g_h + (size_t)r1 * HID + col) =
                    make_float2(c[mt][nt][2] * dn1, c[mt][nt][3] * dn1);
        }
    }
}

// ---------------- CSR aggregation (256-wide): warp per node, unroll 4 ------
__global__ void k_agg(const float* __restrict__ bias, int N) {
    int node = blockIdx.x * (blockDim.x >> 5) + (threadIdx.x >> 5);
    int lane = threadIdx.x & 31;
    if (node >= N) return;
    const int c0 = lane * 4, c1 = 128 + lane * 4;

    const float* selfr = g_h + (size_t)node * HID;
    float4 a0 = *(const float4*)(selfr + c0);
    float4 a1 = *(const float4*)(selfr + c1);

    const int beg = g_ptr[node], end = g_ptr[node + 1];
    int j = beg;
#define ACC(v0, v1)                                                            \
    a0.x += v0.x; a0.y += v0.y; a0.z += v0.z; a0.w += v0.w;                    \
    a1.x += v1.x; a1.y += v1.y; a1.z += v1.z; a1.w += v1.w;
    for (; j + 4 <= end; j += 4) {
        int s0 = g_csrc[j], s1 = g_csrc[j + 1], s2 = g_csrc[j + 2], s3 = g_csrc[j + 3];
        const float* r0 = g_h + (size_t)s0 * HID;
        const float* r1 = g_h + (size_t)s1 * HID;
        const float* r2 = g_h + (size_t)s2 * HID;
        const float* r3 = g_h + (size_t)s3 * HID;
        float4 p0 = *(const float4*)(r0 + c0), q0 = *(const float4*)(r0 + c1);
        float4 p1 = *(const float4*)(r1 + c0), q1 = *(const float4*)(r1 + c1);
        float4 p2 = *(const float4*)(r2 + c0), q2 = *(const float4*)(r2 + c1);
        float4 p3 = *(const float4*)(r3 + c0), q3 = *(const float4*)(r3 + c1);
        ACC(p0, q0) ACC(p1, q1) ACC(p2, q2) ACC(p3, q3)
    }
    for (; j < end; j++) {
        int s = g_csrc[j];
        const float* r = g_h + (size_t)s * HID;
        float4 p = *(const float4*)(r + c0), q = *(const float4*)(r + c1);
        ACC(p, q)
    }
#undef ACC
    float dn = g_dinv[node];
    float4 b0 = *(const float4*)(bias + c0);
    float4 b1 = *(const float4*)(bias + c1);
    float* o = g_a + (size_t)node * HID;
    *(float4*)(o + c0) = make_float4(fmaf(a0.x, dn, b0.x), fmaf(a0.y, dn, b0.y),
                                     fmaf(a0.z, dn, b0.z), fmaf(a0.w, dn, b0.w));
    *(float4*)(o + c1) = make_float4(fmaf(a1.x, dn, b1.x), fmaf(a1.y, dn, b1.y),
                                     fmaf(a1.z, dn, b1.z), fmaf(a1.w, dn, b1.w));
}

// ---------------- layer-4 folded GEMV: hs2 = relu(g_a) @ W4l * dinv --------
__global__ void k_gemv4(int M) {
    __shared__ float w4l[HID * 2];
    const int tid = threadIdx.x;   // 256 = 8 warps
    w4l[tid] = g_w4l[tid];
    w4l[tid + 256] = g_w4l[tid + 256];
    __syncthreads();
    int row = blockIdx.x * 8 + (tid >> 5);
    if (row >= M) return;
    int lane = tid & 31;
    const float* a = g_a + (size_t)row * HID + lane * 8;
    float4 v0 = *(const float4*)(a);
    float4 v1 = *(const float4*)(a + 4);
    float s0 = 0.f, s1 = 0.f;
    const float* w = w4l + lane * 16;
    float vv[8] = {v0.x, v0.y, v0.z, v0.w, v1.x, v1.y, v1.z, v1.w};
#pragma unroll
    for (int i = 0; i < 8; i++) {
        float r = fmaxf(vv[i], 0.f);
        s0 = fmaf(r, w[i * 2 + 0], s0);
        s1 = fmaf(r, w[i * 2 + 1], s1);
    }
#pragma unroll
    for (int off = 16; off > 0; off >>= 1) {
        s0 += __shfl_down_sync(0xffffffffu, s0, off);
        s1 += __shfl_down_sync(0xffffffffu, s1, off);
    }
    if (lane == 0) {
        float dn = g_dinv[row];
        *(float2*)(g_hs2 + (size_t)row * 2) = make_float2(s0 * dn, s1 * dn);
    }
}

// ---------------- layer-4 agg (2 cols) fused with mean-pool accumulation ---
__global__ void k_agg2_pool(const int* __restrict__ batch, int N, int G) {
    int node = blockIdx.x * blockDim.x + threadIdx.x;
    if (node >= N) return;
    float2 acc = *(const float2*)(g_hs2 + (size_t)node * 2);
    const int beg = g_ptr[node], end = g_ptr[node + 1];
    int j = beg;
    for (; j + 4 <= end; j += 4) {
        int s0 = g_csrc[j], s1 = g_csrc[j + 1], s2 = g_csrc[j + 2], s3 = g_csrc[j + 3];
        float2 v0 = *(const float2*)(g_hs2 + (size_t)s0 * 2);
        float2 v1 = *(const float2*)(g_hs2 + (size_t)s1 * 2);
        float2 v2 = *(const float2*)(g_hs2 + (size_t)s2 * 2);
        float2 v3 = *(const float2*)(g_hs2 + (size_t)s3 * 2);
        acc.x += v0.x + v1.x + v2.x + v3.x;
        acc.y += v0.y + v1.y + v2.y + v3.y;
    }
    for (; j < end; j++) {
        float2 v = *(const float2*)(g_hs2 + (size_t)g_csrc[j] * 2);
        acc.x += v.x; acc.y += v.y;
    }
    float dn = g_dinv[node];
    unsigned g = (unsigned)batch[node];
    if (g >= (unsigned)G) return;
    float* p = g_pool + (size_t)g * 2;
    asm volatile("red.global.add.v2.f32 [%0], {%1, %2};"
                 :: "l"(p), "f"(acc.x * dn), "f"(acc.y * dn) : "memory");
    atomicAdd(&g_cnt[g], 1.f);
}

__global__ void k_zero_pool(int G) {
    int t = blockIdx.x * blockDim.x + threadIdx.x;
    if (t < G * 2) g_pool[t] = 0.f;
    if (t < G) g_cnt[t] = 0.f;
}

__global__ void k_head2(float* __restrict__ out, int G) {
    int g = blockIdx.x * blockDim.x + threadIdx.x;
    if (g >= G) return;
    float cn = fmaxf(g_cnt[g], 1.f);
    out[g * 2 + 0] = g_pool[g * 2 + 0] / cn + g_w4l[HID * 2 + 0];
    out[g * 2 + 1] = g_pool[g * 2 + 1] / cn + g_w4l[HID * 2 + 1];
}

// ---------------------------------------------------------------------------
extern "C" void kernel_launch(void* const* d_in, const int* in_sizes, int n_in,
                              void* d_out, int out_size) {
    const float* x   = (const float*)d_in[0];
    const int*   ei  = (const int*)d_in[1];
    const int*   bat = (const int*)d_in[2];
    const float* W1 = (const float*)d_in[3];
    const float* b1 = (const float*)d_in[4];
    const float* W2 = (const float*)d_in[5];
    const float* b2 = (const float*)d_in[6];
    const float* W3 = (const float*)d_in[7];
    const float* b3 = (const float*)d_in[8];
    const float* W4 = (const float*)d_in[9];
    const float* b4 = (const float*)d_in[10];
    const float* Wl = (const float*)d_in[11];
    const float* bl = (const float*)d_in[12];
    float* out = (float*)d_out;

    const int N  = in_sizes[2];
    const int E  = in_sizes[1] / 2;
    const int K1 = in_sizes[0] / N;
    const int G  = out_size / 2;

    const int* src = ei;
    const int* dst = ei + E;

    const int TB = 256;
    const int nScanBlocks = (N + SCHUNK - 1) / SCHUNK;

    // ---- CSR build + dinv + folded W4l ----
    k_zero_deg<<<(N + TB - 1) / TB, TB>>>(N);
    k_count_deg<<<(E + TB - 1) / TB, TB>>>(dst, E, N);
    k_dinv<<<(N + TB - 1) / TB, TB>>>(N);
    k_scan1<<<nScanBlocks, 256>>>(N);
    k_scan2<<<1, 256>>>(nScanBlocks);
    k_scan3<<<nScanBlocks, 256>>>(N);
    k_fill_csr<<<(E + TB - 1) / TB, TB>>>(src, dst, E, N);
    k_w4l<<<1, 256>>>(W4, Wl, b4, bl);
    k_zero_pool<<<(G * 2 + TB - 1) / TB, TB>>>(G);

    dim3 gemmGrid((N + 127) / 128, HID / 128);
    const unsigned aggGrid = (unsigned)((N + 7) / 8);

    // ---- layers 1-3 ----
    k_sgemm_l1<<<gemmGrid, 256>>>(x, W1, N, K1);
    k_agg<<<aggGrid, 256>>>(b1, N);
    k_mma256<<<gemmGrid, 256>>>(W2, N);
    k_agg<<<aggGrid, 256>>>(b2, N);
    k_mma256<<<gemmGrid, 256>>>(W3, N);
    k_agg<<<aggGrid, 256>>>(b3, N);

    // ---- folded layer 4 + pool + head ----
    k_gemv4<<<(N + 7) / 8, 256>>>(N);
    k_agg2_pool<<<(N + TB - 1) / TB, TB>>>(bat, N, G);
    k_head2<<<(G + TB - 1) / TB, TB>>>(out, G);
}

// round 8
// speedup vs baseline: 4.0350x; 1.0362x over previous
#include <cuda_runtime.h>
#include <cstdint>

// ---------------------------------------------------------------------------
// GCN pipeline (S = D^-1/2 (A+I) D^-1/2):
//  L1 (commuted): xa = S·X  (69-wide agg), a1 = xa@W1 + b1
//  L2,L3: h = relu(a)@W * dinv (tf32 mma) ; a = dinv*(h_self + sum h_src) + b
//  L4 folded through pool+head: out_g = mean_g(S·(relu(a3)@(W4@Wl))) + (b4@Wl+bl)
// ---------------------------------------------------------------------------

#define MAXN 100000
#define MAXE 400000
#define HID  256
#define IND  69
#define MAXG 4096
#define SCHUNK 2048

__device__ float g_h[(size_t)MAXN * HID];
__device__ float g_a[(size_t)MAXN * HID];
__device__ float g_xa[(size_t)MAXN * IND];   // S·X
__device__ float g_hs2[(size_t)MAXN * 2];
__device__ float g_dinv[MAXN];
__device__ int   g_deg[MAXN];
__device__ int   g_ptr[MAXN + 1];
__device__ int   g_cur[MAXN];
__device__ int   g_csrc[MAXE];
__device__ int   g_bsum[256];
__device__ float g_w4l[HID * 2 + 2];
__device__ float g_pool[(size_t)MAXG * 2];
__device__ float g_cnt[MAXG];

__device__ __forceinline__ float to_tf32(float x) {
    float r;
    asm("cvt.rna.tf32.f32 %0, %1;" : "=f"(r) : "f"(x));
    return r;
}

// ---------------- CSR build ----------------
__global__ void k_zero_deg(int N) {
    int i = blockIdx.x * blockDim.x + threadIdx.x;
    if (i < N) g_deg[i] = 0;
}
__global__ void k_count_deg(const int* __restrict__ dst, int E, int N) {
    int e = blockIdx.x * blockDim.x + threadIdx.x;
    if (e < E) {
        unsigned d = (unsigned)dst[e];
        if (d < (unsigned)N) atomicAdd(&g_deg[d], 1);
    }
}
__global__ void k_dinv(int N) {
    int i = blockIdx.x * blockDim.x + threadIdx.x;
    if (i < N) g_dinv[i] = rsqrtf((float)g_deg[i] + 1.f);
}
__global__ void k_scan1(int N) {
    __shared__ int sh[256];
    const int tid = threadIdx.x;
    const int base = blockIdx.x * SCHUNK + tid * 8;
    int s = 0;
#pragma unroll
    for (int i = 0; i < 8; i++) {
        int idx = base + i;
        if (idx < N) s += g_deg[idx];
    }
    sh[tid] = s;
    __syncthreads();
    for (int off = 1; off < 256; off <<= 1) {
        int v = (tid >= off) ? sh[tid - off] : 0;
        __syncthreads();
        sh[tid] += v;
        __syncthreads();
    }
    if (tid == 255) g_bsum[blockIdx.x] = sh[255];
}
__global__ void k_scan2(int nb) {
    __shared__ int sh[256];
    const int tid = threadIdx.x;
    int v = (tid < nb) ? g_bsum[tid] : 0;
    sh[tid] = v;
    __syncthreads();
    for (int off = 1; off < 256; off <<= 1) {
        int t = (tid >= off) ? sh[tid - off] : 0;
        __syncthreads();
        sh[tid] += t;
        __syncthreads();
    }
    if (tid < nb) g_bsum[tid] = sh[tid] - v;
}
__global__ void k_scan3(int N) {
    __shared__ int sh[256];
    const int tid = threadIdx.x;
    const int base = blockIdx.x * SCHUNK + tid * 8;
    int d[8];
    int s = 0;
#pragma unroll
    for (int i = 0; i < 8; i++) {
        int idx = base + i;
        d[i] = (idx < N) ? g_deg[idx] : 0;
        s += d[i];
    }
    sh[tid] = s;
    __syncthreads();
    for (int off = 1; off < 256; off <<= 1) {
        int v = (tid >= off) ? sh[tid - off] : 0;
        __syncthreads();
        sh[tid] += v;
        __syncthreads();
    }
    int run = g_bsum[blockIdx.x] + sh[tid] - s;
#pragma unroll
    for (int i = 0; i < 8; i++) {
        int idx = base + i;
        if (idx < N) {
            g_ptr[idx] = run;
            g_cur[idx] = run;
            run += d[i];
            if (idx == N - 1) g_ptr[N] = run;
        }
    }
}
__global__ void k_fill_csr(const int* __restrict__ src, const int* __restrict__ dst,
                           int E, int N) {
    int e = blockIdx.x * blockDim.x + threadIdx.x;
    if (e >= E) return;
    unsigned s = (unsigned)src[e], d = (unsigned)dst[e];
    if (s >= (unsigned)N || d >= (unsigned)N) return;
    int pos = atomicAdd(&g_cur[d], 1);
    if (pos < MAXE) g_csrc[pos] = (int)s;
}

// ---------------- fold W4@Wl and b4@Wl+bl ----------------
__global__ void k_w4l(const float* __restrict__ W4, const float* __restrict__ Wl,
                      const float* __restrict__ b4, const float* __restrict__ bl) {
    __shared__ float wl[HID * 2];
    const int tid = threadIdx.x;   // 256
    wl[tid] = Wl[tid];
    wl[tid + 256] = Wl[tid + 256];
    __syncthreads();
    float s0 = 0.f, s1 = 0.f;
    for (int k = 0; k < HID; k++) {
        float w = W4[(size_t)tid * HID + k];
        s0 = fmaf(w, wl[k * 2 + 0], s0);
        s1 = fmaf(w, wl[k * 2 + 1], s1);
    }
    g_w4l[tid * 2 + 0] = s0;
    g_w4l[tid * 2 + 1] = s1;
    __shared__ float r0[256], r1[256];
    float b = b4[tid];
    r0[tid] = b * wl[tid * 2 + 0];
    r1[tid] = b * wl[tid * 2 + 1];
    __syncthreads();
    for (int st = 128; st > 0; st >>= 1) {
        if (tid < st) { r0[tid] += r0[tid + st]; r1[tid] += r1[tid + st]; }
        __syncthreads();
    }
    if (tid == 0) {
        g_w4l[HID * 2 + 0] = r0[0] + bl[0];
        g_w4l[HID * 2 + 1] = r1[0] + bl[1];
    }
}

// ---------------- layer-1 input agg: g_xa = S·X (69-wide, warp per node) ---
__global__ void k_aggx(const float* __restrict__ x, int N, int K) {
    int node = blockIdx.x * 8 + (threadIdx.x >> 5);
    int lane = threadIdx.x & 31;
    if (node >= N) return;
    const bool p0 = lane < K, p1 = lane + 32 < K, p2 = lane + 64 < K;
    float dn = g_dinv[node];

    const float* xr = x + (size_t)node * K;
    float a0 = p0 ? xr[lane] * dn : 0.f;
    float a1 = p1 ? xr[lane + 32] * dn : 0.f;
    float a2 = p2 ? xr[lane + 64] * dn : 0.f;

    const int beg = g_ptr[node], end = g_ptr[node + 1];
    int j = beg;
    for (; j + 2 <= end; j += 2) {
        int s0 = g_csrc[j], s1 = g_csrc[j + 1];
        float d0 = g_dinv[s0], d1 = g_dinv[s1];
        const float* r0 = x + (size_t)s0 * K;
        const float* r1 = x + (size_t)s1 * K;
        if (p0) { a0 = fmaf(r0[lane], d0, a0);      a0 = fmaf(r1[lane], d1, a0); }
        if (p1) { a1 = fmaf(r0[lane + 32], d0, a1); a1 = fmaf(r1[lane + 32], d1, a1); }
        if (p2) { a2 = fmaf(r0[lane + 64], d0, a2); a2 = fmaf(r1[lane + 64], d1, a2); }
    }
    for (; j < end; j++) {
        int s = g_csrc[j];
        float ds = g_dinv[s];
        const float* r = x + (size_t)s * K;
        if (p0) a0 = fmaf(r[lane], ds, a0);
        if (p1) a1 = fmaf(r[lane + 32], ds, a1);
        if (p2) a2 = fmaf(r[lane + 64], ds, a2);
    }
    float* o = g_xa + (size_t)node * K;
    if (p0) o[lane] = a0 * dn;
    if (p1) o[lane + 32] = a1 * dn;
    if (p2) o[lane + 64] = a2 * dn;
}

// ---------------- layer-1 SGEMM: g_a = g_xa @ W1 + b1 (K=69, fp32) ---------
__global__ __launch_bounds__(256, 2)
void k_sgemm_l1(const float* __restrict__ W, const float* __restrict__ bias,
                int M, int K) {
    __shared__ float As[8][128];
    __shared__ float Ws[8][128];
    const int tid = threadIdx.x;
    const int m0 = blockIdx.x * 128;
    const int n0 = blockIdx.y * 128;
    const int wrow = tid >> 5;
    const int wcol = (tid & 31) * 4;
    const int tx = tid & 15;
    const int ty = tid >> 4;

    float acc[8][8] = {};

    for (int k0 = 0; k0 < K; k0 += 8) {
        __syncthreads();
#pragma unroll
        for (int i = 0; i < 4; i++) {
            int idx = tid + i * 256;
            int r = idx >> 3, kk = idx & 7;
            int gm = m0 + r, gk = k0 + kk;
            As[kk][r] = (gm < M && gk < K) ? g_xa[(size_t)gm * K + gk] : 0.f;
        }
        {
            int gk = k0 + wrow;
            float4 w = (gk < K) ? *(const float4*)(W + (size_t)gk * HID + n0 + wcol)
                                : make_float4(0.f, 0.f, 0.f, 0.f);
            *(float4*)&Ws[wrow][wcol] = w;
        }
        __syncthreads();
#pragma unroll
        for (int kk = 0; kk < 8; kk++) {
            float4 a0 = *(const float4*)&As[kk][ty * 4];
            float4 a1 = *(const float4*)&As[kk][64 + ty * 4];
            float4 b0 = *(const float4*)&Ws[kk][tx * 4];
            float4 b1 = *(const float4*)&Ws[kk][64 + tx * 4];
            float a[8] = {a0.x, a0.y, a0.z, a0.w, a1.x, a1.y, a1.z, a1.w};
            float b[8] = {b0.x, b0.y, b0.z, b0.w, b1.x, b1.y, b1.z, b1.w};
#pragma unroll
            for (int i = 0; i < 8; i++)
#pragma unroll
                for (int j = 0; j < 8; j++)
                    acc[i][j] = fmaf(a[i], b[j], acc[i][j]);
        }
    }

    float4 bb0 = *(const float4*)(bias + n0 + tx * 4);
    float4 bb1 = *(const float4*)(bias + n0 + 64 + tx * 4);
#pragma unroll
    for (int i = 0; i < 8; i++) {
        int gm = m0 + ((i < 4) ? (ty * 4 + i) : (64 + ty * 4 + i - 4));
        if (gm >= M) continue;
        size_t off = (size_t)gm * HID + n0 + tx * 4;
        *(float4*)(g_a + off) = make_float4(acc[i][0] + bb0.x, acc[i][1] + bb0.y,
                                            acc[i][2] + bb0.z, acc[i][3] + bb0.w);
        *(float4*)(g_a + off + 64) = make_float4(acc[i][4] + bb1.x, acc[i][5] + bb1.y,
                                                 acc[i][6] + bb1.z, acc[i][7] + bb1.w);
    }
}

// ---------------- K=256 GEMM on tensor cores (tf32 mma) ----------------
// g_h[m] = (relu(g_a)@W)[m] * dinv[m]
__global__ __launch_bounds__(256, 2)
void k_mma256(const float* __restrict__ W, int M) {
    const float* Asrc = (const float*)g_a;

    __shared__ float As[2][8][136];
    __shared__ float Ws[2][8][136];

    const int tid = threadIdx.x;
    const int lane = tid & 31;
    const int warp = tid >> 5;
    const int m0 = blockIdx.x * 128;
    const int n0 = blockIdx.y * 128;
    const int wm = (warp >> 2) * 64;
    const int wn = (warp & 3) * 32;

    const int arow = tid & 127;
    const int akg  = (tid >> 7) * 4;
    const int wrow = tid >> 5;
    const int wcol = (tid & 31) * 4;

    float4 pa, pw;

#define LDG_STAGE(k0)                                                          \
    do {                                                                       \
        int gm = m0 + arow;                                                    \
        if (gm < M) {                                                          \
            pa = *(const float4*)(Asrc + (size_t)gm * HID + (k0) + akg);       \
            pa.x = fmaxf(pa.x, 0.f); pa.y = fmaxf(pa.y, 0.f);                  \
            pa.z = fmaxf(pa.z, 0.f); pa.w = fmaxf(pa.w, 0.f);                  \
        } else pa = make_float4(0.f, 0.f, 0.f, 0.f);                           \
        pw = *(const float4*)(W + (size_t)((k0) + wrow) * HID + n0 + wcol);    \
    } while (0)

#define STS_STAGE(buf)                                                         \
    do {                                                                       \
        As[buf][akg + 0][arow] = to_tf32(pa.x);                                \
        As[buf][akg + 1][arow] = to_tf32(pa.y);                                \
        As[buf][akg + 2][arow] = to_tf32(pa.z);                                \
        As[buf][akg + 3][arow] = to_tf32(pa.w);                                \
        float4 cw = make_float4(to_tf32(pw.x), to_tf32(pw.y),                  \
                                to_tf32(pw.z), to_tf32(pw.w));                 \
        *(float4*)&Ws[buf][wrow][wcol] = cw;                                   \
    } while (0)

    float c[4][4][4] = {};

    LDG_STAGE(0);
    STS_STAGE(0);
    __syncthreads();

    const int NS = HID / 8;
    for (int s = 0; s < NS; s++) {
        if (s + 1 < NS) LDG_STAGE((s + 1) * 8);
        const int buf = s & 1;

        unsigned af[4][4], bf[4][2];
        const int kq = lane & 3;
        const int g8 = lane >> 2;
#pragma unroll
        for (int mt = 0; mt < 4; mt++) {
            int mr = wm + mt * 16 + g8;
            af[mt][0] = __float_as_uint(As[buf][kq][mr]);
            af[mt][1] = __float_as_uint(As[buf][kq][mr + 8]);
            af[mt][2] = __float_as_uint(As[buf][kq + 4][mr]);
            af[mt][3] = __float_as_uint(As[buf][kq + 4][mr + 8]);
        }
#pragma unroll
        for (int nt = 0; nt < 4; nt++) {
            int nc = wn + nt * 8 + g8;
            bf[nt][0] = __float_as_uint(Ws[buf][kq][nc]);
            bf[nt][1] = __float_as_uint(Ws[buf][kq + 4][nc]);
        }
#pragma unroll
        for (int mt = 0; mt < 4; mt++)
#pragma unroll
            for (int nt = 0; nt < 4; nt++) {
                asm volatile(
                    "mma.sync.aligned.m16n8k8.row.col.f32.tf32.tf32.f32 "
                    "{%0,%1,%2,%3}, {%4,%5,%6,%7}, {%8,%9}, {%0,%1,%2,%3};"
                    : "+f"(c[mt][nt][0]), "+f"(c[mt][nt][1]),
                      "+f"(c[mt][nt][2]), "+f"(c[mt][nt][3])
                    : "r"(af[mt][0]), "r"(af[mt][1]), "r"(af[mt][2]), "r"(af[mt][3]),
                      "r"(bf[nt][0]), "r"(bf[nt][1]));
            }

        if (s + 1 < NS) {
            STS_STAGE((s + 1) & 1);
            __syncthreads();
        }
    }
#undef LDG_STAGE
#undef STS_STAGE

    const int g8 = lane >> 2;
    const int cq = (lane & 3) * 2;
#pragma unroll
    for (int mt = 0; mt < 4; mt++) {
        int r0 = m0 + wm + mt * 16 + g8;
        int r1 = r0 + 8;
        float dn0 = (r0 < M) ? g_dinv[r0] : 0.f;
        float dn1 = (r1 < M) ? g_dinv[r1] : 0.f;
#pragma unroll
        for (int nt = 0; nt < 4; nt++) {
            int col = n0 + wn + nt * 8 + cq;
            if (r0 < M)
                *(float2*)(g_h + (size_t)r0 * HID + col) =
                    make_float2(c[mt][nt][0] * dn0, c[mt][nt][1] * dn0);
            if (r1 < M)
                *(float2*)(g_h + (size_t)r1 * HID + col) =
                    make_float2(c[mt][nt][2] * dn1, c[mt][nt][3] * dn1);
        }
    }
}

// ---------------- CSR agg: 2 warps per node, each owns 128 cols ------------
__global__ void k_agg(const float* __restrict__ bias, int N) {
    int node = blockIdx.x * 4 + (threadIdx.x >> 6);
    int half = (threadIdx.x >> 5) & 1;
    int lane = threadIdx.x & 31;
    if (node >= N) return;
    const int c = half * 128 + lane * 4;

    float4 a = *(const float4*)(g_h + (size_t)node * HID + c);

    const int beg = g_ptr[node], end = g_ptr[node + 1];
    int j = beg;
#define ACC(v) a.x += v.x; a.y += v.y; a.z += v.z; a.w += v.w;
    for (; j + 4 <= end; j += 4) {
        int s0 = g_csrc[j], s1 = g_csrc[j + 1], s2 = g_csrc[j + 2], s3 = g_csrc[j + 3];
        float4 v0 = *(const float4*)(g_h + (size_t)s0 * HID + c);
        float4 v1 = *(const float4*)(g_h + (size_t)s1 * HID + c);
        float4 v2 = *(const float4*)(g_h + (size_t)s2 * HID + c);
        float4 v3 = *(const float4*)(g_h + (size_t)s3 * HID + c);
        ACC(v0) ACC(v1) ACC(v2) ACC(v3)
    }
    for (; j < end; j++) {
        float4 v = *(const float4*)(g_h + (size_t)g_csrc[j] * HID + c);
        ACC(v)
    }
#undef ACC
    float dn = g_dinv[node];
    float4 b = *(const float4*)(bias + c);
    *(float4*)(g_a + (size_t)node * HID + c) =
        make_float4(fmaf(a.x, dn, b.x), fmaf(a.y, dn, b.y),
                    fmaf(a.z, dn, b.z), fmaf(a.w, dn, b.w));
}

// ---------------- layer-4 folded GEMV: hs2 = relu(g_a) @ W4l * dinv --------
__global__ void k_gemv4(int M) {
    __shared__ float w4l[HID * 2];
    const int tid = threadIdx.x;   // 256
    w4l[tid] = g_w4l[tid];
    w4l[tid + 256] = g_w4l[tid + 256];
    __syncthreads();
    int row = blockIdx.x * 8 + (tid >> 5);
    if (row >= M) return;
    int lane = tid & 31;
    const float* a = g_a + (size_t)row * HID + lane * 8;
    float4 v0 = *(const float4*)(a);
    float4 v1 = *(const float4*)(a + 4);
    float s0 = 0.f, s1 = 0.f;
    const float* w = w4l + lane * 16;
    float vv[8] = {v0.x, v0.y, v0.z, v0.w, v1.x, v1.y, v1.z, v1.w};
#pragma unroll
    for (int i = 0; i < 8; i++) {
        float r = fmaxf(vv[i], 0.f);
        s0 = fmaf(r, w[i * 2 + 0], s0);
        s1 = fmaf(r, w[i * 2 + 1], s1);
    }
#pragma unroll
    for (int off = 16; off > 0; off >>= 1) {
        s0 += __shfl_down_sync(0xffffffffu, s0, off);
        s1 += __shfl_down_sync(0xffffffffu, s1, off);
    }
    if (lane == 0) {
        float dn = g_dinv[row];
        *(float2*)(g_hs2 + (size_t)row * 2) = make_float2(s0 * dn, s1 * dn);
    }
}

// ---------------- layer-4 agg (2 cols) fused with mean-pool ----------------
__global__ void k_agg2_pool(const int* __restrict__ batch, int N, int G) {
    int node = blockIdx.x * blockDim.x + threadIdx.x;
    if (node >= N) return;
    float2 acc = *(const float2*)(g_hs2 + (size_t)node * 2);
    const int beg = g_ptr[node], end = g_ptr[node + 1];
    int j = beg;
    for (; j + 4 <= end; j += 4) {
        int s0 = g_csrc[j], s1 = g_csrc[j + 1], s2 = g_csrc[j + 2], s3 = g_csrc[j + 3];
        float2 v0 = *(const float2*)(g_hs2 + (size_t)s0 * 2);
        float2 v1 = *(const float2*)(g_hs2 + (size_t)s1 * 2);
        float2 v2 = *(const float2*)(g_hs2 + (size_t)s2 * 2);
        float2 v3 = *(const float2*)(g_hs2 + (size_t)s3 * 2);
        acc.x += v0.x + v1.x + v2.x + v3.x;
        acc.y += v0.y + v1.y + v2.y + v3.y;
    }
    for (; j < end; j++) {
        float2 v = *(const float2*)(g_hs2 + (size_t)g_csrc[j] * 2);
        acc.x += v.x; acc.y += v.y;
    }
    float dn = g_dinv[node];
    unsigned g = (unsigned)batch[node];
    if (g >= (unsigned)G) return;
    float* p = g_pool + (size_t)g * 2;
    asm volatile("red.global.add.v2.f32 [%0], {%1, %2};"
                 :: "l"(p), "f"(acc.x * dn), "f"(acc.y * dn) : "memory");
    atomicAdd(&g_cnt[g], 1.f);
}

__global__ void k_zero_pool(int G) {
    int t = blockIdx.x * blockDim.x + threadIdx.x;
    if (t < G * 2) g_pool[t] = 0.f;
    if (t < G) g_cnt[t] = 0.f;
}

__global__ void k_head2(float* __restrict__ out, int G) {
    int g = blockIdx.x * blockDim.x + threadIdx.x;
    if (g >= G) return;
    float cn = fmaxf(g_cnt[g], 1.f);
    out[g * 2 + 0] = g_pool[g * 2 + 0] / cn + g_w4l[HID * 2 + 0];
    out[g * 2 + 1] = g_pool[g * 2 + 1] / cn + g_w4l[HID * 2 + 1];
}

// ---------------------------------------------------------------------------
extern "C" void kernel_launch(void* const* d_in, const int* in_sizes, int n_in,
                              void* d_out, int out_size) {
    const float* x   = (const float*)d_in[0];
    const int*   ei  = (const int*)d_in[1];
    const int*   bat = (const int*)d_in[2];
    const float* W1 = (const float*)d_in[3];
    const float* b1 = (const float*)d_in[4];
    const float* W2 = (const float*)d_in[5];
    const float* b2 = (const float*)d_in[6];
    const float* W3 = (const float*)d_in[7];
    const float* b3 = (const float*)d_in[8];
    const float* W4 = (const float*)d_in[9];
    const float* b4 = (const float*)d_in[10];
    const float* Wl = (const float*)d_in[11];
    const float* bl = (const float*)d_in[12];
    float* out = (float*)d_out;

    const int N  = in_sizes[2];
    const int E  = in_sizes[1] / 2;
    const int K1 = in_sizes[0] / N;
    const int G  = out_size / 2;

    const int* src = ei;
    const int* dst = ei + E;

    const int TB = 256;
    const int nScanBlocks = (N + SCHUNK - 1) / SCHUNK;

    // ---- CSR build + dinv + folded W4l ----
    k_zero_deg<<<(N + TB - 1) / TB, TB>>>(N);
    k_count_deg<<<(E + TB - 1) / TB, TB>>>(dst, E, N);
    k_dinv<<<(N + TB - 1) / TB, TB>>>(N);
    k_scan1<<<nScanBlocks, 256>>>(N);
    k_scan2<<<1, 256>>>(nScanBlocks);
    k_scan3<<<nScanBlocks, 256>>>(N);
    k_fill_csr<<<(E + TB - 1) / TB, TB>>>(src, dst, E, N);
    k_w4l<<<1, 256>>>(W4, Wl, b4, bl);
    k_zero_pool<<<(G * 2 + TB - 1) / TB, TB>>>(G);

    dim3 gemmGrid((N + 127) / 128, HID / 128);
    const unsigned aggGrid = (unsigned)((N + 3) / 4);

    // ---- layer 1 (commuted: agg X then GEMM) ----
    k_aggx<<<(N + 7) / 8, 256>>>(x, N, K1);
    k_sgemm_l1<<<gemmGrid, 256>>>(W1, b1, N, K1);
    // ---- layers 2-3 ----
    k_mma256<<<gemmGrid, 256>>>(W2, N);
    k_agg<<<aggGrid, 256>>>(b2, N);
    k_mma256<<<gemmGrid, 256>>>(W3, N);
    k_agg<<<aggGrid, 256>>>(b3, N);
    // ---- folded layer 4 + pool + head ----
    k_gemv4<<<(N + 7) / 8, 256>>>(N);
    k_agg2_pool<<<(N + TB - 1) / TB, TB>>>(bat, N, G);
    k_head2<<<(G + TB - 1) / TB, TB>>>(out, G);
}

// round 9
// speedup vs baseline: 4.4603x; 1.1054x over previous
#include <cuda_runtime.h>
#include <cuda_fp16.h>
#include <cstdint>

// ---------------------------------------------------------------------------
// GCN pipeline (S = D^-1/2 (A+I) D^-1/2):
//  L1 (commuted): xa = S·X (69-wide agg), a1 = xa@W1 + b1   [fp32]
//  L2,L3: h = relu(a)@W * dinv (tf32 mma, fp16 store) ; a = dinv*sum(h) + b
//  L4 folded: out_g = mean_g(S·(relu(a3)@(W4@Wl))) + (b4@Wl + bl)
// g_h is fp16: halves agg gather traffic and makes it L2-resident (51MB<126MB).
// ---------------------------------------------------------------------------

#define MAXN 100000
#define MAXE 400000
#define HID  256
#define IND  69
#define MAXG 4096
#define SCHUNK 2048

__device__ __half g_h[(size_t)MAXN * HID];   // hs = h*dinv, fp16
__device__ float  g_a[(size_t)MAXN * HID];
__device__ float  g_xa[(size_t)MAXN * IND];
__device__ float  g_hs2[(size_t)MAXN * 2];
__device__ float  g_dinv[MAXN];
__device__ int    g_deg[MAXN];
__device__ int    g_ptr[MAXN + 1];
__device__ int    g_cur[MAXN];
__device__ int    g_csrc[MAXE];
__device__ int    g_bsum[256];
__device__ float  g_w4l[HID * 2 + 2];
__device__ float  g_pool[(size_t)MAXG * 2];
__device__ float  g_cnt[MAXG];

__device__ __forceinline__ float to_tf32(float x) {
    float r;
    asm("cvt.rna.tf32.f32 %0, %1;" : "=f"(r) : "f"(x));
    return r;
}

// ---------------- CSR build ----------------
__global__ void k_zero_deg(int N) {
    int i = blockIdx.x * blockDim.x + threadIdx.x;
    if (i < N) g_deg[i] = 0;
}
__global__ void k_count_deg(const int* __restrict__ dst, int E, int N) {
    int e = blockIdx.x * blockDim.x + threadIdx.x;
    if (e < E) {
        unsigned d = (unsigned)dst[e];
        if (d < (unsigned)N) atomicAdd(&g_deg[d], 1);
    }
}
__global__ void k_dinv(int N) {
    int i = blockIdx.x * blockDim.x + threadIdx.x;
    if (i < N) g_dinv[i] = rsqrtf((float)g_deg[i] + 1.f);
}
__global__ void k_scan1(int N) {
    __shared__ int sh[256];
    const int tid = threadIdx.x;
    const int base = blockIdx.x * SCHUNK + tid * 8;
    int s = 0;
#pragma unroll
    for (int i = 0; i < 8; i++) {
        int idx = base + i;
        if (idx < N) s += g_deg[idx];
    }
    sh[tid] = s;
    __syncthreads();
    for (int off = 1; off < 256; off <<= 1) {
        int v = (tid >= off) ? sh[tid - off] : 0;
        __syncthreads();
        sh[tid] += v;
        __syncthreads();
    }
    if (tid == 255) g_bsum[blockIdx.x] = sh[255];
}
__global__ void k_scan2(int nb) {
    __shared__ int sh[256];
    const int tid = threadIdx.x;
    int v = (tid < nb) ? g_bsum[tid] : 0;
    sh[tid] = v;
    __syncthreads();
    for (int off = 1; off < 256; off <<= 1) {
        int t = (tid >= off) ? sh[tid - off] : 0;
        __syncthreads();
        sh[tid] += t;
        __syncthreads();
    }
    if (tid < nb) g_bsum[tid] = sh[tid] - v;
}
__global__ void k_scan3(int N) {
    __shared__ int sh[256];
    const int tid = threadIdx.x;
    const int base = blockIdx.x * SCHUNK + tid * 8;
    int d[8];
    int s = 0;
#pragma unroll
    for (int i = 0; i < 8; i++) {
        int idx = base + i;
        d[i] = (idx < N) ? g_deg[idx] : 0;
        s += d[i];
    }
    sh[tid] = s;
    __syncthreads();
    for (int off = 1; off < 256; off <<= 1) {
        int v = (tid >= off) ? sh[tid - off] : 0;
        __syncthreads();
        sh[tid] += v;
        __syncthreads();
    }
    int run = g_bsum[blockIdx.x] + sh[tid] - s;
#pragma unroll
    for (int i = 0; i < 8; i++) {
        int idx = base + i;
        if (idx < N) {
            g_ptr[idx] = run;
            g_cur[idx] = run;
            run += d[i];
            if (idx == N - 1) g_ptr[N] = run;
        }
    }
}
__global__ void k_fill_csr(const int* __restrict__ src, const int* __restrict__ dst,
                           int E, int N) {
    int e = blockIdx.x * blockDim.x + threadIdx.x;
    if (e >= E) return;
    unsigned s = (unsigned)src[e], d = (unsigned)dst[e];
    if (s >= (unsigned)N || d >= (unsigned)N) return;
    int pos = atomicAdd(&g_cur[d], 1);
    if (pos < MAXE) g_csrc[pos] = (int)s;
}

// ---------------- fold W4@Wl and b4@Wl+bl ----------------
__global__ void k_w4l(const float* __restrict__ W4, const float* __restrict__ Wl,
                      const float* __restrict__ b4, const float* __restrict__ bl) {
    __shared__ float wl[HID * 2];
    const int tid = threadIdx.x;   // 256
    wl[tid] = Wl[tid];
    wl[tid + 256] = Wl[tid + 256];
    __syncthreads();
    float s0 = 0.f, s1 = 0.f;
    for (int k = 0; k < HID; k++) {
        float w = W4[(size_t)tid * HID + k];
        s0 = fmaf(w, wl[k * 2 + 0], s0);
        s1 = fmaf(w, wl[k * 2 + 1], s1);
    }
    g_w4l[tid * 2 + 0] = s0;
    g_w4l[tid * 2 + 1] = s1;
    __shared__ float r0[256], r1[256];
    float b = b4[tid];
    r0[tid] = b * wl[tid * 2 + 0];
    r1[tid] = b * wl[tid * 2 + 1];
    __syncthreads();
    for (int st = 128; st > 0; st >>= 1) {
        if (tid < st) { r0[tid] += r0[tid + st]; r1[tid] += r1[tid + st]; }
        __syncthreads();
    }
    if (tid == 0) {
        g_w4l[HID * 2 + 0] = r0[0] + bl[0];
        g_w4l[HID * 2 + 1] = r1[0] + bl[1];
    }
}

// ---------------- layer-1 input agg: g_xa = S·X (69-wide) ----------------
__global__ void k_aggx(const float* __restrict__ x, int N, int K) {
    int node = blockIdx.x * 8 + (threadIdx.x >> 5);
    int lane = threadIdx.x & 31;
    if (node >= N) return;
    const bool p0 = lane < K, p1 = lane + 32 < K, p2 = lane + 64 < K;
    float dn = g_dinv[node];

    const float* xr = x + (size_t)node * K;
    float a0 = p0 ? xr[lane] * dn : 0.f;
    float a1 = p1 ? xr[lane + 32] * dn : 0.f;
    float a2 = p2 ? xr[lane + 64] * dn : 0.f;

    const int beg = g_ptr[node], end = g_ptr[node + 1];
    int j = beg;
    for (; j + 2 <= end; j += 2) {
        int s0 = g_csrc[j], s1 = g_csrc[j + 1];
        float d0 = g_dinv[s0], d1 = g_dinv[s1];
        const float* r0 = x + (size_t)s0 * K;
        const float* r1 = x + (size_t)s1 * K;
        if (p0) { a0 = fmaf(r0[lane], d0, a0);      a0 = fmaf(r1[lane], d1, a0); }
        if (p1) { a1 = fmaf(r0[lane + 32], d0, a1); a1 = fmaf(r1[lane + 32], d1, a1); }
        if (p2) { a2 = fmaf(r0[lane + 64], d0, a2); a2 = fmaf(r1[lane + 64], d1, a2); }
    }
    for (; j < end; j++) {
        int s = g_csrc[j];
        float ds = g_dinv[s];
        const float* r = x + (size_t)s * K;
        if (p0) a0 = fmaf(r[lane], ds, a0);
        if (p1) a1 = fmaf(r[lane + 32], ds, a1);
        if (p2) a2 = fmaf(r[lane + 64], ds, a2);
    }
    float* o = g_xa + (size_t)node * K;
    if (p0) o[lane] = a0 * dn;
    if (p1) o[lane + 32] = a1 * dn;
    if (p2) o[lane + 64] = a2 * dn;
}

// ---------------- layer-1 SGEMM: g_a = g_xa @ W1 + b1 (fp32) ---------------
// grid: x = n-block (2), y = m-block (adjacent blocks share A tile via L2)
__global__ __launch_bounds__(256, 2)
void k_sgemm_l1(const float* __restrict__ W, const float* __restrict__ bias,
                int M, int K) {
    __shared__ float As[8][128];
    __shared__ float Ws[8][128];
    const int tid = threadIdx.x;
    const int n0 = blockIdx.x * 128;
    const int m0 = blockIdx.y * 128;
    const int wrow = tid >> 5;
    const int wcol = (tid & 31) * 4;
    const int tx = tid & 15;
    const int ty = tid >> 4;

    float acc[8][8] = {};

    for (int k0 = 0; k0 < K; k0 += 8) {
        __syncthreads();
#pragma unroll
        for (int i = 0; i < 4; i++) {
            int idx = tid + i * 256;
            int r = idx >> 3, kk = idx & 7;
            int gm = m0 + r, gk = k0 + kk;
            As[kk][r] = (gm < M && gk < K) ? g_xa[(size_t)gm * K + gk] : 0.f;
        }
        {
            int gk = k0 + wrow;
            float4 w = (gk < K) ? *(const float4*)(W + (size_t)gk * HID + n0 + wcol)
                                : make_float4(0.f, 0.f, 0.f, 0.f);
            *(float4*)&Ws[wrow][wcol] = w;
        }
        __syncthreads();
#pragma unroll
        for (int kk = 0; kk < 8; kk++) {
            float4 a0 = *(const float4*)&As[kk][ty * 4];
            float4 a1 = *(const float4*)&As[kk][64 + ty * 4];
            float4 b0 = *(const float4*)&Ws[kk][tx * 4];
            float4 b1 = *(const float4*)&Ws[kk][64 + tx * 4];
            float a[8] = {a0.x, a0.y, a0.z, a0.w, a1.x, a1.y, a1.z, a1.w};
            float b[8] = {b0.x, b0.y, b0.z, b0.w, b1.x, b1.y, b1.z, b1.w};
#pragma unroll
            for (int i = 0; i < 8; i++)
#pragma unroll
                for (int j = 0; j < 8; j++)
                    acc[i][j] = fmaf(a[i], b[j], acc[i][j]);
        }
    }

    float4 bb0 = *(const float4*)(bias + n0 + tx * 4);
    float4 bb1 = *(const float4*)(bias + n0 + 64 + tx * 4);
#pragma unroll
    for (int i = 0; i < 8; i++) {
        int gm = m0 + ((i < 4) ? (ty * 4 + i) : (64 + ty * 4 + i - 4));
        if (gm >= M) continue;
        size_t off = (size_t)gm * HID + n0 + tx * 4;
        *(float4*)(g_a + off) = make_float4(acc[i][0] + bb0.x, acc[i][1] + bb0.y,
                                            acc[i][2] + bb0.z, acc[i][3] + bb0.w);
        *(float4*)(g_a + off + 64) = make_float4(acc[i][4] + bb1.x, acc[i][5] + bb1.y,
                                                 acc[i][6] + bb1.z, acc[i][7] + bb1.w);
    }
}

// ---------------- K=256 GEMM on tensor cores (tf32 mma, fp16 store) --------
// g_h[m] = fp16( (relu(g_a)@W)[m] * dinv[m] )
__global__ __launch_bounds__(256, 2)
void k_mma256(const float* __restrict__ W, int M) {
    const float* Asrc = (const float*)g_a;

    __shared__ float As[2][8][136];
    __shared__ float Ws[2][8][136];

    const int tid = threadIdx.x;
    const int lane = tid & 31;
    const int warp = tid >> 5;
    const int n0 = blockIdx.x * 128;
    const int m0 = blockIdx.y * 128;
    const int wm = (warp >> 2) * 64;
    const int wn = (warp & 3) * 32;

    const int arow = tid & 127;
    const int akg  = (tid >> 7) * 4;
    const int wrow = tid >> 5;
    const int wcol = (tid & 31) * 4;

    float4 pa, pw;

#define LDG_STAGE(k0)                                                          \
    do {                                                                       \
        int gm = m0 + arow;                                                    \
        if (gm < M) {                                                          \
            pa = *(const float4*)(Asrc + (size_t)gm * HID + (k0) + akg);       \
            pa.x = fmaxf(pa.x, 0.f); pa.y = fmaxf(pa.y, 0.f);                  \
            pa.z = fmaxf(pa.z, 0.f); pa.w = fmaxf(pa.w, 0.f);                  \
        } else pa = make_float4(0.f, 0.f, 0.f, 0.f);                           \
        pw = *(const float4*)(W + (size_t)((k0) + wrow) * HID + n0 + wcol);    \
    } while (0)

#define STS_STAGE(buf)                                                         \
    do {                                                                       \
        As[buf][akg + 0][arow] = to_tf32(pa.x);                                \
        As[buf][akg + 1][arow] = to_tf32(pa.y);                                \
        As[buf][akg + 2][arow] = to_tf32(pa.z);                                \
        As[buf][akg + 3][arow] = to_tf32(pa.w);                                \
        float4 cw = make_float4(to_tf32(pw.x), to_tf32(pw.y),                  \
                                to_tf32(pw.z), to_tf32(pw.w));                 \
        *(float4*)&Ws[buf][wrow][wcol] = cw;                                   \
    } while (0)

    float c[4][4][4] = {};

    LDG_STAGE(0);
    STS_STAGE(0);
    __syncthreads();

    const int NS = HID / 8;
    for (int s = 0; s < NS; s++) {
        if (s + 1 < NS) LDG_STAGE((s + 1) * 8);
        const int buf = s & 1;

        unsigned af[4][4], bf[4][2];
        const int kq = lane & 3;
        const int g8 = lane >> 2;
#pragma unroll
        for (int mt = 0; mt < 4; mt++) {
            int mr = wm + mt * 16 + g8;
            af[mt][0] = __float_as_uint(As[buf][kq][mr]);
            af[mt][1] = __float_as_uint(As[buf][kq][mr + 8]);
            af[mt][2] = __float_as_uint(As[buf][kq + 4][mr]);
            af[mt][3] = __float_as_uint(As[buf][kq + 4][mr + 8]);
        }
#pragma unroll
        for (int nt = 0; nt < 4; nt++) {
            int nc = wn + nt * 8 + g8;
            bf[nt][0] = __float_as_uint(Ws[buf][kq][nc]);
            bf[nt][1] = __float_as_uint(Ws[buf][kq + 4][nc]);
        }
#pragma unroll
        for (int mt = 0; mt < 4; mt++)
#pragma unroll
            for (int nt = 0; nt < 4; nt++) {
                asm volatile(
                    "mma.sync.aligned.m16n8k8.row.col.f32.tf32.tf32.f32 "
                    "{%0,%1,%2,%3}, {%4,%5,%6,%7}, {%8,%9}, {%0,%1,%2,%3};"
                    : "+f"(c[mt][nt][0]), "+f"(c[mt][nt][1]),
                      "+f"(c[mt][nt][2]), "+f"(c[mt][nt][3])
                    : "r"(af[mt][0]), "r"(af[mt][1]), "r"(af[mt][2]), "r"(af[mt][3]),
                      "r"(bf[nt][0]), "r"(bf[nt][1]));
            }

        if (s + 1 < NS) {
            STS_STAGE((s + 1) & 1);
            __syncthreads();
        }
    }
#undef LDG_STAGE
#undef STS_STAGE

    const int g8 = lane >> 2;
    const int cq = (lane & 3) * 2;
#pragma unroll
    for (int mt = 0; mt < 4; mt++) {
        int r0 = m0 + wm + mt * 16 + g8;
        int r1 = r0 + 8;
        float dn0 = (r0 < M) ? g_dinv[r0] : 0.f;
        float dn1 = (r1 < M) ? g_dinv[r1] : 0.f;
#pragma unroll
        for (int nt = 0; nt < 4; nt++) {
            int col = n0 + wn + nt * 8 + cq;
            if (r0 < M)
                *(__half2*)(g_h + (size_t)r0 * HID + col) =
                    __floats2half2_rn(c[mt][nt][0] * dn0, c[mt][nt][1] * dn0);
            if (r1 < M)
                *(__half2*)(g_h + (size_t)r1 * HID + col) =
                    __floats2half2_rn(c[mt][nt][2] * dn1, c[mt][nt][3] * dn1);
        }
    }
}

// ---------------- CSR agg (fp16 gather): warp per node ---------------------
// g_a[d] = dinv[d]*(h[d] + sum h[src]) + b    (h rows are 512B: uint4/lane)
__device__ __forceinline__ void h8_acc(uint4 v, float* a) {
    const __half2* p = (const __half2*)&v;
#pragma unroll
    for (int i = 0; i < 4; i++) {
        float2 f = __half22float2(p[i]);
        a[i * 2] += f.x;
        a[i * 2 + 1] += f.y;
    }
}

__global__ void k_agg(const float* __restrict__ bias, int N) {
    int node = blockIdx.x * 8 + (threadIdx.x >> 5);
    int lane = threadIdx.x & 31;
    if (node >= N) return;
    const int c = lane * 8;

    float acc[8] = {};
    h8_acc(*(const uint4*)(g_h + (size_t)node * HID + c), acc);

    const int beg = g_ptr[node], end = g_ptr[node + 1];
    int j = beg;
    for (; j + 4 <= end; j += 4) {
        int s0 = g_csrc[j], s1 = g_csrc[j + 1], s2 = g_csrc[j + 2], s3 = g_csrc[j + 3];
        uint4 v0 = *(const uint4*)(g_h + (size_t)s0 * HID + c);
        uint4 v1 = *(const uint4*)(g_h + (size_t)s1 * HID + c);
        uint4 v2 = *(const uint4*)(g_h + (size_t)s2 * HID + c);
        uint4 v3 = *(const uint4*)(g_h + (size_t)s3 * HID + c);
        h8_acc(v0, acc); h8_acc(v1, acc); h8_acc(v2, acc); h8_acc(v3, acc);
    }
    for (; j < end; j++) {
        h8_acc(*(const uint4*)(g_h + (size_t)g_csrc[j] * HID + c), acc);
    }

    float dn = g_dinv[node];
    float4 b0 = *(const float4*)(bias + c);
    float4 b1 = *(const float4*)(bias + c + 4);
    float* o = g_a + (size_t)node * HID + c;
    *(float4*)(o) = make_float4(fmaf(acc[0], dn, b0.x), fmaf(acc[1], dn, b0.y),
                                fmaf(acc[2], dn, b0.z), fmaf(acc[3], dn, b0.w));
    *(float4*)(o + 4) = make_float4(fmaf(acc[4], dn, b1.x), fmaf(acc[5], dn, b1.y),
                                    fmaf(acc[6], dn, b1.z), fmaf(acc[7], dn, b1.w));
}

// ---------------- layer-4 folded GEMV ----------------
__global__ void k_gemv4(int M) {
    __shared__ float w4l[HID * 2];
    const int tid = threadIdx.x;   // 256
    w4l[tid] = g_w4l[tid];
    w4l[tid + 256] = g_w4l[tid + 256];
    __syncthreads();
    int row = blockIdx.x * 8 + (tid >> 5);
    if (row >= M) return;
    int lane = tid & 31;
    const float* a = g_a + (size_t)row * HID + lane * 8;
    float4 v0 = *(const float4*)(a);
    float4 v1 = *(const float4*)(a + 4);
    float s0 = 0.f, s1 = 0.f;
    const float* w = w4l + lane * 16;
    float vv[8] = {v0.x, v0.y, v0.z, v0.w, v1.x, v1.y, v1.z, v1.w};
#pragma unroll
    for (int i = 0; i < 8; i++) {
        float r = fmaxf(vv[i], 0.f);
        s0 = fmaf(r, w[i * 2 + 0], s0);
        s1 = fmaf(r, w[i * 2 + 1], s1);
    }
#pragma unroll
    for (int off = 16; off > 0; off >>= 1) {
        s0 += __shfl_down_sync(0xffffffffu, s0, off);
        s1 += __shfl_down_sync(0xffffffffu, s1, off);
    }
    if (lane == 0) {
        float dn = g_dinv[row];
        *(float2*)(g_hs2 + (size_t)row * 2) = make_float2(s0 * dn, s1 * dn);
    }
}

// ---------------- layer-4 agg (2 cols) fused with mean-pool ----------------
__global__ void k_agg2_pool(const int* __restrict__ batch, int N, int G) {
    int node = blockIdx.x * blockDim.x + threadIdx.x;
    if (node >= N) return;
    float2 acc = *(const float2*)(g_hs2 + (size_t)node * 2);
    const int beg = g_ptr[node], end = g_ptr[node + 1];
    int j = beg;
    for (; j + 4 <= end; j += 4) {
        int s0 = g_csrc[j], s1 = g_csrc[j + 1], s2 = g_csrc[j + 2], s3 = g_csrc[j + 3];
        float2 v0 = *(const float2*)(g_hs2 + (size_t)s0 * 2);
        float2 v1 = *(const float2*)(g_hs2 + (size_t)s1 * 2);
        float2 v2 = *(const float2*)(g_hs2 + (size_t)s2 * 2);
        float2 v3 = *(const float2*)(g_hs2 + (size_t)s3 * 2);
        acc.x += v0.x + v1.x + v2.x + v3.x;
        acc.y += v0.y + v1.y + v2.y + v3.y;
    }
    for (; j < end; j++) {
        float2 v = *(const float2*)(g_hs2 + (size_t)g_csrc[j] * 2);
        acc.x += v.x; acc.y += v.y;
    }
    float dn = g_dinv[node];
    unsigned g = (unsigned)batch[node];
    if (g >= (unsigned)G) return;
    float* p = g_pool + (size_t)g * 2;
    asm volatile("red.global.add.v2.f32 [%0], {%1, %2};"
                 :: "l"(p), "f"(acc.x * dn), "f"(acc.y * dn) : "memory");
    atomicAdd(&g_cnt[g], 1.f);
}

__global__ void k_zero_pool(int G) {
    int t = blockIdx.x * blockDim.x + threadIdx.x;
    if (t < G * 2) g_pool[t] = 0.f;
    if (t < G) g_cnt[t] = 0.f;
}

__global__ void k_head2(float* __restrict__ out, int G) {
    int g = blockIdx.x * blockDim.x + threadIdx.x;
    if (g >= G) return;
    float cn = fmaxf(g_cnt[g], 1.f);
    out[g * 2 + 0] = g_pool[g * 2 + 0] / cn + g_w4l[HID * 2 + 0];
    out[g * 2 + 1] = g_pool[g * 2 + 1] / cn + g_w4l[HID * 2 + 1];
}

// ---------------------------------------------------------------------------
extern "C" void kernel_launch(void* const* d_in, const int* in_sizes, int n_in,
                              void* d_out, int out_size) {
    const float* x   = (const float*)d_in[0];
    const int*   ei  = (const int*)d_in[1];
    const int*   bat = (const int*)d_in[2];
    const float* W1 = (const float*)d_in[3];
    const float* b1 = (const float*)d_in[4];
    const float* W2 = (const float*)d_in[5];
    const float* b2 = (const float*)d_in[6];
    const float* W3 = (const float*)d_in[7];
    const float* b3 = (const float*)d_in[8];
    const float* W4 = (const float*)d_in[9];
    const float* b4 = (const float*)d_in[10];
    const float* Wl = (const float*)d_in[11];
    const float* bl = (const float*)d_in[12];
    float* out = (float*)d_out;

    const int N  = in_sizes[2];
    const int E  = in_sizes[1] / 2;
    const int K1 = in_sizes[0] / N;
    const int G  = out_size / 2;

    const int* src = ei;
    const int* dst = ei + E;

    const int TB = 256;
    const int nScanBlocks = (N + SCHUNK - 1) / SCHUNK;

    // ---- CSR build + dinv + folded W4l ----
    k_zero_deg<<<(N + TB - 1) / TB, TB>>>(N);
    k_count_deg<<<(E + TB - 1) / TB, TB>>>(dst, E, N);
    k_dinv<<<(N + TB - 1) / TB, TB>>>(N);
    k_scan1<<<nScanBlocks, 256>>>(N);
    k_scan2<<<1, 256>>>(nScanBlocks);
    k_scan3<<<nScanBlocks, 256>>>(N);
    k_fill_csr<<<(E + TB - 1) / TB, TB>>>(src, dst, E, N);
    k_w4l<<<1, 256>>>(W4, Wl, b4, bl);
    k_zero_pool<<<(G * 2 + TB - 1) / TB, TB>>>(G);

    // grid: x = n-blocks (2), y = m-blocks  -> adjacent blocks share A tile
    dim3 gemmGrid(HID / 128, (N + 127) / 128);
    const unsigned aggGrid = (unsigned)((N + 7) / 8);

    // ---- layer 1 (commuted: agg X then GEMM) ----
    k_aggx<<<(N + 7) / 8, 256>>>(x, N, K1);
    k_sgemm_l1<<<gemmGrid, 256>>>(W1, b1, N, K1);
    // ---- layers 2-3 ----
    k_mma256<<<gemmGrid, 256>>>(W2, N);
    k_agg<<<aggGrid, 256>>>(b2, N);
    k_mma256<<<gemmGrid, 256>>>(W3, N);
    k_agg<<<aggGrid, 256>>>(b3, N);
    // ---- folded layer 4 + pool + head ----
    k_gemv4<<<(N + 7) / 8, 256>>>(N);
    k_agg2_pool<<<(N + TB - 1) / TB, TB>>>(bat, N, G);
    k_head2<<<(G + TB - 1) / TB, TB>>>(out, G);
}

// round 11
// speedup vs baseline: 6.0934x; 1.3661x over previous
#include <cuda_runtime.h>
#include <cuda_fp16.h>
#include <cstdint>

// ---------------------------------------------------------------------------
// GCN pipeline (S = D^-1/2 (A+I) D^-1/2):
//  L1 (commuted): xa = S·X (fp32 agg), a1 = xa@W1 + b1  -> g_a (fp16)
//  L2,L3: h = relu(a)@W * dinv  (fp16 m16n8k16 mma, fp32 accum) -> g_h (fp16)
//         a = dinv*(h_self + sum h_src) + b              -> g_a (fp16)
//  L4 folded: out_g = mean_g(S·(relu(a3)@(W4@Wl))) + (b4@Wl + bl)
// fp16 activations: both 51MB buffers are L2-resident; fp16 has the same 10
// mantissa bits as tf32, so accuracy class is unchanged (~3e-4).
// ---------------------------------------------------------------------------

#define MAXN 100000
#define MAXE 400000
#define HID  256
#define IND  69
#define MAXG 4096
#define SCHUNK 2048

__device__ __half g_h[(size_t)MAXN * HID];    // hs = h*dinv
__device__ __half g_a[(size_t)MAXN * HID];    // layer input (pre-relu)
__device__ __half g_wh[(size_t)HID * HID];    // W transposed [n][k], fp16
__device__ float  g_xa[(size_t)MAXN * IND];
__device__ float  g_hs2[(size_t)MAXN * 2];
__device__ float  g_dinv[MAXN];
__device__ int    g_deg[MAXN];
__device__ int    g_ptr[MAXN + 1];
__device__ int    g_cur[MAXN];
__device__ int    g_csrc[MAXE];
__device__ int    g_bsum[256];
__device__ float  g_w4l[HID * 2 + 2];
__device__ float  g_pool[(size_t)MAXG * 2];
__device__ float  g_cnt[MAXG];

// ---------------- CSR build ----------------
__global__ void k_zero_deg(int N) {
    int i = blockIdx.x * blockDim.x + threadIdx.x;
    if (i < N) g_deg[i] = 0;
}
__global__ void k_count_deg(const int* __restrict__ dst, int E, int N) {
    int e = blockIdx.x * blockDim.x + threadIdx.x;
    if (e < E) {
        unsigned d = (unsigned)dst[e];
        if (d < (unsigned)N) atomicAdd(&g_deg[d], 1);
    }
}
__global__ void k_dinv(int N) {
    int i = blockIdx.x * blockDim.x + threadIdx.x;
    if (i < N) g_dinv[i] = rsqrtf((float)g_deg[i] + 1.f);
}
__global__ void k_scan1(int N) {
    __shared__ int sh[256];
    const int tid = threadIdx.x;
    const int base = blockIdx.x * SCHUNK + tid * 8;
    int s = 0;
#pragma unroll
    for (int i = 0; i < 8; i++) {
        int idx = base + i;
        if (idx < N) s += g_deg[idx];
    }
    sh[tid] = s;
    __syncthreads();
    for (int off = 1; off < 256; off <<= 1) {
        int v = (tid >= off) ? sh[tid - off] : 0;
        __syncthreads();
        sh[tid] += v;
        __syncthreads();
    }
    if (tid == 255) g_bsum[blockIdx.x] = sh[255];
}
__global__ void k_scan2(int nb) {
    __shared__ int sh[256];
    const int tid = threadIdx.x;
    int v = (tid < nb) ? g_bsum[tid] : 0;
    sh[tid] = v;
    __syncthreads();
    for (int off = 1; off < 256; off <<= 1) {
        int t = (tid >= off) ? sh[tid - off] : 0;
        __syncthreads();
        sh[tid] += t;
        __syncthreads();
    }
    if (tid < nb) g_bsum[tid] = sh[tid] - v;
}
__global__ void k_scan3(int N) {
    __shared__ int sh[256];
    const int tid = threadIdx.x;
    const int base = blockIdx.x * SCHUNK + tid * 8;
    int d[8];
    int s = 0;
#pragma unroll
    for (int i = 0; i < 8; i++) {
        int idx = base + i;
        d[i] = (idx < N) ? g_deg[idx] : 0;
        s += d[i];
    }
    sh[tid] = s;
    __syncthreads();
    for (int off = 1; off < 256; off <<= 1) {
        int v = (tid >= off) ? sh[tid - off] : 0;
        __syncthreads();
        sh[tid] += v;
        __syncthreads();
    }
    int run = g_bsum[blockIdx.x] + sh[tid] - s;
#pragma unroll
    for (int i = 0; i < 8; i++) {
        int idx = base + i;
        if (idx < N) {
            g_ptr[idx] = run;
            g_cur[idx] = run;
            run += d[i];
            if (idx == N - 1) g_ptr[N] = run;
        }
    }
}
__global__ void k_fill_csr(const int* __restrict__ src, const int* __restrict__ dst,
                           int E, int N) {
    int e = blockIdx.x * blockDim.x + threadIdx.x;
    if (e >= E) return;
    unsigned s = (unsigned)src[e], d = (unsigned)dst[e];
    if (s >= (unsigned)N || d >= (unsigned)N) return;
    int pos = atomicAdd(&g_cur[d], 1);
    if (pos < MAXE) g_csrc[pos] = (int)s;
}

// ---------------- fold W4@Wl and b4@Wl+bl ----------------
__global__ void k_w4l(const float* __restrict__ W4, const float* __restrict__ Wl,
                      const float* __restrict__ b4, const float* __restrict__ bl) {
    __shared__ float wl[HID * 2];
    const int tid = threadIdx.x;   // 256
    wl[tid] = Wl[tid];
    wl[tid + 256] = Wl[tid + 256];
    __syncthreads();
    float s0 = 0.f, s1 = 0.f;
    for (int k = 0; k < HID; k++) {
        float w = W4[(size_t)tid * HID + k];
        s0 = fmaf(w, wl[k * 2 + 0], s0);
        s1 = fmaf(w, wl[k * 2 + 1], s1);
    }
    g_w4l[tid * 2 + 0] = s0;
    g_w4l[tid * 2 + 1] = s1;
    __shared__ float r0[256], r1[256];
    float b = b4[tid];
    r0[tid] = b * wl[tid * 2 + 0];
    r1[tid] = b * wl[tid * 2 + 1];
    __syncthreads();
    for (int st = 128; st > 0; st >>= 1) {
        if (tid < st) { r0[tid] += r0[tid + st]; r1[tid] += r1[tid + st]; }
        __syncthreads();
    }
    if (tid == 0) {
        g_w4l[HID * 2 + 0] = r0[0] + bl[0];
        g_w4l[HID * 2 + 1] = r1[0] + bl[1];
    }
}

// ---------------- W -> g_wh[n][k] fp16 transpose ----------------
__global__ void k_cvtW(const float* __restrict__ W) {
    __shared__ float t[32][33];
    const int bx = blockIdx.x * 32;   // n offset
    const int by = blockIdx.y * 32;   // k offset
    const int tx = threadIdx.x, ty = threadIdx.y;   // 32 x 8
    for (int i = ty; i < 32; i += 8)
        t[i][tx] = W[(size_t)(by + i) * HID + bx + tx];   // t[k'][n']
    __syncthreads();
    for (int i = ty; i < 32; i += 8)
        g_wh[(size_t)(bx + i) * HID + by + tx] = __float2half(t[tx][i]);
}

// ---------------- layer-1 input agg: g_xa = S·X (fp32) ----------------
__global__ void k_aggx(const float* __restrict__ x, int N, int K) {
    int node = blockIdx.x * 8 + (threadIdx.x >> 5);
    int lane = threadIdx.x & 31;
    if (node >= N) return;
    const bool p0 = lane < K, p1 = lane + 32 < K, p2 = lane + 64 < K;
    float dn = g_dinv[node];

    const float* xr = x + (size_t)node * K;
    float a0 = p0 ? xr[lane] * dn : 0.f;
    float a1 = p1 ? xr[lane + 32] * dn : 0.f;
    float a2 = p2 ? xr[lane + 64] * dn : 0.f;

    const int beg = g_ptr[node], end = g_ptr[node + 1];
    int j = beg;
    for (; j + 2 <= end; j += 2) {
        int s0 = g_csrc[j], s1 = g_csrc[j + 1];
        float d0 = g_dinv[s0], d1 = g_dinv[s1];
        const float* r0 = x + (size_t)s0 * K;
        const float* r1 = x + (size_t)s1 * K;
        if (p0) { a0 = fmaf(r0[lane], d0, a0);      a0 = fmaf(r1[lane], d1, a0); }
        if (p1) { a1 = fmaf(r0[lane + 32], d0, a1); a1 = fmaf(r1[lane + 32], d1, a1); }
        if (p2) { a2 = fmaf(r0[lane + 64], d0, a2); a2 = fmaf(r1[lane + 64], d1, a2); }
    }
    for (; j < end; j++) {
        int s = g_csrc[j];
        float ds = g_dinv[s];
        const float* r = x + (size_t)s * K;
        if (p0) a0 = fmaf(r[lane], ds, a0);
        if (p1) a1 = fmaf(r[lane + 32], ds, a1);
        if (p2) a2 = fmaf(r[lane + 64], ds, a2);
    }
    float* o = g_xa + (size_t)node * K;
    if (p0) o[lane] = a0 * dn;
    if (p1) o[lane + 32] = a1 * dn;
    if (p2) o[lane + 64] = a2 * dn;
}

// ---------------- layer-1 SGEMM: g_a = fp16(g_xa @ W1 + b1) ----------------
__global__ __launch_bounds__(256, 2)
void k_sgemm_l1(const float* __restrict__ W, const float* __restrict__ bias,
                int M, int K) {
    __shared__ float As[8][128];
    __shared__ float Ws[8][128];
    const int tid = threadIdx.x;
    const int n0 = blockIdx.x * 128;
    const int m0 = blockIdx.y * 128;
    const int wrow = tid >> 5;
    const int wcol = (tid & 31) * 4;
    const int tx = tid & 15;
    const int ty = tid >> 4;

    float acc[8][8] = {};

    for (int k0 = 0; k0 < K; k0 += 8) {
        __syncthreads();
#pragma unroll
        for (int i = 0; i < 4; i++) {
            int idx = tid + i * 256;
            int r = idx >> 3, kk = idx & 7;
            int gm = m0 + r, gk = k0 + kk;
            As[kk][r] = (gm < M && gk < K) ? g_xa[(size_t)gm * K + gk] : 0.f;
        }
        {
            int gk = k0 + wrow;
            float4 w = (gk < K) ? *(const float4*)(W + (size_t)gk * HID + n0 + wcol)
                                : make_float4(0.f, 0.f, 0.f, 0.f);
            *(float4*)&Ws[wrow][wcol] = w;
        }
        __syncthreads();
#pragma unroll
        for (int kk = 0; kk < 8; kk++) {
            float4 a0 = *(const float4*)&As[kk][ty * 4];
            float4 a1 = *(const float4*)&As[kk][64 + ty * 4];
            float4 b0 = *(const float4*)&Ws[kk][tx * 4];
            float4 b1 = *(const float4*)&Ws[kk][64 + tx * 4];
            float a[8] = {a0.x, a0.y, a0.z, a0.w, a1.x, a1.y, a1.z, a1.w};
            float b[8] = {b0.x, b0.y, b0.z, b0.w, b1.x, b1.y, b1.z, b1.w};
#pragma unroll
            for (int i = 0; i < 8; i++)
#pragma unroll
                for (int j = 0; j < 8; j++)
                    acc[i][j] = fmaf(a[i], b[j], acc[i][j]);
        }
    }

    float4 bb0 = *(const float4*)(bias + n0 + tx * 4);
    float4 bb1 = *(const float4*)(bias + n0 + 64 + tx * 4);
#pragma unroll
    for (int i = 0; i < 8; i++) {
        int gm = m0 + ((i < 4) ? (ty * 4 + i) : (64 + ty * 4 + i - 4));
        if (gm >= M) continue;
        size_t off = (size_t)gm * HID + n0 + tx * 4;
        __half2 hh[4];
        hh[0] = __floats2half2_rn(acc[i][0] + bb0.x, acc[i][1] + bb0.y);
        hh[1] = __floats2half2_rn(acc[i][2] + bb0.z, acc[i][3] + bb0.w);
        hh[2] = __floats2half2_rn(acc[i][4] + bb1.x, acc[i][5] + bb1.y);
        hh[3] = __floats2half2_rn(acc[i][6] + bb1.z, acc[i][7] + bb1.w);
        *(uint2*)(g_a + off) = *(const uint2*)&hh[0];
        *(uint2*)(g_a + off + 64) = *(const uint2*)&hh[2];
    }
}

// ---------------- K=256 fp16 tensor-core GEMM (m16n8k16, fp32 accum) -------
// g_h[m] = fp16( (relu(g_a)@W)[m] * dinv[m] ),  W pre-staged in g_wh[n][k]
__global__ __launch_bounds__(256, 2)
void k_mma256h(int M) {
    __shared__ __half As[2][128][16];
    __shared__ __half Bs[2][128][16];

    const int tid = threadIdx.x;
    const int lane = tid & 31;
    const int warp = tid >> 5;
    const int n0 = blockIdx.x * 128;
    const int m0 = blockIdx.y * 128;
    const int wm = (warp >> 2) * 64;
    const int wn = (warp & 3) * 32;
    const int lrow = tid >> 1;           // 0..127
    const int lhp = (tid & 1) * 8;       // 0 or 8

    uint4 pa, pb;

#define LDG_STAGE(k0)                                                          \
    do {                                                                       \
        int gm = m0 + lrow;                                                    \
        pa = (gm < M) ? *(const uint4*)(g_a + (size_t)gm * HID + (k0) + lhp)   \
                      : make_uint4(0, 0, 0, 0);                                \
        pb = *(const uint4*)(g_wh + (size_t)(n0 + lrow) * HID + (k0) + lhp);   \
    } while (0)

#define STS_STAGE(buf)                                                         \
    do {                                                                       \
        __half2* ap = (__half2*)&pa;                                           \
        const __half2 z = __float2half2_rn(0.f);                               \
        ap[0] = __hmax2(ap[0], z); ap[1] = __hmax2(ap[1], z);                  \
        ap[2] = __hmax2(ap[2], z); ap[3] = __hmax2(ap[3], z);                  \
        *(uint4*)&As[buf][lrow][lhp] = pa;                                     \
        *(uint4*)&Bs[buf][lrow][lhp] = pb;                                     \
    } while (0)

    float c[4][4][4] = {};

    LDG_STAGE(0);
    STS_STAGE(0);
    __syncthreads();

    const int g8 = lane >> 2;
    const int kq = lane & 3;

    const int NS = HID / 16;   // 16 stages
    for (int s = 0; s < NS; s++) {
        if (s + 1 < NS) LDG_STAGE((s + 1) * 16);
        const int buf = s & 1;

        unsigned af[4][4], bf[4][2];
#pragma unroll
        for (int mt = 0; mt < 4; mt++) {
            int mr = wm + mt * 16 + g8;
            af[mt][0] = *(const unsigned*)&As[buf][mr][kq * 2];
            af[mt][1] = *(const unsigned*)&As[buf][mr + 8][kq * 2];
            af[mt][2] = *(const unsigned*)&As[buf][mr][kq * 2 + 8];
            af[mt][3] = *(const unsigned*)&As[buf][mr + 8][kq * 2 + 8];
        }
#pragma unroll
        for (int nt = 0; nt < 4; nt++) {
            int nc = wn + nt * 8 + g8;
            bf[nt][0] = *(const unsigned*)&Bs[buf][nc][kq * 2];
            bf[nt][1] = *(const unsigned*)&Bs[buf][nc][kq * 2 + 8];
        }
#pragma unroll
        for (int mt = 0; mt < 4; mt++)
#pragma unroll
            for (int nt = 0; nt < 4; nt++) {
                asm volatile(
                    "mma.sync.aligned.m16n8k16.row.col.f32.f16.f16.f32 "
                    "{%0,%1,%2,%3}, {%4,%5,%6,%7}, {%8,%9}, {%0,%1,%2,%3};"
                    : "+f"(c[mt][nt][0]), "+f"(c[mt][nt][1]),
                      "+f"(c[mt][nt][2]), "+f"(c[mt][nt][3])
                    : "r"(af[mt][0]), "r"(af[mt][1]), "r"(af[mt][2]), "r"(af[mt][3]),
                      "r"(bf[nt][0]), "r"(bf[nt][1]));
            }

        if (s + 1 < NS) {
            STS_STAGE((s + 1) & 1);
            __syncthreads();
        }
    }
#undef LDG_STAGE
#undef STS_STAGE

    const int cq = kq * 2;
#pragma unroll
    for (int mt = 0; mt < 4; mt++) {
        int r0 = m0 + wm + mt * 16 + g8;
        int r1 = r0 + 8;
        float dn0 = (r0 < M) ? g_dinv[r0] : 0.f;
        float dn1 = (r1 < M) ? g_dinv[r1] : 0.f;
#pragma unroll
        for (int nt = 0; nt < 4; nt++) {
            int col = n0 + wn + nt * 8 + cq;
            if (r0 < M)
                *(__half2*)(g_h + (size_t)r0 * HID + col) =
                    __floats2half2_rn(c[mt][nt][0] * dn0, c[mt][nt][1] * dn0);
            if (r1 < M)
                *(__half2*)(g_h + (size_t)r1 * HID + col) =
                    __floats2half2_rn(c[mt][nt][2] * dn1, c[mt][nt][3] * dn1);
        }
    }
}

// ---------------- CSR agg (fp16 gather, fp16 out): warp per node -----------
__device__ __forceinline__ void h8_acc(uint4 v, float* a) {
    const __half2* p = (const __half2*)&v;
#pragma unroll
    for (int i = 0; i < 4; i++) {
        float2 f = __half22float2(p[i]);
        a[i * 2] += f.x;
        a[i * 2 + 1] += f.y;
    }
}

__global__ void k_agg(const float* __restrict__ bias, int N) {
    int node = blockIdx.x * 8 + (threadIdx.x >> 5);
    int lane = threadIdx.x & 31;
    if (node >= N) return;
    const int c = lane * 8;

    float acc[8] = {};
    h8_acc(*(const uint4*)(g_h + (size_t)node * HID + c), acc);

    const int beg = g_ptr[node], end = g_ptr[node + 1];
    int j = beg;
    for (; j + 4 <= end; j += 4) {
        int s0 = g_csrc[j], s1 = g_csrc[j + 1], s2 = g_csrc[j + 2], s3 = g_csrc[j + 3];
        uint4 v0 = *(const uint4*)(g_h + (size_t)s0 * HID + c);
        uint4 v1 = *(const uint4*)(g_h + (size_t)s1 * HID + c);
        uint4 v2 = *(const uint4*)(g_h + (size_t)s2 * HID + c);
        uint4 v3 = *(const uint4*)(g_h + (size_t)s3 * HID + c);
        h8_acc(v0, acc); h8_acc(v1, acc); h8_acc(v2, acc); h8_acc(v3, acc);
    }
    for (; j < end; j++) {
        h8_acc(*(const uint4*)(g_h + (size_t)g_csrc[j] * HID + c), acc);
    }

    float dn = g_dinv[node];
    float4 b0 = *(const float4*)(bias + c);
    float4 b1 = *(const float4*)(bias + c + 4);
    __half2 hh[4];
    hh[0] = __floats2half2_rn(fmaf(acc[0], dn, b0.x), fmaf(acc[1], dn, b0.y));
    hh[1] = __floats2half2_rn(fmaf(acc[2], dn, b0.z), fmaf(acc[3], dn, b0.w));
    hh[2] = __floats2half2_rn(fmaf(acc[4], dn, b1.x), fmaf(acc[5], dn, b1.y));
    hh[3] = __floats2half2_rn(fmaf(acc[6], dn, b1.z), fmaf(acc[7], dn, b1.w));
    *(uint4*)(g_a + (size_t)node * HID + c) = *(const uint4*)hh;
}

// ---------------- layer-4 folded GEMV (fp16 in) ----------------
__global__ void k_gemv4(int M) {
    __shared__ float w4l[HID * 2];
    const int tid = threadIdx.x;   // 256
    w4l[tid] = g_w4l[tid];
    w4l[tid + 256] = g_w4l[tid + 256];
    __syncthreads();
    int row = blockIdx.x * 8 + (tid >> 5);
    if (row >= M) return;
    int lane = tid & 31;
    uint4 v = *(const uint4*)(g_a + (size_t)row * HID + lane * 8);
    const __half2* p = (const __half2*)&v;
    float s0 = 0.f, s1 = 0.f;
    const float* w = w4l + lane * 16;
#pragma unroll
    for (int i = 0; i < 4; i++) {
        float2 f = __half22float2(p[i]);
        float r0 = fmaxf(f.x, 0.f), r1 = fmaxf(f.y, 0.f);
        s0 = fmaf(r0, w[i * 4 + 0], s0);
        s1 = fmaf(r0, w[i * 4 + 1], s1);
        s0 = fmaf(r1, w[i * 4 + 2], s0);
        s1 = fmaf(r1, w[i * 4 + 3], s1);
    }
#pragma unroll
    for (int off = 16; off > 0; off >>= 1) {
        s0 += __shfl_down_sync(0xffffffffu, s0, off);
        s1 += __shfl_down_sync(0xffffffffu, s1, off);
    }
    if (lane == 0) {
        float dn = g_dinv[row];
        *(float2*)(g_hs2 + (size_t)row * 2) = make_float2(s0 * dn, s1 * dn);
    }
}

// ---------------- layer-4 agg (2 cols) fused with mean-pool ----------------
__global__ void k_agg2_pool(const int* __restrict__ batch, int N, int G) {
    int node = blockIdx.x * blockDim.x + threadIdx.x;
    if (node >= N) return;
    float2 acc = *(const float2*)(g_hs2 + (size_t)node * 2);
    const int beg = g_ptr[node], end = g_ptr[node + 1];
    int j = beg;
    for (; j + 4 <= end; j += 4) {
        int s0 = g_csrc[j], s1 = g_csrc[j + 1], s2 = g_csrc[j + 2], s3 = g_csrc[j + 3];
        float2 v0 = *(const float2*)(g_hs2 + (size_t)s0 * 2);
        float2 v1 = *(const float2*)(g_hs2 + (size_t)s1 * 2);
        float2 v2 = *(const float2*)(g_hs2 + (size_t)s2 * 2);
        float2 v3 = *(const float2*)(g_hs2 + (size_t)s3 * 2);
        acc.x += v0.x + v1.x + v2.x + v3.x;
        acc.y += v0.y + v1.y + v2.y + v3.y;
    }
    for (; j < end; j++) {
        float2 v = *(const float2*)(g_hs2 + (size_t)g_csrc[j] * 2);
        acc.x += v.x; acc.y += v.y;
    }
    float dn = g_dinv[node];
    unsigned g = (unsigned)batch[node];
    if (g >= (unsigned)G) return;
    float* p = g_pool + (size_t)g * 2;
    asm volatile("red.global.add.v2.f32 [%0], {%1, %2};"
                 :: "l"(p), "f"(acc.x * dn), "f"(acc.y * dn) : "memory");
    atomicAdd(&g_cnt[g], 1.f);
}

__global__ void k_zero_pool(int G) {
    int t = blockIdx.x * blockDim.x + threadIdx.x;
    if (t < G * 2) g_pool[t] = 0.f;
    if (t < G) g_cnt[t] = 0.f;
}

__global__ void k_head2(float* __restrict__ out, int G) {
    int g = blockIdx.x * blockDim.x + threadIdx.x;
    if (g >= G) return;
    float cn = fmaxf(g_cnt[g], 1.f);
    out[g * 2 + 0] = g_pool[g * 2 + 0] / cn + g_w4l[HID * 2 + 0];
    out[g * 2 + 1] = g_pool[g * 2 + 1] / cn + g_w4l[HID * 2 + 1];
}

// ---------------------------------------------------------------------------
extern "C" void kernel_launch(void* const* d_in, const int* in_sizes, int n_in,
                              void* d_out, int out_size) {
    const float* x   = (const float*)d_in[0];
    const int*   ei  = (const int*)d_in[1];
    const int*   bat = (const int*)d_in[2];
    const float* W1 = (const float*)d_in[3];
    const float* b1 = (const float*)d_in[4];
    const float* W2 = (const float*)d_in[5];
    const float* b2 = (const float*)d_in[6];
    const float* W3 = (const float*)d_in[7];
    const float* b3 = (const float*)d_in[8];
    const float* W4 = (const float*)d_in[9];
    const float* b4 = (const float*)d_in[10];
    const float* Wl = (const float*)d_in[11];
    const float* bl = (const float*)d_in[12];
    float* out = (float*)d_out;

    const int N  = in_sizes[2];
    const int E  = in_sizes[1] / 2;
    const int K1 = in_sizes[0] / N;
    const int G  = out_size / 2;

    const int* src = ei;
    const int* dst = ei + E;

    const int TB = 256;
    const int nScanBlocks = (N + SCHUNK - 1) / SCHUNK;

    // ---- CSR build + dinv + folded W4l ----
    k_zero_deg<<<(N + TB - 1) / TB, TB>>>(N);
    k_count_deg<<<(E + TB - 1) / TB, TB>>>(dst, E, N);
    k_dinv<<<(N + TB - 1) / TB, TB>>>(N);
    k_scan1<<<nScanBlocks, 256>>>(N);
    k_scan2<<<1, 256>>>(nScanBlocks);
    k_scan3<<<nScanBlocks, 256>>>(N);
    k_fill_csr<<<(E + TB - 1) / TB, TB>>>(src, dst, E, N);
    k_w4l<<<1, 256>>>(W4, Wl, b4, bl);
    k_zero_pool<<<(G * 2 + TB - 1) / TB, TB>>>(G);

    dim3 gemmGrid(HID / 128, (N + 127) / 128);
    dim3 cvtGrid(HID / 32, HID / 32), cvtBlk(32, 8);
    const unsigned aggGrid = (unsigned)((N + 7) / 8);

    // ---- layer 1 (commuted: agg X then GEMM -> fp16 a1) ----
    k_aggx<<<(N + 7) / 8, 256>>>(x, N, K1);
    k_sgemm_l1<<<gemmGrid, 256>>>(W1, b1, N, K1);
    // ---- layer 2 ----
    k_cvtW<<<cvtGrid, cvtBlk>>>(W2);
    k_mma256h<<<gemmGrid, 256>>>(N);
    k_agg<<<aggGrid, 256>>>(b2, N);
    // ---- layer 3 ----
    k_cvtW<<<cvtGrid, cvtBlk>>>(W3);
    k_mma256h<<<gemmGrid, 256>>>(N);
    k_agg<<<aggGrid, 256>>>(b3, N);
    // ---- folded layer 4 + pool + head ----
    k_gemv4<<<(N + 7) / 8, 256>>>(N);
    k_agg2_pool<<<(N + TB - 1) / TB, TB>>>(bat, N, G);
    k_head2<<<(G + TB - 1) / TB, TB>>>(out, G);
}

// round 12
// speedup vs baseline: 7.0207x; 1.1522x over previous
#include <cuda_runtime.h>
#include <cuda_fp16.h>
#include <cstdint>

// ---------------------------------------------------------------------------
// GCN pipeline (S = D^-1/2 (A+I) D^-1/2):
//  L1 (commuted): xah = fp16(S·X) padded K=80 ; a1 = xah@W1 + b1 (fp16 MMA)
//  L2: h2 = relu(a1)@W2 * dinv (fp16 MMA) -> g_h ; a2 = dinv*sum(h2)+b2 -> g_a
//  L3: h3 = relu(a2)@W3 * dinv (fp16 MMA) -> g_h
//  L4 folded + fused with L3 agg: per node, gather a3 = dinv*sum(h3)+b3,
//     hs2 = relu(a3)@(W4@Wl) * dinv ; then mean-pool + bias fold.
// ---------------------------------------------------------------------------

#define MAXN 100000
#define MAXE 400000
#define HID  256
#define K1P  80        // layer-1 K padded (IN_DIM=69 -> 80)
#define MAXG 4096
#define SCHUNK 2048

__device__ __half g_h[(size_t)MAXN * HID];    // hs = h*dinv
__device__ __half g_a[(size_t)MAXN * HID];    // layer input (pre-relu)
__device__ __half g_wh[(size_t)HID * HID];    // W transposed [n][k], fp16
__device__ __half g_xah[(size_t)MAXN * K1P];  // S·X, fp16, K padded to 80
__device__ float  g_hs2[(size_t)MAXN * 2];
__device__ float  g_dinv[MAXN];
__device__ int    g_deg[MAXN];
__device__ int    g_ptr[MAXN + 1];
__device__ int    g_cur[MAXN];
__device__ int    g_csrc[MAXE];
__device__ int    g_bsum[256];
__device__ float  g_w4l[HID * 2 + 2];
__device__ float  g_pool[(size_t)MAXG * 2];
__device__ float  g_cnt[MAXG];

// ---------------- CSR build ----------------
__global__ void k_zero_deg(int N) {
    int i = blockIdx.x * blockDim.x + threadIdx.x;
    if (i < N) g_deg[i] = 0;
}
__global__ void k_count_deg(const int* __restrict__ dst, int E, int N) {
    int e = blockIdx.x * blockDim.x + threadIdx.x;
    if (e < E) {
        unsigned d = (unsigned)dst[e];
        if (d < (unsigned)N) atomicAdd(&g_deg[d], 1);
    }
}
__global__ void k_dinv(int N) {
    int i = blockIdx.x * blockDim.x + threadIdx.x;
    if (i < N) g_dinv[i] = rsqrtf((float)g_deg[i] + 1.f);
}
__global__ void k_scan1(int N) {
    __shared__ int sh[256];
    const int tid = threadIdx.x;
    const int base = blockIdx.x * SCHUNK + tid * 8;
    int s = 0;
#pragma unroll
    for (int i = 0; i < 8; i++) {
        int idx = base + i;
        if (idx < N) s += g_deg[idx];
    }
    sh[tid] = s;
    __syncthreads();
    for (int off = 1; off < 256; off <<= 1) {
        int v = (tid >= off) ? sh[tid - off] : 0;
        __syncthreads();
        sh[tid] += v;
        __syncthreads();
    }
    if (tid == 255) g_bsum[blockIdx.x] = sh[255];
}
__global__ void k_scan2(int nb) {
    __shared__ int sh[256];
    const int tid = threadIdx.x;
    int v = (tid < nb) ? g_bsum[tid] : 0;
    sh[tid] = v;
    __syncthreads();
    for (int off = 1; off < 256; off <<= 1) {
        int t = (tid >= off) ? sh[tid - off] : 0;
        __syncthreads();
        sh[tid] += t;
        __syncthreads();
    }
    if (tid < nb) g_bsum[tid] = sh[tid] - v;
}
__global__ void k_scan3(int N) {
    __shared__ int sh[256];
    const int tid = threadIdx.x;
    const int base = blockIdx.x * SCHUNK + tid * 8;
    int d[8];
    int s = 0;
#pragma unroll
    for (int i = 0; i < 8; i++) {
        int idx = base + i;
        d[i] = (idx < N) ? g_deg[idx] : 0;
        s += d[i];
    }
    sh[tid] = s;
    __syncthreads();
    for (int off = 1; off < 256; off <<= 1) {
        int v = (tid >= off) ? sh[tid - off] : 0;
        __syncthreads();
        sh[tid] += v;
        __syncthreads();
    }
    int run = g_bsum[blockIdx.x] + sh[tid] - s;
#pragma unroll
    for (int i = 0; i < 8; i++) {
        int idx = base + i;
        if (idx < N) {
            g_ptr[idx] = run;
            g_cur[idx] = run;
            run += d[i];
            if (idx == N - 1) g_ptr[N] = run;
        }
    }
}
__global__ void k_fill_csr(const int* __restrict__ src, const int* __restrict__ dst,
                           int E, int N) {
    int e = blockIdx.x * blockDim.x + threadIdx.x;
    if (e >= E) return;
    unsigned s = (unsigned)src[e], d = (unsigned)dst[e];
    if (s >= (unsigned)N || d >= (unsigned)N) return;
    int pos = atomicAdd(&g_cur[d], 1);
    if (pos < MAXE) g_csrc[pos] = (int)s;
}

// ---------------- fold W4@Wl and b4@Wl+bl ----------------
__global__ void k_w4l(const float* __restrict__ W4, const float* __restrict__ Wl,
                      const float* __restrict__ b4, const float* __restrict__ bl) {
    __shared__ float wl[HID * 2];
    const int tid = threadIdx.x;   // 256
    wl[tid] = Wl[tid];
    wl[tid + 256] = Wl[tid + 256];
    __syncthreads();
    float s0 = 0.f, s1 = 0.f;
    for (int k = 0; k < HID; k++) {
        float w = W4[(size_t)tid * HID + k];
        s0 = fmaf(w, wl[k * 2 + 0], s0);
        s1 = fmaf(w, wl[k * 2 + 1], s1);
    }
    g_w4l[tid * 2 + 0] = s0;
    g_w4l[tid * 2 + 1] = s1;
    __shared__ float r0[256], r1[256];
    float b = b4[tid];
    r0[tid] = b * wl[tid * 2 + 0];
    r1[tid] = b * wl[tid * 2 + 1];
    __syncthreads();
    for (int st = 128; st > 0; st >>= 1) {
        if (tid < st) { r0[tid] += r0[tid + st]; r1[tid] += r1[tid + st]; }
        __syncthreads();
    }
    if (tid == 0) {
        g_w4l[HID * 2 + 0] = r0[0] + bl[0];
        g_w4l[HID * 2 + 1] = r1[0] + bl[1];
    }
}

// ---------------- W (256x256) -> g_wh[n][256] fp16 transpose ---------------
__global__ void k_cvtW(const float* __restrict__ W) {
    __shared__ float t[32][33];
    const int bx = blockIdx.x * 32;   // n offset
    const int by = blockIdx.y * 32;   // k offset
    const int tx = threadIdx.x, ty = threadIdx.y;   // 32 x 8
    for (int i = ty; i < 32; i += 8)
        t[i][tx] = W[(size_t)(by + i) * HID + bx + tx];
    __syncthreads();
    for (int i = ty; i < 32; i += 8)
        g_wh[(size_t)(bx + i) * HID + by + tx] = __float2half(t[tx][i]);
}

// ---------------- W1 (69x256) -> g_wh[n][80] fp16 transpose, zero-padded ---
__global__ void k_cvtW1(const float* __restrict__ W1, int K) {
    int n = blockIdx.x;           // 0..255
    int k = threadIdx.x;          // 0..79
    g_wh[(size_t)n * K1P + k] = (k < K) ? __float2half(W1[(size_t)k * HID + n])
                                        : __float2half(0.f);
}

// ---------------- layer-1 input agg: g_xah = fp16(S·X), K padded to 80 -----
__global__ void k_aggx(const float* __restrict__ x, int N, int K) {
    int node = blockIdx.x * 8 + (threadIdx.x >> 5);
    int lane = threadIdx.x & 31;
    if (node >= N) return;
    const bool p0 = lane < K, p1 = lane + 32 < K, p2 = lane + 64 < K;
    float dn = g_dinv[node];

    const float* xr = x + (size_t)node * K;
    float a0 = p0 ? xr[lane] * dn : 0.f;
    float a1 = p1 ? xr[lane + 32] * dn : 0.f;
    float a2 = p2 ? xr[lane + 64] * dn : 0.f;

    const int beg = g_ptr[node], end = g_ptr[node + 1];
    int j = beg;
    for (; j + 2 <= end; j += 2) {
        int s0 = g_csrc[j], s1 = g_csrc[j + 1];
        float d0 = g_dinv[s0], d1 = g_dinv[s1];
        const float* r0 = x + (size_t)s0 * K;
        const float* r1 = x + (size_t)s1 * K;
        if (p0) { a0 = fmaf(r0[lane], d0, a0);      a0 = fmaf(r1[lane], d1, a0); }
        if (p1) { a1 = fmaf(r0[lane + 32], d0, a1); a1 = fmaf(r1[lane + 32], d1, a1); }
        if (p2) { a2 = fmaf(r0[lane + 64], d0, a2); a2 = fmaf(r1[lane + 64], d1, a2); }
    }
    for (; j < end; j++) {
        int s = g_csrc[j];
        float ds = g_dinv[s];
        const float* r = x + (size_t)s * K;
        if (p0) a0 = fmaf(r[lane], ds, a0);
        if (p1) a1 = fmaf(r[lane + 32], ds, a1);
        if (p2) a2 = fmaf(r[lane + 64], ds, a2);
    }
    __half* o = g_xah + (size_t)node * K1P;
    if (p0) o[lane] = __float2half(a0 * dn);
    if (p1) o[lane + 32] = __float2half(a1 * dn);
    {
        int c2 = lane + 64;
        if (c2 < K1P) o[c2] = __float2half(p2 ? a2 * dn : 0.f);
    }
}

// ---------------- fp16 tensor-core GEMM (m16n8k16, fp32 accum) -------------
// HMODE=true : A = relu(g_a) [K=256], out g_h = C*dinv (fp16)
// HMODE=false: A = g_xah      [K=80],  out g_a = C + bias (fp16)
template <int KDIM, bool HMODE>
__global__ __launch_bounds__(256, 2)
void k_mmaN(const float* __restrict__ bias, int M) {
    const __half* A = HMODE ? (const __half*)g_a : (const __half*)g_xah;

    __shared__ __half As[2][128][16];
    __shared__ __half Bs[2][128][16];

    const int tid = threadIdx.x;
    const int lane = tid & 31;
    const int warp = tid >> 5;
    const int n0 = blockIdx.x * 128;
    const int m0 = blockIdx.y * 128;
    const int wm = (warp >> 2) * 64;
    const int wn = (warp & 3) * 32;
    const int lrow = tid >> 1;           // 0..127
    const int lhp = (tid & 1) * 8;       // 0 or 8

    uint4 pa, pb;

#define LDG_STAGE(k0)                                                          \
    do {                                                                       \
        int gm = m0 + lrow;                                                    \
        pa = (gm < M) ? *(const uint4*)(A + (size_t)gm * KDIM + (k0) + lhp)    \
                      : make_uint4(0, 0, 0, 0);                                \
        pb = *(const uint4*)(g_wh + (size_t)(n0 + lrow) * KDIM + (k0) + lhp);  \
    } while (0)

#define STS_STAGE(buf)                                                         \
    do {                                                                       \
        if (HMODE) {                                                           \
            __half2* ap = (__half2*)&pa;                                       \
            const __half2 z = __float2half2_rn(0.f);                           \
            ap[0] = __hmax2(ap[0], z); ap[1] = __hmax2(ap[1], z);              \
            ap[2] = __hmax2(ap[2], z); ap[3] = __hmax2(ap[3], z);              \
        }                                                                      \
        *(uint4*)&As[buf][lrow][lhp] = pa;                                     \
        *(uint4*)&Bs[buf][lrow][lhp] = pb;                                     \
    } while (0)

    float c[4][4][4] = {};

    LDG_STAGE(0);
    STS_STAGE(0);
    __syncthreads();

    const int g8 = lane >> 2;
    const int kq = lane & 3;

    const int NS = KDIM / 16;
    for (int s = 0; s < NS; s++) {
        if (s + 1 < NS) LDG_STAGE((s + 1) * 16);
        const int buf = s & 1;

        unsigned af[4][4], bf[4][2];
#pragma unroll
        for (int mt = 0; mt < 4; mt++) {
            int mr = wm + mt * 16 + g8;
            af[mt][0] = *(const unsigned*)&As[buf][mr][kq * 2];
            af[mt][1] = *(const unsigned*)&As[buf][mr + 8][kq * 2];
            af[mt][2] = *(const unsigned*)&As[buf][mr][kq * 2 + 8];
            af[mt][3] = *(const unsigned*)&As[buf][mr + 8][kq * 2 + 8];
        }
#pragma unroll
        for (int nt = 0; nt < 4; nt++) {
            int nc = wn + nt * 8 + g8;
            bf[nt][0] = *(const unsigned*)&Bs[buf][nc][kq * 2];
            bf[nt][1] = *(const unsigned*)&Bs[buf][nc][kq * 2 + 8];
        }
#pragma unroll
        for (int mt = 0; mt < 4; mt++)
#pragma unroll
            for (int nt = 0; nt < 4; nt++) {
                asm volatile(
                    "mma.sync.aligned.m16n8k16.row.col.f32.f16.f16.f32 "
                    "{%0,%1,%2,%3}, {%4,%5,%6,%7}, {%8,%9}, {%0,%1,%2,%3};"
                    : "+f"(c[mt][nt][0]), "+f"(c[mt][nt][1]),
                      "+f"(c[mt][nt][2]), "+f"(c[mt][nt][3])
                    : "r"(af[mt][0]), "r"(af[mt][1]), "r"(af[mt][2]), "r"(af[mt][3]),
                      "r"(bf[nt][0]), "r"(bf[nt][1]));
            }

        if (s + 1 < NS) {
            STS_STAGE((s + 1) & 1);
            __syncthreads();
        }
    }
#undef LDG_STAGE
#undef STS_STAGE

    const int cq = kq * 2;
#pragma unroll
    for (int mt = 0; mt < 4; mt++) {
        int r0 = m0 + wm + mt * 16 + g8;
        int r1 = r0 + 8;
        if (HMODE) {
            float dn0 = (r0 < M) ? g_dinv[r0] : 0.f;
            float dn1 = (r1 < M) ? g_dinv[r1] : 0.f;
#pragma unroll
            for (int nt = 0; nt < 4; nt++) {
                int col = n0 + wn + nt * 8 + cq;
                if (r0 < M)
                    *(__half2*)(g_h + (size_t)r0 * HID + col) =
                        __floats2half2_rn(c[mt][nt][0] * dn0, c[mt][nt][1] * dn0);
                if (r1 < M)
                    *(__half2*)(g_h + (size_t)r1 * HID + col) =
                        __floats2half2_rn(c[mt][nt][2] * dn1, c[mt][nt][3] * dn1);
            }
        } else {
#pragma unroll
            for (int nt = 0; nt < 4; nt++) {
                int col = n0 + wn + nt * 8 + cq;
                float bc0 = bias[col], bc1 = bias[col + 1];
                if (r0 < M)
                    *(__half2*)(g_a + (size_t)r0 * HID + col) =
                        __floats2half2_rn(c[mt][nt][0] + bc0, c[mt][nt][1] + bc1);
                if (r1 < M)
                    *(__half2*)(g_a + (size_t)r1 * HID + col) =
                        __floats2half2_rn(c[mt][nt][2] + bc0, c[mt][nt][3] + bc1);
            }
        }
    }
}

// ---------------- CSR agg (fp16 gather, fp16 out): warp per node -----------
__device__ __forceinline__ void h8_acc(uint4 v, float* a) {
    const __half2* p = (const __half2*)&v;
#pragma unroll
    for (int i = 0; i < 4; i++) {
        float2 f = __half22float2(p[i]);
        a[i * 2] += f.x;
        a[i * 2 + 1] += f.y;
    }
}

__global__ void k_agg(const float* __restrict__ bias, int N) {
    int node = blockIdx.x * 8 + (threadIdx.x >> 5);
    int lane = threadIdx.x & 31;
    if (node >= N) return;
    const int c = lane * 8;

    float acc[8] = {};
    h8_acc(*(const uint4*)(g_h + (size_t)node * HID + c), acc);

    const int beg = g_ptr[node], end = g_ptr[node + 1];
    int j = beg;
    for (; j + 4 <= end; j += 4) {
        int s0 = g_csrc[j], s1 = g_csrc[j + 1], s2 = g_csrc[j + 2], s3 = g_csrc[j + 3];
        uint4 v0 = *(const uint4*)(g_h + (size_t)s0 * HID + c);
        uint4 v1 = *(const uint4*)(g_h + (size_t)s1 * HID + c);
        uint4 v2 = *(const uint4*)(g_h + (size_t)s2 * HID + c);
        uint4 v3 = *(const uint4*)(g_h + (size_t)s3 * HID + c);
        h8_acc(v0, acc); h8_acc(v1, acc); h8_acc(v2, acc); h8_acc(v3, acc);
    }
    for (; j < end; j++) {
        h8_acc(*(const uint4*)(g_h + (size_t)g_csrc[j] * HID + c), acc);
    }

    float dn = g_dinv[node];
    float4 b0 = *(const float4*)(bias + c);
    float4 b1 = *(const float4*)(bias + c + 4);
    __half2 hh[4];
    hh[0] = __floats2half2_rn(fmaf(acc[0], dn, b0.x), fmaf(acc[1], dn, b0.y));
    hh[1] = __floats2half2_rn(fmaf(acc[2], dn, b0.z), fmaf(acc[3], dn, b0.w));
    hh[2] = __floats2half2_rn(fmaf(acc[4], dn, b1.x), fmaf(acc[5], dn, b1.y));
    hh[3] = __floats2half2_rn(fmaf(acc[6], dn, b1.z), fmaf(acc[7], dn, b1.w));
    *(uint4*)(g_a + (size_t)node * HID + c) = *(const uint4*)hh;
}

// ---------------- fused L3 agg + layer-4 folded GEMV -----------------------
// a3 = dinv*(h3[self] + sum h3[src]) + b3 ; hs2 = relu(a3)·W4l * dinv
__global__ void k_gemv4f(const float* __restrict__ b3, int N) {
    __shared__ float w4l[HID * 2];
    const int tid = threadIdx.x;   // 256
    w4l[tid] = g_w4l[tid];
    w4l[tid + 256] = g_w4l[tid + 256];
    __syncthreads();
    int node = blockIdx.x * 8 + (tid >> 5);
    if (node >= N) return;
    int lane = tid & 31;
    const int c = lane * 8;

    float acc[8] = {};
    h8_acc(*(const uint4*)(g_h + (size_t)node * HID + c), acc);

    const int beg = g_ptr[node], end = g_ptr[node + 1];
    int j = beg;
    for (; j + 4 <= end; j += 4) {
        int s0 = g_csrc[j], s1 = g_csrc[j + 1], s2 = g_csrc[j + 2], s3 = g_csrc[j + 3];
        uint4 v0 = *(const uint4*)(g_h + (size_t)s0 * HID + c);
        uint4 v1 = *(const uint4*)(g_h + (size_t)s1 * HID + c);
        uint4 v2 = *(const uint4*)(g_h + (size_t)s2 * HID + c);
        uint4 v3 = *(const uint4*)(g_h + (size_t)s3 * HID + c);
        h8_acc(v0, acc); h8_acc(v1, acc); h8_acc(v2, acc); h8_acc(v3, acc);
    }
    for (; j < end; j++) {
        h8_acc(*(const uint4*)(g_h + (size_t)g_csrc[j] * HID + c), acc);
    }

    float dn = g_dinv[node];
    float4 bb0 = *(const float4*)(b3 + c);
    float4 bb1 = *(const float4*)(b3 + c + 4);
    float bv[8] = {bb0.x, bb0.y, bb0.z, bb0.w, bb1.x, bb1.y, bb1.z, bb1.w};
    float s0 = 0.f, s1 = 0.f;
    const float* w = w4l + c * 2;
#pragma unroll
    for (int i = 0; i < 8; i++) {
        float a = fmaxf(fmaf(acc[i], dn, bv[i]), 0.f);
        s0 = fmaf(a, w[i * 2 + 0], s0);
        s1 = fmaf(a, w[i * 2 + 1], s1);
    }
#pragma unroll
    for (int off = 16; off > 0; off >>= 1) {
        s0 += __shfl_down_sync(0xffffffffu, s0, off);
        s1 += __shfl_down_sync(0xffffffffu, s1, off);
    }
    if (lane == 0)
        *(float2*)(g_hs2 + (size_t)node * 2) = make_float2(s0 * dn, s1 * dn);
}

// ---------------- layer-4 agg (2 cols) fused with mean-pool ----------------
__global__ void k_agg2_pool(const int* __restrict__ batch, int N, int G) {
    int node = blockIdx.x * blockDim.x + threadIdx.x;
    if (node >= N) return;
    float2 acc = *(const float2*)(g_hs2 + (size_t)node * 2);
    const int beg = g_ptr[node], end = g_ptr[node + 1];
    int j = beg;
    for (; j + 4 <= end; j += 4) {
        int s0 = g_csrc[j], s1 = g_csrc[j + 1], s2 = g_csrc[j + 2], s3 = g_csrc[j + 3];
        float2 v0 = *(const float2*)(g_hs2 + (size_t)s0 * 2);
        float2 v1 = *(const float2*)(g_hs2 + (size_t)s1 * 2);
        float2 v2 = *(const float2*)(g_hs2 + (size_t)s2 * 2);
        float2 v3 = *(const float2*)(g_hs2 + (size_t)s3 * 2);
        acc.x += v0.x + v1.x + v2.x + v3.x;
        acc.y += v0.y + v1.y + v2.y + v3.y;
    }
    for (; j < end; j++) {
        float2 v = *(const float2*)(g_hs2 + (size_t)g_csrc[j] * 2);
        acc.x += v.x; acc.y += v.y;
    }
    float dn = g_dinv[node];
    unsigned g = (unsigned)batch[node];
    if (g >= (unsigned)G) return;
    float* p = g_pool + (size_t)g * 2;
    asm volatile("red.global.add.v2.f32 [%0], {%1, %2};"
                 :: "l"(p), "f"(acc.x * dn), "f"(acc.y * dn) : "memory");
    atomicAdd(&g_cnt[g], 1.f);
}

__global__ void k_zero_pool(int G) {
    int t = blockIdx.x * blockDim.x + threadIdx.x;
    if (t < G * 2) g_pool[t] = 0.f;
    if (t < G) g_cnt[t] = 0.f;
}

__global__ void k_head2(float* __restrict__ out, int G) {
    int g = blockIdx.x * blockDim.x + threadIdx.x;
    if (g >= G) return;
    float cn = fmaxf(g_cnt[g], 1.f);
    out[g * 2 + 0] = g_pool[g * 2 + 0] / cn + g_w4l[HID * 2 + 0];
    out[g * 2 + 1] = g_pool[g * 2 + 1] / cn + g_w4l[HID * 2 + 1];
}

// ---------------------------------------------------------------------------
extern "C" void kernel_launch(void* const* d_in, const int* in_sizes, int n_in,
                              void* d_out, int out_size) {
    const float* x   = (const float*)d_in[0];
    const int*   ei  = (const int*)d_in[1];
    const int*   bat = (const int*)d_in[2];
    const float* W1 = (const float*)d_in[3];
    const float* b1 = (const float*)d_in[4];
    const float* W2 = (const float*)d_in[5];
    const float* b2 = (const float*)d_in[6];
    const float* W3 = (const float*)d_in[7];
    const float* b3 = (const float*)d_in[8];
    const float* W4 = (const float*)d_in[9];
    const float* b4 = (const float*)d_in[10];
    const float* Wl = (const float*)d_in[11];
    const float* bl = (const float*)d_in[12];
    float* out = (float*)d_out;

    const int N  = in_sizes[2];
    const int E  = in_sizes[1] / 2;
    const int K1 = in_sizes[0] / N;
    const int G  = out_size / 2;

    const int* src = ei;
    const int* dst = ei + E;

    const int TB = 256;
    const int nScanBlocks = (N + SCHUNK - 1) / SCHUNK;

    // ---- CSR build + dinv + folded W4l ----
    k_zero_deg<<<(N + TB - 1) / TB, TB>>>(N);
    k_count_deg<<<(E + TB - 1) / TB, TB>>>(dst, E, N);
    k_dinv<<<(N + TB - 1) / TB, TB>>>(N);
    k_scan1<<<nScanBlocks, 256>>>(N);
    k_scan2<<<1, 256>>>(nScanBlocks);
    k_scan3<<<nScanBlocks, 256>>>(N);
    k_fill_csr<<<(E + TB - 1) / TB, TB>>>(src, dst, E, N);
    k_w4l<<<1, 256>>>(W4, Wl, b4, bl);
    k_zero_pool<<<(G * 2 + TB - 1) / TB, TB>>>(G);

    dim3 gemmGrid(HID / 128, (N + 127) / 128);
    dim3 cvtGrid(HID / 32, HID / 32), cvtBlk(32, 8);
    const unsigned aggGrid = (unsigned)((N + 7) / 8);

    // ---- layer 1 (commuted: agg X -> fp16 MMA with bias epilogue) ----
    k_aggx<<<(N + 7) / 8, 256>>>(x, N, K1);
    k_cvtW1<<<HID, K1P>>>(W1, K1);
    k_mmaN<K1P, false><<<gemmGrid, 256>>>(b1, N);
    // ---- layer 2 ----
    k_cvtW<<<cvtGrid, cvtBlk>>>(W2);
    k_mmaN<HID, true><<<gemmGrid, 256>>>(nullptr, N);
    k_agg<<<aggGrid, 256>>>(b2, N);
    // ---- layer 3 ----
    k_cvtW<<<cvtGrid, cvtBlk>>>(W3);
    k_mmaN<HID, true><<<gemmGrid, 256>>>(nullptr, N);
    // ---- fused L3-agg + folded layer 4, then pool + head ----
    k_gemv4f<<<aggGrid, 256>>>(b3, N);
    k_agg2_pool<<<(N + TB - 1) / TB, TB>>>(bat, N, G);
    k_head2<<<(G + TB - 1) / TB, TB>>>(out, G);
}

// round 13
// speedup vs baseline: 7.1549x; 1.0191x over previous
#include <cuda_runtime.h>
#include <cuda_fp16.h>
#include <cstdint>

// ---------------------------------------------------------------------------
// GCN pipeline (S = D^-1/2 (A+I) D^-1/2):
//  L1 (commuted): xah = fp16(S·X) padded K=80 ; a1 = xah@W1 + b1 (fp16 MMA)
//  L2: h2 = relu(a1)@W2 * dinv (fp16 MMA) -> g_h ; a2 = dinv*sum(h2)+b2 -> g_a
//  L3: h3 = relu(a2)@W3 * dinv (fp16 MMA) -> g_h
//  L4 folded + fused with L3 agg (gemv4f), then mean-pool + bias fold.
// Gather kernels process 2 nodes per warp (interleaved loops -> 2x MLP).
// ---------------------------------------------------------------------------

#define MAXN 100000
#define MAXE 400000
#define HID  256
#define K1P  80
#define MAXG 4096
#define SCHUNK 2048

__device__ __half g_h[(size_t)MAXN * HID];
__device__ __half g_a[(size_t)MAXN * HID];
__device__ __half g_wh[(size_t)HID * HID];
__device__ __half g_xah[(size_t)MAXN * K1P];
__device__ float  g_hs2[(size_t)MAXN * 2];
__device__ float  g_dinv[MAXN];
__device__ int    g_deg[MAXN];
__device__ int    g_ptr[MAXN + 1];
__device__ int    g_cur[MAXN];
__device__ int    g_csrc[MAXE];
__device__ int    g_bsum[256];
__device__ float  g_w4l[HID * 2 + 2];
__device__ float  g_pool[(size_t)MAXG * 2];
__device__ float  g_cnt[MAXG];

// ---------------- CSR build ----------------
__global__ void k_zero_deg(int N) {
    int i = blockIdx.x * blockDim.x + threadIdx.x;
    if (i < N) g_deg[i] = 0;
}
__global__ void k_count_deg(const int* __restrict__ dst, int E, int N) {
    int e = blockIdx.x * blockDim.x + threadIdx.x;
    if (e < E) {
        unsigned d = (unsigned)dst[e];
        if (d < (unsigned)N) atomicAdd(&g_deg[d], 1);
    }
}
// scan1 also computes dinv (merged k_dinv)
__global__ void k_scan1(int N) {
    __shared__ int sh[256];
    const int tid = threadIdx.x;
    const int base = blockIdx.x * SCHUNK + tid * 8;
    int s = 0;
#pragma unroll
    for (int i = 0; i < 8; i++) {
        int idx = base + i;
        if (idx < N) {
            int d = g_deg[idx];
            s += d;
            g_dinv[idx] = rsqrtf((float)d + 1.f);
        }
    }
    sh[tid] = s;
    __syncthreads();
    for (int off = 1; off < 256; off <<= 1) {
        int v = (tid >= off) ? sh[tid - off] : 0;
        __syncthreads();
        sh[tid] += v;
        __syncthreads();
    }
    if (tid == 255) g_bsum[blockIdx.x] = sh[255];
}
__global__ void k_scan2(int nb) {
    __shared__ int sh[256];
    const int tid = threadIdx.x;
    int v = (tid < nb) ? g_bsum[tid] : 0;
    sh[tid] = v;
    __syncthreads();
    for (int off = 1; off < 256; off <<= 1) {
        int t = (tid >= off) ? sh[tid - off] : 0;
        __syncthreads();
        sh[tid] += t;
        __syncthreads();
    }
    if (tid < nb) g_bsum[tid] = sh[tid] - v;
}
__global__ void k_scan3(int N) {
    __shared__ int sh[256];
    const int tid = threadIdx.x;
    const int base = blockIdx.x * SCHUNK + tid * 8;
    int d[8];
    int s = 0;
#pragma unroll
    for (int i = 0; i < 8; i++) {
        int idx = base + i;
        d[i] = (idx < N) ? g_deg[idx] : 0;
        s += d[i];
    }
    sh[tid] = s;
    __syncthreads();
    for (int off = 1; off < 256; off <<= 1) {
        int v = (tid >= off) ? sh[tid - off] : 0;
        __syncthreads();
        sh[tid] += v;
        __syncthreads();
    }
    int run = g_bsum[blockIdx.x] + sh[tid] - s;
#pragma unroll
    for (int i = 0; i < 8; i++) {
        int idx = base + i;
        if (idx < N) {
            g_ptr[idx] = run;
            g_cur[idx] = run;
            run += d[i];
            if (idx == N - 1) g_ptr[N] = run;
        }
    }
}
__global__ void k_fill_csr(const int* __restrict__ src, const int* __restrict__ dst,
                           int E, int N) {
    int e = blockIdx.x * blockDim.x + threadIdx.x;
    if (e >= E) return;
    unsigned s = (unsigned)src[e], d = (unsigned)dst[e];
    if (s >= (unsigned)N || d >= (unsigned)N) return;
    int pos = atomicAdd(&g_cur[d], 1);
    if (pos < MAXE) g_csrc[pos] = (int)s;
}

// ---------------- merged setup: w4l fold + pool zero + W1 convert ----------
// block 0: W4@Wl fold; blocks 1..PZ: zero pool/cnt; blocks PZ+1..: cvtW1.
__global__ void k_setup(const float* __restrict__ W4, const float* __restrict__ Wl,
                        const float* __restrict__ b4, const float* __restrict__ bl,
                        const float* __restrict__ W1, int K, int G, int PZ) {
    const int bid = blockIdx.x;
    const int tid = threadIdx.x;
    if (bid == 0) {
        __shared__ float wl[HID * 2];
        wl[tid] = Wl[tid];
        wl[tid + 256] = Wl[tid + 256];
        __syncthreads();
        float s0 = 0.f, s1 = 0.f;
        for (int k = 0; k < HID; k++) {
            float w = W4[(size_t)tid * HID + k];
            s0 = fmaf(w, wl[k * 2 + 0], s0);
            s1 = fmaf(w, wl[k * 2 + 1], s1);
        }
        g_w4l[tid * 2 + 0] = s0;
        g_w4l[tid * 2 + 1] = s1;
        __shared__ float r0[256], r1[256];
        float b = b4[tid];
        r0[tid] = b * wl[tid * 2 + 0];
        r1[tid] = b * wl[tid * 2 + 1];
        __syncthreads();
        for (int st = 128; st > 0; st >>= 1) {
            if (tid < st) { r0[tid] += r0[tid + st]; r1[tid] += r1[tid + st]; }
            __syncthreads();
        }
        if (tid == 0) {
            g_w4l[HID * 2 + 0] = r0[0] + bl[0];
            g_w4l[HID * 2 + 1] = r1[0] + bl[1];
        }
    } else if (bid <= PZ) {
        int t = (bid - 1) * 256 + tid;
        if (t < G * 2) g_pool[t] = 0.f;
        if (t < G) g_cnt[t] = 0.f;
    } else {
        int n = bid - PZ - 1;   // 0..255
        if (n < HID && tid < K1P)
            g_wh[(size_t)n * K1P + tid] =
                (tid < K) ? __float2half(W1[(size_t)tid * HID + n]) : __float2half(0.f);
    }
}

// ---------------- W (256x256) -> g_wh[n][256] fp16 transpose ---------------
__global__ void k_cvtW(const float* __restrict__ W) {
    __shared__ float t[32][33];
    const int bx = blockIdx.x * 32;
    const int by = blockIdx.y * 32;
    const int tx = threadIdx.x, ty = threadIdx.y;   // 32 x 8
    for (int i = ty; i < 32; i += 8)
        t[i][tx] = W[(size_t)(by + i) * HID + bx + tx];
    __syncthreads();
    for (int i = ty; i < 32; i += 8)
        g_wh[(size_t)(bx + i) * HID + by + tx] = __float2half(t[tx][i]);
}

// ---------------- layer-1 input agg: g_xah = fp16(S·X), K padded -----------
__global__ void k_aggx(const float* __restrict__ x, int N, int K) {
    int node = blockIdx.x * 8 + (threadIdx.x >> 5);
    int lane = threadIdx.x & 31;
    if (node >= N) return;
    const bool p0 = lane < K, p1 = lane + 32 < K, p2 = lane + 64 < K;
    float dn = g_dinv[node];

    const float* xr = x + (size_t)node * K;
    float a0 = p0 ? xr[lane] * dn : 0.f;
    float a1 = p1 ? xr[lane + 32] * dn : 0.f;
    float a2 = p2 ? xr[lane + 64] * dn : 0.f;

    const int beg = g_ptr[node], end = g_ptr[node + 1];
    int j = beg;
    for (; j + 2 <= end; j += 2) {
        int s0 = g_csrc[j], s1 = g_csrc[j + 1];
        float d0 = g_dinv[s0], d1 = g_dinv[s1];
        const float* r0 = x + (size_t)s0 * K;
        const float* r1 = x + (size_t)s1 * K;
        if (p0) { a0 = fmaf(r0[lane], d0, a0);      a0 = fmaf(r1[lane], d1, a0); }
        if (p1) { a1 = fmaf(r0[lane + 32], d0, a1); a1 = fmaf(r1[lane + 32], d1, a1); }
        if (p2) { a2 = fmaf(r0[lane + 64], d0, a2); a2 = fmaf(r1[lane + 64], d1, a2); }
    }
    for (; j < end; j++) {
        int s = g_csrc[j];
        float ds = g_dinv[s];
        const float* r = x + (size_t)s * K;
        if (p0) a0 = fmaf(r[lane], ds, a0);
        if (p1) a1 = fmaf(r[lane + 32], ds, a1);
        if (p2) a2 = fmaf(r[lane + 64], ds, a2);
    }
    __half* o = g_xah + (size_t)node * K1P;
    if (p0) o[lane] = __float2half(a0 * dn);
    if (p1) o[lane + 32] = __float2half(a1 * dn);
    {
        int c2 = lane + 64;
        if (c2 < K1P) o[c2] = __float2half(p2 ? a2 * dn : 0.f);
    }
}

// ---------------- fp16 tensor-core GEMM (m16n8k16, fp32 accum) -------------
template <int KDIM, bool HMODE>
__global__ __launch_bounds__(256, 2)
void k_mmaN(const float* __restrict__ bias, int M) {
    const __half* A = HMODE ? (const __half*)g_a : (const __half*)g_xah;

    __shared__ __half As[2][128][16];
    __shared__ __half Bs[2][128][16];

    const int tid = threadIdx.x;
    const int lane = tid & 31;
    const int warp = tid >> 5;
    const int n0 = blockIdx.x * 128;
    const int m0 = blockIdx.y * 128;
    const int wm = (warp >> 2) * 64;
    const int wn = (warp & 3) * 32;
    const int lrow = tid >> 1;
    const int lhp = (tid & 1) * 8;

    uint4 pa, pb;

#define LDG_STAGE(k0)                                                          \
    do {                                                                       \
        int gm = m0 + lrow;                                                    \
        pa = (gm < M) ? *(const uint4*)(A + (size_t)gm * KDIM + (k0) + lhp)    \
                      : make_uint4(0, 0, 0, 0);                                \
        pb = *(const uint4*)(g_wh + (size_t)(n0 + lrow) * KDIM + (k0) + lhp);  \
    } while (0)

#define STS_STAGE(buf)                                                         \
    do {                                                                       \
        if (HMODE) {                                                           \
            __half2* ap = (__half2*)&pa;                                       \
            const __half2 z = __float2half2_rn(0.f);                           \
            ap[0] = __hmax2(ap[0], z); ap[1] = __hmax2(ap[1], z);              \
            ap[2] = __hmax2(ap[2], z); ap[3] = __hmax2(ap[3], z);              \
        }                                                                      \
        *(uint4*)&As[buf][lrow][lhp] = pa;                                     \
        *(uint4*)&Bs[buf][lrow][lhp] = pb;                                     \
    } while (0)

    float c[4][4][4] = {};

    LDG_STAGE(0);
    STS_STAGE(0);
    __syncthreads();

    const int g8 = lane >> 2;
    const int kq = lane & 3;

    const int NS = KDIM / 16;
    for (int s = 0; s < NS; s++) {
        if (s + 1 < NS) LDG_STAGE((s + 1) * 16);
        const int buf = s & 1;

        unsigned af[4][4], bf[4][2];
#pragma unroll
        for (int mt = 0; mt < 4; mt++) {
            int mr = wm + mt * 16 + g8;
            af[mt][0] = *(const unsigned*)&As[buf][mr][kq * 2];
            af[mt][1] = *(const unsigned*)&As[buf][mr + 8][kq * 2];
            af[mt][2] = *(const unsigned*)&As[buf][mr][kq * 2 + 8];
            af[mt][3] = *(const unsigned*)&As[buf][mr + 8][kq * 2 + 8];
        }
#pragma unroll
        for (int nt = 0; nt < 4; nt++) {
            int nc = wn + nt * 8 + g8;
            bf[nt][0] = *(const unsigned*)&Bs[buf][nc][kq * 2];
            bf[nt][1] = *(const unsigned*)&Bs[buf][nc][kq * 2 + 8];
        }
#pragma unroll
        for (int mt = 0; mt < 4; mt++)
#pragma unroll
            for (int nt = 0; nt < 4; nt++) {
                asm volatile(
                    "mma.sync.aligned.m16n8k16.row.col.f32.f16.f16.f32 "
                    "{%0,%1,%2,%3}, {%4,%5,%6,%7}, {%8,%9}, {%0,%1,%2,%3};"
                    : "+f"(c[mt][nt][0]), "+f"(c[mt][nt][1]),
                      "+f"(c[mt][nt][2]), "+f"(c[mt][nt][3])
                    : "r"(af[mt][0]), "r"(af[mt][1]), "r"(af[mt][2]), "r"(af[mt][3]),
                      "r"(bf[nt][0]), "r"(bf[nt][1]));
            }

        if (s + 1 < NS) {
            STS_STAGE((s + 1) & 1);
            __syncthreads();
        }
    }
#undef LDG_STAGE
#undef STS_STAGE

    const int cq = kq * 2;
#pragma unroll
    for (int mt = 0; mt < 4; mt++) {
        int r0 = m0 + wm + mt * 16 + g8;
        int r1 = r0 + 8;
        if (HMODE) {
            float dn0 = (r0 < M) ? g_dinv[r0] : 0.f;
            float dn1 = (r1 < M) ? g_dinv[r1] : 0.f;
#pragma unroll
            for (int nt = 0; nt < 4; nt++) {
                int col = n0 + wn + nt * 8 + cq;
                if (r0 < M)
                    *(__half2*)(g_h + (size_t)r0 * HID + col) =
                        __floats2half2_rn(c[mt][nt][0] * dn0, c[mt][nt][1] * dn0);
                if (r1 < M)
                    *(__half2*)(g_h + (size_t)r1 * HID + col) =
                        __floats2half2_rn(c[mt][nt][2] * dn1, c[mt][nt][3] * dn1);
            }
        } else {
#pragma unroll
            for (int nt = 0; nt < 4; nt++) {
                int col = n0 + wn + nt * 8 + cq;
                float bc0 = bias[col], bc1 = bias[col + 1];
                if (r0 < M)
                    *(__half2*)(g_a + (size_t)r0 * HID + col) =
                        __floats2half2_rn(c[mt][nt][0] + bc0, c[mt][nt][1] + bc1);
                if (r1 < M)
                    *(__half2*)(g_a + (size_t)r1 * HID + col) =
                        __floats2half2_rn(c[mt][nt][2] + bc0, c[mt][nt][3] + bc1);
            }
        }
    }
}

// ---------------- gather helpers ----------------
__device__ __forceinline__ void h8_acc(uint4 v, float* a) {
    const __half2* p = (const __half2*)&v;
#pragma unroll
    for (int i = 0; i < 4; i++) {
        float2 f = __half22float2(p[i]);
        a[i * 2] += f.x;
        a[i * 2 + 1] += f.y;
    }
}

// ---------------- CSR agg: 2 nodes per warp (interleaved loops) ------------
__global__ void k_agg(const float* __restrict__ bias, int N) {
    int warp = threadIdx.x >> 5;
    int lane = threadIdx.x & 31;
    int n0 = blockIdx.x * 16 + warp * 2;
    if (n0 >= N) return;
    int n1 = n0 + 1;
    bool has1 = n1 < N;
    const int c = lane * 8;

    float acc0[8] = {}, acc1[8] = {};
    h8_acc(*(const uint4*)(g_h + (size_t)n0 * HID + c), acc0);
    if (has1) h8_acc(*(const uint4*)(g_h + (size_t)n1 * HID + c), acc1);

    int j0 = g_ptr[n0];
    int e0 = g_ptr[n0 + 1];
    int j1 = e0;                              // g_ptr[n1] == e0
    int e1 = has1 ? g_ptr[n1 + 1] : e0;

    while (j0 < e0 || j1 < e1) {
        bool p0 = j0 < e0, p1 = j1 < e1;
        uint4 v0, v1;
        if (p0) v0 = *(const uint4*)(g_h + (size_t)g_csrc[j0] * HID + c);
        if (p1) v1 = *(const uint4*)(g_h + (size_t)g_csrc[j1] * HID + c);
        if (p0) { h8_acc(v0, acc0); j0++; }
        if (p1) { h8_acc(v1, acc1); j1++; }
    }

    float4 b0 = *(const float4*)(bias + c);
    float4 b1 = *(const float4*)(bias + c + 4);
    float bv[8] = {b0.x, b0.y, b0.z, b0.w, b1.x, b1.y, b1.z, b1.w};

    {
        float dn = g_dinv[n0];
        __half2 hh[4];
#pragma unroll
        for (int i = 0; i < 4; i++)
            hh[i] = __floats2half2_rn(fmaf(acc0[i * 2], dn, bv[i * 2]),
                                      fmaf(acc0[i * 2 + 1], dn, bv[i * 2 + 1]));
        *(uint4*)(g_a + (size_t)n0 * HID + c) = *(const uint4*)hh;
    }
    if (has1) {
        float dn = g_dinv[n1];
        __half2 hh[4];
#pragma unroll
        for (int i = 0; i < 4; i++)
            hh[i] = __floats2half2_rn(fmaf(acc1[i * 2], dn, bv[i * 2]),
                                      fmaf(acc1[i * 2 + 1], dn, bv[i * 2 + 1]));
        *(uint4*)(g_a + (size_t)n1 * HID + c) = *(const uint4*)hh;
    }
}

// ---------------- fused L3 agg + folded layer 4: 2 nodes per warp ----------
__global__ void k_gemv4f(const float* __restrict__ b3, int N) {
    __shared__ float w4l[HID * 2];
    const int tid = threadIdx.x;   // 256
    w4l[tid] = g_w4l[tid];
    w4l[tid + 256] = g_w4l[tid + 256];
    __syncthreads();
    int warp = tid >> 5;
    int lane = tid & 31;
    int n0 = blockIdx.x * 16 + warp * 2;
    if (n0 >= N) return;
    int n1 = n0 + 1;
    bool has1 = n1 < N;
    const int c = lane * 8;

    float acc0[8] = {}, acc1[8] = {};
    h8_acc(*(const uint4*)(g_h + (size_t)n0 * HID + c), acc0);
    if (has1) h8_acc(*(const uint4*)(g_h + (size_t)n1 * HID + c), acc1);

    int j0 = g_ptr[n0];
    int e0 = g_ptr[n0 + 1];
    int j1 = e0;
    int e1 = has1 ? g_ptr[n1 + 1] : e0;

    while (j0 < e0 || j1 < e1) {
        bool p0 = j0 < e0, p1 = j1 < e1;
        uint4 v0, v1;
        if (p0) v0 = *(const uint4*)(g_h + (size_t)g_csrc[j0] * HID + c);
        if (p1) v1 = *(const uint4*)(g_h + (size_t)g_csrc[j1] * HID + c);
        if (p0) { h8_acc(v0, acc0); j0++; }
        if (p1) { h8_acc(v1, acc1); j1++; }
    }

    float4 bb0 = *(const float4*)(b3 + c);
    float4 bb1 = *(const float4*)(b3 + c + 4);
    float bv[8] = {bb0.x, bb0.y, bb0.z, bb0.w, bb1.x, bb1.y, bb1.z, bb1.w};
    const float* w = w4l + c * 2;

    float s00 = 0.f, s01 = 0.f, s10 = 0.f, s11 = 0.f;
    float dn0 = g_dinv[n0];
    float dn1 = has1 ? g_dinv[n1] : 0.f;
#pragma unroll
    for (int i = 0; i < 8; i++) {
        float a0 = fmaxf(fmaf(acc0[i], dn0, bv[i]), 0.f);
        float a1 = fmaxf(fmaf(acc1[i], dn1, bv[i]), 0.f);
        s00 = fmaf(a0, w[i * 2 + 0], s00);
        s01 = fmaf(a0, w[i * 2 + 1], s01);
        s10 = fmaf(a1, w[i * 2 + 0], s10);
        s11 = fmaf(a1, w[i * 2 + 1], s11);
    }
#pragma unroll
    for (int off = 16; off > 0; off >>= 1) {
        s00 += __shfl_down_sync(0xffffffffu, s00, off);
        s01 += __shfl_down_sync(0xffffffffu, s01, off);
        s10 += __shfl_down_sync(0xffffffffu, s10, off);
        s11 += __shfl_down_sync(0xffffffffu, s11, off);
    }
    if (lane == 0) {
        *(float2*)(g_hs2 + (size_t)n0 * 2) = make_float2(s00 * dn0, s01 * dn0);
        if (has1)
            *(float2*)(g_hs2 + (size_t)n1 * 2) = make_float2(s10 * dn1, s11 * dn1);
    }
}

// ---------------- layer-4 agg (2 cols) fused with mean-pool ----------------
__global__ void k_agg2_pool(const int* __restrict__ batch, int N, int G) {
    int node = blockIdx.x * blockDim.x + threadIdx.x;
    if (node >= N) return;
    float2 acc = *(const float2*)(g_hs2 + (size_t)node * 2);
    const int beg = g_ptr[node], end = g_ptr[node + 1];
    int j = beg;
    for (; j + 4 <= end; j += 4) {
        int s0 = g_csrc[j], s1 = g_csrc[j + 1], s2 = g_csrc[j + 2], s3 = g_csrc[j + 3];
        float2 v0 = *(const float2*)(g_hs2 + (size_t)s0 * 2);
        float2 v1 = *(const float2*)(g_hs2 + (size_t)s1 * 2);
        float2 v2 = *(const float2*)(g_hs2 + (size_t)s2 * 2);
        float2 v3 = *(const float2*)(g_hs2 + (size_t)s3 * 2);
        acc.x += v0.x + v1.x + v2.x + v3.x;
        acc.y += v0.y + v1.y + v2.y + v3.y;
    }
    for (; j < end; j++) {
        float2 v = *(const float2*)(g_hs2 + (size_t)g_csrc[j] * 2);
        acc.x += v.x; acc.y += v.y;
    }
    float dn = g_dinv[node];
    unsigned g = (unsigned)batch[node];
    if (g >= (unsigned)G) return;
    float* p = g_pool + (size_t)g * 2;
    asm volatile("red.global.add.v2.f32 [%0], {%1, %2};"
                 :: "l"(p), "f"(acc.x * dn), "f"(acc.y * dn) : "memory");
    atomicAdd(&g_cnt[g], 1.f);
}

__global__ void k_head2(float* __restrict__ out, int G) {
    int g = blockIdx.x * blockDim.x + threadIdx.x;
    if (g >= G) return;
    float cn = fmaxf(g_cnt[g], 1.f);
    out[g * 2 + 0] = g_pool[g * 2 + 0] / cn + g_w4l[HID * 2 + 0];
    out[g * 2 + 1] = g_pool[g * 2 + 1] / cn + g_w4l[HID * 2 + 1];
}

// ---------------------------------------------------------------------------
extern "C" void kernel_launch(void* const* d_in, const int* in_sizes, int n_in,
                              void* d_out, int out_size) {
    const float* x   = (const float*)d_in[0];
    const int*   ei  = (const int*)d_in[1];
    const int*   bat = (const int*)d_in[2];
    const float* W1 = (const float*)d_in[3];
    const float* b1 = (const float*)d_in[4];
    const float* W2 = (const float*)d_in[5];
    const float* b2 = (const float*)d_in[6];
    const float* W3 = (const float*)d_in[7];
    const float* b3 = (const float*)d_in[8];
    const float* W4 = (const float*)d_in[9];
    const float* b4 = (const float*)d_in[10];
    const float* Wl = (const float*)d_in[11];
    const float* bl = (const float*)d_in[12];
    float* out = (float*)d_out;

    const int N  = in_sizes[2];
    const int E  = in_sizes[1] / 2;
    const int K1 = in_sizes[0] / N;
    const int G  = out_size / 2;

    const int* src = ei;
    const int* dst = ei + E;

    const int TB = 256;
    const int nScanBlocks = (N + SCHUNK - 1) / SCHUNK;
    const int PZ = (G * 2 + 255) / 256;

    // ---- CSR build (dinv merged into scan1) + merged setup ----
    k_zero_deg<<<(N + TB - 1) / TB, TB>>>(N);
    k_count_deg<<<(E + TB - 1) / TB, TB>>>(dst, E, N);
    k_scan1<<<nScanBlocks, 256>>>(N);
    k_scan2<<<1, 256>>>(nScanBlocks);
    k_scan3<<<nScanBlocks, 256>>>(N);
    k_fill_csr<<<(E + TB - 1) / TB, TB>>>(src, dst, E, N);
    k_setup<<<1 + PZ + HID, 256>>>(W4, Wl, b4, bl, W1, K1, G, PZ);

    dim3 gemmGrid(HID / 128, (N + 127) / 128);
    dim3 cvtGrid(HID / 32, HID / 32), cvtBlk(32, 8);
    const unsigned aggGrid = (unsigned)((N + 15) / 16);

    // ---- layer 1 (commuted: agg X -> fp16 MMA with bias epilogue) ----
    k_aggx<<<(N + 7) / 8, 256>>>(x, N, K1);
    k_mmaN<K1P, false><<<gemmGrid, 256>>>(b1, N);
    // ---- layer 2 ----
    k_cvtW<<<cvtGrid, cvtBlk>>>(W2);
    k_mmaN<HID, true><<<gemmGrid, 256>>>(nullptr, N);
    k_agg<<<aggGrid, 256>>>(b2, N);
    // ---- layer 3 ----
    k_cvtW<<<cvtGrid, cvtBlk>>>(W3);
    k_mmaN<HID, true><<<gemmGrid, 256>>>(nullptr, N);
    // ---- fused L3-agg + folded layer 4, then pool + head ----
    k_gemv4f<<<aggGrid, 256>>>(b3, N);
    k_agg2_pool<<<(N + TB - 1) / TB, TB>>>(bat, N, G);
    k_head2<<<(G + TB - 1) / TB, TB>>>(out, G);
}